// round 1
// baseline (speedup 1.0000x reference)
#include <cuda_runtime.h>
#include <cstdint>

#define NB 8
#define SS 1024
#define DD 64
#define HID 512
#define NTOK (NB*SS)          // 8192
#define EPSV 1e-6f

// ---------------- device scratch (no allocation allowed) ----------------
__device__ float g_Q[NTOK*DD];
__device__ float g_K[NTOK*DD];
__device__ float g_V[NTOK*DD];
__device__ float g_hopv[2*NTOK*DD];
__device__ float g_gate[NTOK*2];
__device__ float g_comb[NTOK*DD];
__device__ float g_rs[6*NTOK];           // rowsums: 0=A 1=P 2=Qm 3=A2 4=P2 5=Q2
__device__ float g_A [(size_t)NB*SS*SS]; // softmax attention
__device__ float g_P [(size_t)NB*SS*SS]; // A A^T
__device__ float g_Qm[(size_t)NB*SS*SS]; // A^T A
__device__ float g_A2[(size_t)NB*SS*SS]; // A A
__device__ float g_P2[(size_t)NB*SS*SS]; // P P
__device__ float g_Q2[(size_t)NB*SS*SS]; // Qm Qm

__device__ __forceinline__ float* matsel(int s) {
    switch (s) {
        case 0: return g_A;
        case 1: return g_P;
        case 2: return g_Qm;
        case 3: return g_A2;
        case 4: return g_P2;
        default: return g_Q2;
    }
}

__device__ __forceinline__ float warp_max(float v) {
    #pragma unroll
    for (int o = 16; o > 0; o >>= 1) v = fmaxf(v, __shfl_xor_sync(0xffffffffu, v, o));
    return v;
}
__device__ __forceinline__ float warp_sum(float v) {
    #pragma unroll
    for (int o = 16; o > 0; o >>= 1) v += __shfl_xor_sync(0xffffffffu, v, o);
    return v;
}

// ---------------- 1) QKV + gate-logit projection ----------------
// x:[NTOK,512]  Wq/Wk/Wv:[64,512]  gate_W:[2,512]
#define TOK_PB 16
__global__ __launch_bounds__(256) void proj_kernel(
    const float* __restrict__ x, const float* __restrict__ Wq,
    const float* __restrict__ Wk, const float* __restrict__ Wv,
    const float* __restrict__ gW)
{
    __shared__ float xs[TOK_PB*HID];
    int tb = blockIdx.x * TOK_PB;
    int tid = threadIdx.x;
    const float4* xg = (const float4*)(x + (size_t)tb*HID);
    float4* xs4 = (float4*)xs;
    #pragma unroll
    for (int i = tid; i < TOK_PB*HID/4; i += 256) xs4[i] = xg[i];
    __syncthreads();

    for (int o = tid; o < TOK_PB*194; o += 256) {
        int tok = o / 194, ch = o % 194;
        const float* w;
        if (ch < 64)       w = Wq + ch*HID;
        else if (ch < 128) w = Wk + (ch-64)*HID;
        else if (ch < 192) w = Wv + (ch-128)*HID;
        else               w = gW + (ch-192)*HID;
        const float4* w4  = (const float4*)w;
        const float4* xv4 = (const float4*)(xs + tok*HID);
        float acc = 0.f;
        #pragma unroll 8
        for (int k = 0; k < HID/4; k++) {
            float4 a = xv4[k];
            float4 b = __ldg(&w4[k]);
            acc += a.x*b.x + a.y*b.y + a.z*b.z + a.w*b.w;
        }
        size_t gt = tb + tok;
        if (ch < 64)       g_Q[gt*DD + ch]        = acc;
        else if (ch < 128) g_K[gt*DD + (ch-64)]   = acc;
        else if (ch < 192) g_V[gt*DD + (ch-128)]  = acc;
        else               g_gate[gt*2 + (ch-192)] = acc;   // raw logit
    }
}

// ---------------- 2) RoPE in place on Q,K ----------------
__global__ void rope_kernel()
{
    int gid = blockIdx.x*256 + threadIdx.x;
    if (gid >= NTOK*32) return;
    int tok = gid >> 5, j = gid & 31;
    int s = tok & (SS-1);
    float invf = (float)exp(-log(10000.0) * (double)j / 32.0);
    float ang = (float)s * invf;
    float sn, cs;
    sincosf(ang, &sn, &cs);
    size_t base = (size_t)tok * DD;
    float q0 = g_Q[base+j], q1 = g_Q[base+j+32];
    g_Q[base+j]    = q0*cs - q1*sn;
    g_Q[base+j+32] = q1*cs + q0*sn;
    float k0 = g_K[base+j], k1 = g_K[base+j+32];
    g_K[base+j]    = k0*cs - k1*sn;
    g_K[base+j+32] = k1*cs + k0*sn;
}

// ---------------- 3) hop_v = V @ hop_W[h]^T ; gate softmax ----------------
__global__ void hopv_gate_kernel(const float* __restrict__ hopW,
                                 const float* __restrict__ gateb)
{
    int gid = blockIdx.x*256 + threadIdx.x;
    if (gid >= NTOK*DD) return;
    int tok = gid >> 6, e = gid & 63;
    const float* vrow = g_V + (size_t)tok*DD;
    float a0 = 0.f, a1 = 0.f;
    #pragma unroll
    for (int d = 0; d < DD; d++) {
        float v = vrow[d];
        a0 += v * __ldg(&hopW[e*DD + d]);
        a1 += v * __ldg(&hopW[DD*DD + e*DD + d]);
    }
    g_hopv[(size_t)tok*DD + e]              = a0;
    g_hopv[(size_t)NTOK*DD + (size_t)tok*DD + e] = a1;
    if (e == 0) {
        float l0 = g_gate[tok*2]   + gateb[0];
        float l1 = g_gate[tok*2+1] + gateb[1];
        float m = fmaxf(l0, l1);
        float e0 = expf(l0-m), e1 = expf(l1-m);
        float inv = 1.f/(e0+e1);
        g_gate[tok*2]   = e0*inv;
        g_gate[tok*2+1] = e1*inv;
    }
}

// ---------------- 4) scores = (QK^T/8 + pb)/temp  (fp32 SIMT) ----------------
__global__ __launch_bounds__(256) void scores_kernel(
    const float* __restrict__ bias_table, const int* __restrict__ rel_idx,
    const float* __restrict__ temperature)
{
    __shared__ float qs[64][65];
    __shared__ float ks[64][65];
    int b = blockIdx.z;
    int s0 = blockIdx.y * 64, t0 = blockIdx.x * 64;
    int tid = threadIdx.x;
    const float* Qb = g_Q + ((size_t)b*SS + s0)*DD;
    const float* Kb = g_K + ((size_t)b*SS + t0)*DD;
    #pragma unroll
    for (int e = tid; e < 64*64; e += 256) {
        qs[e>>6][e&63] = Qb[e];
        ks[e>>6][e&63] = Kb[e];
    }
    __syncthreads();
    int ty = tid >> 4, tx = tid & 15;
    float c[4][4];
    #pragma unroll
    for (int i=0;i<4;i++) { c[i][0]=0;c[i][1]=0;c[i][2]=0;c[i][3]=0; }
    #pragma unroll 4
    for (int d = 0; d < 64; d++) {
        float rq[4], rk[4];
        #pragma unroll
        for (int i=0;i<4;i++) { rq[i] = qs[ty*4+i][d]; rk[i] = ks[tx*4+i][d]; }
        #pragma unroll
        for (int i=0;i<4;i++)
            #pragma unroll
            for (int j=0;j<4;j++) c[i][j] += rq[i]*rk[j];
    }
    float inv_t = 1.f / fmaxf(temperature[0], 0.1f);
    const float scale = 0.125f;
    float* Ab = g_A + (size_t)b*SS*SS;
    #pragma unroll
    for (int i = 0; i < 4; i++) {
        int s = s0 + ty*4 + i;
        int4 idx = *(const int4*)(rel_idx + (size_t)s*SS + t0 + tx*4);
        float4 out;
        out.x = (c[i][0]*scale + __ldg(&bias_table[idx.x])) * inv_t;
        out.y = (c[i][1]*scale + __ldg(&bias_table[idx.y])) * inv_t;
        out.z = (c[i][2]*scale + __ldg(&bias_table[idx.z])) * inv_t;
        out.w = (c[i][3]*scale + __ldg(&bias_table[idx.w])) * inv_t;
        *(float4*)(Ab + (size_t)s*SS + t0 + tx*4) = out;
    }
}

// ---------------- 5) row softmax in place on g_A ----------------
__global__ __launch_bounds__(256) void softmax_kernel()
{
    size_t row = blockIdx.x;
    float* Ar = g_A + row*SS;
    int tid = threadIdx.x;
    int wid = tid >> 5, lane = tid & 31;
    __shared__ float sm[8];
    float4 v = ((float4*)Ar)[tid];
    float m = fmaxf(fmaxf(v.x, v.y), fmaxf(v.z, v.w));
    m = warp_max(m);
    if (lane == 0) sm[wid] = m;
    __syncthreads();
    if (wid == 0) {
        float t = (lane < 8) ? sm[lane] : -3.4e38f;
        t = warp_max(t);
        if (lane == 0) sm[0] = t;
    }
    __syncthreads();
    m = sm[0];
    __syncthreads();
    float e0 = expf(v.x-m), e1 = expf(v.y-m), e2 = expf(v.z-m), e3 = expf(v.w-m);
    float s = e0+e1+e2+e3;
    s = warp_sum(s);
    if (lane == 0) sm[wid] = s;
    __syncthreads();
    if (wid == 0) {
        float t = (lane < 8) ? sm[lane] : 0.f;
        t = warp_sum(t);
        if (lane == 0) sm[0] = t;
    }
    __syncthreads();
    float inv = 1.f / sm[0];
    float4 o = make_float4(e0*inv, e1*inv, e2*inv, e3*inv);
    ((float4*)Ar)[tid] = o;
    if (tid == 0) g_rs[row] = 1.0f;   // softmax rows sum to 1
}

// ---------------- 6) TF32 tensor-core batched GEMM ----------------
__device__ __forceinline__ float to_tf32(float x) {
    uint32_t u;
    asm("cvt.rna.tf32.f32 %0, %1;" : "=r"(u) : "f"(x));
    return __uint_as_float(u);
}
__device__ __forceinline__ void mma_tf32(float* c,
    uint32_t a0, uint32_t a1, uint32_t a2, uint32_t a3, uint32_t b0, uint32_t b1)
{
    asm volatile(
        "mma.sync.aligned.m16n8k8.row.col.f32.tf32.tf32.f32 "
        "{%0,%1,%2,%3},{%4,%5,%6,%7},{%8,%9},{%0,%1,%2,%3};"
        : "+f"(c[0]), "+f"(c[1]), "+f"(c[2]), "+f"(c[3])
        : "r"(a0), "r"(a1), "r"(a2), "r"(a3), "r"(b0), "r"(b1));
}

#define GBM 128
#define GBN 128
__global__ __launch_bounds__(256) void gemm_tf32_kernel(
    int aSel, int bSel, int cSel, int tA, int tB)
{
    __shared__ float As[16][GBM+4];
    __shared__ float Bs[16][GBN+4];
    const float* __restrict__ Ag = matsel(aSel) + (size_t)blockIdx.z*SS*SS;
    const float* __restrict__ Bg = matsel(bSel) + (size_t)blockIdx.z*SS*SS;
    float* __restrict__ Cg = matsel(cSel) + (size_t)blockIdx.z*SS*SS;
    int tid = threadIdx.x;
    int warp = tid >> 5, lane = tid & 31;
    int wr = warp >> 2, wc = warp & 3;       // 2 x 4 warp grid
    int group = lane >> 2, tig = lane & 3;
    int m0 = blockIdx.y * GBM, n0 = blockIdx.x * GBN;

    float c[16][4];
    #pragma unroll
    for (int t = 0; t < 16; t++) { c[t][0]=0;c[t][1]=0;c[t][2]=0;c[t][3]=0; }

    for (int k0 = 0; k0 < SS; k0 += 16) {
        if (!tA) {
            int kk = tid & 15, ms = tid >> 4;
            #pragma unroll
            for (int p = 0; p < 8; p++)
                As[kk][ms + p*16] = to_tf32(Ag[(size_t)(m0+ms+p*16)*SS + k0 + kk]);
        } else {
            int mm = tid & 127, ks0 = tid >> 7;
            #pragma unroll
            for (int p = 0; p < 8; p++)
                As[ks0 + p*2][mm] = to_tf32(Ag[(size_t)(k0+ks0+p*2)*SS + m0 + mm]);
        }
        if (!tB) {
            int nn = tid & 127, ks0 = tid >> 7;
            #pragma unroll
            for (int p = 0; p < 8; p++)
                Bs[ks0 + p*2][nn] = to_tf32(Bg[(size_t)(k0+ks0+p*2)*SS + n0 + nn]);
        } else {
            int kk = tid & 15, ns = tid >> 4;
            #pragma unroll
            for (int p = 0; p < 8; p++)
                Bs[kk][ns + p*16] = to_tf32(Bg[(size_t)(n0+ns+p*16)*SS + k0 + kk]);
        }
        __syncthreads();
        #pragma unroll
        for (int ks = 0; ks < 2; ks++) {
            int kb = ks * 8;
            uint32_t af[4][4], bf[4][2];
            #pragma unroll
            for (int i = 0; i < 4; i++) {
                int mb = wr*64 + i*16 + group;
                af[i][0] = __float_as_uint(As[kb+tig  ][mb]);
                af[i][1] = __float_as_uint(As[kb+tig  ][mb+8]);
                af[i][2] = __float_as_uint(As[kb+tig+4][mb]);
                af[i][3] = __float_as_uint(As[kb+tig+4][mb+8]);
            }
            #pragma unroll
            for (int j = 0; j < 4; j++) {
                int nb = wc*32 + j*8 + group;
                bf[j][0] = __float_as_uint(Bs[kb+tig  ][nb]);
                bf[j][1] = __float_as_uint(Bs[kb+tig+4][nb]);
            }
            #pragma unroll
            for (int i = 0; i < 4; i++)
                #pragma unroll
                for (int j = 0; j < 4; j++)
                    mma_tf32(c[i*4+j], af[i][0], af[i][1], af[i][2], af[i][3],
                             bf[j][0], bf[j][1]);
        }
        __syncthreads();
    }
    #pragma unroll
    for (int i = 0; i < 4; i++)
        #pragma unroll
        for (int j = 0; j < 4; j++) {
            int r0 = m0 + wr*64 + i*16 + group;
            int cc = n0 + wc*32 + j*8 + 2*tig;
            float2 v01 = make_float2(c[i*4+j][0], c[i*4+j][1]);
            float2 v23 = make_float2(c[i*4+j][2], c[i*4+j][3]);
            *(float2*)&Cg[(size_t)r0*SS + cc]     = v01;
            *(float2*)&Cg[(size_t)(r0+8)*SS + cc] = v23;
        }
}

// ---------------- 7) rowsums of P,Qm,A2,P2,Q2 ----------------
__global__ __launch_bounds__(256) void rowsum_kernel()
{
    int m = blockIdx.y;                 // 0..4 -> slots 1..5
    const float* Mp = matsel(m + 1);
    size_t row = blockIdx.x;
    int tid = threadIdx.x;
    int wid = tid >> 5, lane = tid & 31;
    __shared__ float sm[8];
    float4 v = ((const float4*)(Mp + row*SS))[tid];
    float s = v.x + v.y + v.z + v.w;
    s = warp_sum(s);
    if (lane == 0) sm[wid] = s;
    __syncthreads();
    if (tid == 0) {
        float t = 0.f;
        #pragma unroll
        for (int i = 0; i < 8; i++) t += sm[i];
        g_rs[(size_t)(m+1)*NTOK + row] = t;
    }
}

// ---------------- 8) fused epilogue: hop_out accumulation into combined ----------------
__global__ __launch_bounds__(256) void fused_kernel(
    const float* __restrict__ fusion_w, const float* __restrict__ fusion_b, int hop)
{
    __shared__ float fs[16][65];
    __shared__ float vs[64][65];
    __shared__ float rsf[16];
    __shared__ float irs_s[16], irs_c[16], irs_p[16];

    int b = blockIdx.y;
    int sr0 = blockIdx.x * 16;
    int tid = threadIdx.x;
    const float *Ms, *Mc, *Mp;
    int rbase;
    if (hop == 0) { Ms = g_A;  Mc = g_P;  Mp = g_Qm; rbase = 0; }
    else          { Ms = g_A2; Mc = g_P2; Mp = g_Q2; rbase = 3; }
    float w0 = fusion_w[hop*3 + 0];
    float w1 = fusion_w[hop*3 + 1];
    float w2 = fusion_w[hop*3 + 2];
    float fb = fusion_b[hop];
    size_t rowbase = (size_t)b*SS + sr0;

    if (tid < 16) {
        irs_s[tid] = 1.f / (g_rs[(size_t)(rbase+0)*NTOK + rowbase + tid] + EPSV);
        irs_c[tid] = 1.f / (g_rs[(size_t)(rbase+1)*NTOK + rowbase + tid] + EPSV);
        irs_p[tid] = 1.f / (g_rs[(size_t)(rbase+2)*NTOK + rowbase + tid] + EPSV);
    }
    __syncthreads();

    int r2 = tid >> 5;       // 0..7 -> rows {2r2, 2r2+1}
    int e2 = tid & 31;       // cols {2e2, 2e2+1}
    float acc00 = 0, acc01 = 0, acc10 = 0, acc11 = 0;
    float rsum0 = 0, rsum1 = 0;
    const float* hv_base = g_hopv + (size_t)hop*NTOK*DD + (size_t)b*SS*DD;

    for (int tc = 0; tc < 16; tc++) {
        int t0 = tc * 64;
        const float* hv = hv_base + (size_t)t0*DD;
        #pragma unroll
        for (int e = tid; e < 64*64; e += 256) vs[e>>6][e&63] = hv[e];
        #pragma unroll
        for (int e = tid; e < 16*64; e += 256) {
            int r = e >> 6, t = e & 63;
            size_t off = (rowbase + r)*SS + t0 + t;
            float ps = fminf(fmaxf(Ms[off]*irs_s[r], EPSV), 1.f-EPSV);
            float pc = fminf(fmaxf(Mc[off]*irs_c[r], EPSV), 1.f-EPSV);
            float pp = fminf(fmaxf(Mp[off]*irs_p[r], EPSV), 1.f-EPSV);
            float L0 = logf(ps/(1.f-ps+EPSV));
            float L1 = logf(pc/(1.f-pc+EPSV));
            float L2 = logf(pp/(1.f-pp+EPSV));
            float logit = fb + w0*L0 + w1*L1 + w2*L2;
            fs[r][t] = 1.f/(1.f+expf(-logit));
        }
        __syncthreads();
        #pragma unroll 8
        for (int t = 0; t < 64; t++) {
            float f0 = fs[2*r2][t],   f1 = fs[2*r2+1][t];
            float v0 = vs[t][2*e2],   v1 = vs[t][2*e2+1];
            acc00 += f0*v0; acc01 += f0*v1;
            acc10 += f1*v0; acc11 += f1*v1;
            if (e2 == 0) { rsum0 += f0; rsum1 += f1; }
        }
        __syncthreads();
    }
    if (e2 == 0) { rsf[2*r2] = rsum0; rsf[2*r2+1] = rsum1; }
    __syncthreads();
    float gt0 = g_gate[(rowbase + 2*r2)*2 + hop];
    float gt1 = g_gate[(rowbase + 2*r2 + 1)*2 + hop];
    float sc0 = gt0 / (rsf[2*r2] + EPSV);
    float sc1 = gt1 / (rsf[2*r2+1] + EPSV);
    float* C0 = g_comb + (rowbase + 2*r2)*DD + 2*e2;
    float* C1 = g_comb + (rowbase + 2*r2 + 1)*DD + 2*e2;
    if (hop == 0) {
        C0[0] = acc00*sc0; C0[1] = acc01*sc0;
        C1[0] = acc10*sc1; C1[1] = acc11*sc1;
    } else {
        C0[0] += acc00*sc0; C0[1] += acc01*sc0;
        C1[0] += acc10*sc1; C1[1] += acc11*sc1;
    }
}

// ---------------- 9) out = combined @ out_W^T ----------------
__global__ __launch_bounds__(256) void outproj_kernel(
    const float* __restrict__ outW, float* __restrict__ out)
{
    __shared__ float cs[16][65];
    __shared__ float ws[128][65];
    int tb = blockIdx.x * 16;
    int tid = threadIdx.x;
    #pragma unroll
    for (int e = tid; e < 16*64; e += 256) cs[e>>6][e&63] = g_comb[(size_t)tb*DD + e];
    int tk2 = tid >> 5;      // 0..7 -> tokens {2tk2, 2tk2+1}
    int h4  = tid & 31;      // h chunk of 4
    for (int hc = 0; hc < 4; hc++) {
        __syncthreads();
        #pragma unroll
        for (int e = tid; e < 128*64; e += 256)
            ws[e>>6][e&63] = outW[(size_t)hc*128*DD + e];
        __syncthreads();
        float a0[4] = {0,0,0,0}, a1[4] = {0,0,0,0};
        #pragma unroll 4
        for (int d = 0; d < 64; d++) {
            float c0 = cs[2*tk2][d], c1 = cs[2*tk2+1][d];
            #pragma unroll
            for (int j = 0; j < 4; j++) {
                float w = ws[h4*4 + j][d];
                a0[j] += c0*w; a1[j] += c1*w;
            }
        }
        *(float4*)&out[(size_t)(tb + 2*tk2)*HID + hc*128 + h4*4] =
            make_float4(a0[0], a0[1], a0[2], a0[3]);
        *(float4*)&out[(size_t)(tb + 2*tk2 + 1)*HID + hc*128 + h4*4] =
            make_float4(a1[0], a1[1], a1[2], a1[3]);
    }
}

// ---------------- launch ----------------
extern "C" void kernel_launch(void* const* d_in, const int* in_sizes, int n_in,
                              void* d_out, int out_size)
{
    const float* x      = (const float*)d_in[0];
    const float* Wq     = (const float*)d_in[1];
    const float* Wk     = (const float*)d_in[2];
    const float* Wv     = (const float*)d_in[3];
    const float* btab   = (const float*)d_in[4];
    const float* fw     = (const float*)d_in[5];
    const float* fbias  = (const float*)d_in[6];
    const float* hopW   = (const float*)d_in[7];
    const float* gateW  = (const float*)d_in[8];
    const float* gateb  = (const float*)d_in[9];
    const float* outW   = (const float*)d_in[10];
    const float* temp   = (const float*)d_in[11];
    const int*   relidx = (const int*)d_in[12];
    float* out = (float*)d_out;

    proj_kernel<<<NTOK/TOK_PB, 256>>>(x, Wq, Wk, Wv, gateW);
    rope_kernel<<<(NTOK*32)/256, 256>>>();
    hopv_gate_kernel<<<(NTOK*DD)/256, 256>>>(hopW, gateb);
    scores_kernel<<<dim3(16,16,NB), 256>>>(btab, relidx, temp);
    softmax_kernel<<<NTOK, 256>>>();

    dim3 gg(SS/GBN, SS/GBM, NB);
    gemm_tf32_kernel<<<gg, 256>>>(0, 0, 1, 0, 1);   // P  = A  A^T
    gemm_tf32_kernel<<<gg, 256>>>(0, 0, 2, 1, 0);   // Qm = A^T A
    gemm_tf32_kernel<<<gg, 256>>>(0, 0, 3, 0, 0);   // A2 = A  A
    gemm_tf32_kernel<<<gg, 256>>>(1, 1, 4, 0, 0);   // P2 = P  P
    gemm_tf32_kernel<<<gg, 256>>>(2, 2, 5, 0, 0);   // Q2 = Qm Qm

    rowsum_kernel<<<dim3(NTOK, 5), 256>>>();
    fused_kernel<<<dim3(SS/16, NB), 256>>>(fw, fbias, 0);
    fused_kernel<<<dim3(SS/16, NB), 256>>>(fw, fbias, 1);
    outproj_kernel<<<NTOK/16, 256>>>(outW, out);
}

// round 5
// speedup vs baseline: 1.3730x; 1.3730x over previous
#include <cuda_runtime.h>
#include <cuda_bf16.h>
#include <cstdint>

#define NB 8
#define SS 1024
#define DD 64
#define HID 512
#define NTOK (NB*SS)          // 8192
#define EPSV 1e-6f

// ---------------- device scratch (no allocation allowed) ----------------
__device__ float g_Q[NTOK*DD];
__device__ float g_K[NTOK*DD];
__device__ float g_V[NTOK*DD];
__device__ float g_hopv[2*NTOK*DD];
__device__ float g_gate[NTOK*2];
__device__ float g_comb[NTOK*DD];
__device__ float g_rs[6*NTOK];           // rowsums: 0=A 1=P 2=Qm 3=A2 4=P2 5=Q2
__device__ float g_A [(size_t)NB*SS*SS]; // softmax attention
__device__ float g_P [(size_t)NB*SS*SS]; // A A^T
__device__ float g_Qm[(size_t)NB*SS*SS]; // A^T A
__device__ float g_A2[(size_t)NB*SS*SS]; // A A
__device__ float g_P2[(size_t)NB*SS*SS]; // P P
__device__ float g_Q2[(size_t)NB*SS*SS]; // Qm Qm
// bf16 GEMM operands
__device__ __nv_bfloat16 g_Ah [(size_t)NB*SS*SS];
__device__ __nv_bfloat16 g_Th [(size_t)NB*SS*SS];
__device__ __nv_bfloat16 g_Ph [(size_t)NB*SS*SS];
__device__ __nv_bfloat16 g_Qmh[(size_t)NB*SS*SS];

__device__ __forceinline__ float* matsel(int s) {
    switch (s) {
        case 0: return g_A;
        case 1: return g_P;
        case 2: return g_Qm;
        case 3: return g_A2;
        case 4: return g_P2;
        default: return g_Q2;
    }
}
__device__ __forceinline__ __nv_bfloat16* hmatsel(int s) {
    switch (s) {
        case 0: return g_Ah;
        case 1: return g_Th;
        case 2: return g_Ph;
        default: return g_Qmh;
    }
}

__device__ __forceinline__ float warp_max(float v) {
    #pragma unroll
    for (int o = 16; o > 0; o >>= 1) v = fmaxf(v, __shfl_xor_sync(0xffffffffu, v, o));
    return v;
}
__device__ __forceinline__ float warp_sum(float v) {
    #pragma unroll
    for (int o = 16; o > 0; o >>= 1) v += __shfl_xor_sync(0xffffffffu, v, o);
    return v;
}

// ---------------- 1) QKV + gate-logit projection ----------------
#define TOK_PB 16
__global__ __launch_bounds__(256) void proj_kernel(
    const float* __restrict__ x, const float* __restrict__ Wq,
    const float* __restrict__ Wk, const float* __restrict__ Wv,
    const float* __restrict__ gW)
{
    __shared__ float xs[TOK_PB*HID];
    int tb = blockIdx.x * TOK_PB;
    int tid = threadIdx.x;
    const float4* xg = (const float4*)(x + (size_t)tb*HID);
    float4* xs4 = (float4*)xs;
    #pragma unroll
    for (int i = tid; i < TOK_PB*HID/4; i += 256) xs4[i] = xg[i];
    __syncthreads();

    for (int o = tid; o < TOK_PB*194; o += 256) {
        int tok = o / 194, ch = o % 194;
        const float* w;
        if (ch < 64)       w = Wq + ch*HID;
        else if (ch < 128) w = Wk + (ch-64)*HID;
        else if (ch < 192) w = Wv + (ch-128)*HID;
        else               w = gW + (ch-192)*HID;
        const float4* w4  = (const float4*)w;
        const float4* xv4 = (const float4*)(xs + tok*HID);
        float acc = 0.f;
        #pragma unroll 8
        for (int k = 0; k < HID/4; k++) {
            float4 a = xv4[k];
            float4 b = __ldg(&w4[k]);
            acc += a.x*b.x + a.y*b.y + a.z*b.z + a.w*b.w;
        }
        size_t gt = tb + tok;
        if (ch < 64)       g_Q[gt*DD + ch]        = acc;
        else if (ch < 128) g_K[gt*DD + (ch-64)]   = acc;
        else if (ch < 192) g_V[gt*DD + (ch-128)]  = acc;
        else               g_gate[gt*2 + (ch-192)] = acc;
    }
}

// ---------------- 2) RoPE in place on Q,K ----------------
__global__ void rope_kernel()
{
    int gid = blockIdx.x*256 + threadIdx.x;
    if (gid >= NTOK*32) return;
    int tok = gid >> 5, j = gid & 31;
    int s = tok & (SS-1);
    float invf = (float)exp(-log(10000.0) * (double)j / 32.0);
    float ang = (float)s * invf;
    float sn, cs;
    sincosf(ang, &sn, &cs);
    size_t base = (size_t)tok * DD;
    float q0 = g_Q[base+j], q1 = g_Q[base+j+32];
    g_Q[base+j]    = q0*cs - q1*sn;
    g_Q[base+j+32] = q1*cs + q0*sn;
    float k0 = g_K[base+j], k1 = g_K[base+j+32];
    g_K[base+j]    = k0*cs - k1*sn;
    g_K[base+j+32] = k1*cs + k0*sn;
}

// ---------------- 3) hop_v = V @ hop_W[h]^T ; gate softmax ----------------
__global__ void hopv_gate_kernel(const float* __restrict__ hopW,
                                 const float* __restrict__ gateb)
{
    int gid = blockIdx.x*256 + threadIdx.x;
    if (gid >= NTOK*DD) return;
    int tok = gid >> 6, e = gid & 63;
    const float* vrow = g_V + (size_t)tok*DD;
    float a0 = 0.f, a1 = 0.f;
    #pragma unroll
    for (int d = 0; d < DD; d++) {
        float v = vrow[d];
        a0 += v * __ldg(&hopW[e*DD + d]);
        a1 += v * __ldg(&hopW[DD*DD + e*DD + d]);
    }
    g_hopv[(size_t)tok*DD + e]              = a0;
    g_hopv[(size_t)NTOK*DD + (size_t)tok*DD + e] = a1;
    if (e == 0) {
        float l0 = g_gate[tok*2]   + gateb[0];
        float l1 = g_gate[tok*2+1] + gateb[1];
        float m = fmaxf(l0, l1);
        float e0 = expf(l0-m), e1 = expf(l1-m);
        float inv = 1.f/(e0+e1);
        g_gate[tok*2]   = e0*inv;
        g_gate[tok*2+1] = e1*inv;
    }
}

// ---------------- 4) scores ----------------
__global__ __launch_bounds__(256) void scores_kernel(
    const float* __restrict__ bias_table, const int* __restrict__ rel_idx,
    const float* __restrict__ temperature)
{
    __shared__ float qs[64][65];
    __shared__ float ks[64][65];
    int b = blockIdx.z;
    int s0 = blockIdx.y * 64, t0 = blockIdx.x * 64;
    int tid = threadIdx.x;
    const float* Qb = g_Q + ((size_t)b*SS + s0)*DD;
    const float* Kb = g_K + ((size_t)b*SS + t0)*DD;
    #pragma unroll
    for (int e = tid; e < 64*64; e += 256) {
        qs[e>>6][e&63] = Qb[e];
        ks[e>>6][e&63] = Kb[e];
    }
    __syncthreads();
    int ty = tid >> 4, tx = tid & 15;
    float c[4][4];
    #pragma unroll
    for (int i=0;i<4;i++) { c[i][0]=0;c[i][1]=0;c[i][2]=0;c[i][3]=0; }
    #pragma unroll 4
    for (int d = 0; d < 64; d++) {
        float rq[4], rk[4];
        #pragma unroll
        for (int i=0;i<4;i++) { rq[i] = qs[ty*4+i][d]; rk[i] = ks[tx*4+i][d]; }
        #pragma unroll
        for (int i=0;i<4;i++)
            #pragma unroll
            for (int j=0;j<4;j++) c[i][j] += rq[i]*rk[j];
    }
    float inv_t = 1.f / fmaxf(temperature[0], 0.1f);
    const float scale = 0.125f;
    float* Ab = g_A + (size_t)b*SS*SS;
    #pragma unroll
    for (int i = 0; i < 4; i++) {
        int s = s0 + ty*4 + i;
        int4 idx = *(const int4*)(rel_idx + (size_t)s*SS + t0 + tx*4);
        float4 out;
        out.x = (c[i][0]*scale + __ldg(&bias_table[idx.x])) * inv_t;
        out.y = (c[i][1]*scale + __ldg(&bias_table[idx.y])) * inv_t;
        out.z = (c[i][2]*scale + __ldg(&bias_table[idx.z])) * inv_t;
        out.w = (c[i][3]*scale + __ldg(&bias_table[idx.w])) * inv_t;
        *(float4*)(Ab + (size_t)s*SS + t0 + tx*4) = out;
    }
}

// ---------------- 5) row softmax in place on g_A (+ bf16 copy) ----------------
__global__ __launch_bounds__(256) void softmax_kernel()
{
    size_t row = blockIdx.x;
    float* Ar = g_A + row*SS;
    __nv_bfloat16* Ah = g_Ah + row*SS;
    int tid = threadIdx.x;
    int wid = tid >> 5, lane = tid & 31;
    __shared__ float sm[8];
    float4 v = ((float4*)Ar)[tid];
    float m = fmaxf(fmaxf(v.x, v.y), fmaxf(v.z, v.w));
    m = warp_max(m);
    if (lane == 0) sm[wid] = m;
    __syncthreads();
    if (wid == 0) {
        float t = (lane < 8) ? sm[lane] : -3.4e38f;
        t = warp_max(t);
        if (lane == 0) sm[0] = t;
    }
    __syncthreads();
    m = sm[0];
    __syncthreads();
    float e0 = expf(v.x-m), e1 = expf(v.y-m), e2 = expf(v.z-m), e3 = expf(v.w-m);
    float s = e0+e1+e2+e3;
    s = warp_sum(s);
    if (lane == 0) sm[wid] = s;
    __syncthreads();
    if (wid == 0) {
        float t = (lane < 8) ? sm[lane] : 0.f;
        t = warp_sum(t);
        if (lane == 0) sm[0] = t;
    }
    __syncthreads();
    float inv = 1.f / sm[0];
    float4 o = make_float4(e0*inv, e1*inv, e2*inv, e3*inv);
    ((float4*)Ar)[tid] = o;
    __nv_bfloat162 h0 = __floats2bfloat162_rn(o.x, o.y);
    __nv_bfloat162 h1 = __floats2bfloat162_rn(o.z, o.w);
    ((__nv_bfloat162*)Ah)[tid*2]   = h0;
    ((__nv_bfloat162*)Ah)[tid*2+1] = h1;
    if (tid == 0) g_rs[row] = 1.0f;
}

// ---------------- 5b) transpose: g_Th = bf16(A^T) per batch ----------------
__global__ __launch_bounds__(256) void transpose_kernel()
{
    __shared__ float t[32][33];
    int b = blockIdx.z;
    int x0 = blockIdx.x*32, y0 = blockIdx.y*32;
    const float* Ab = g_A + (size_t)b*SS*SS;
    __nv_bfloat16* Tb = g_Th + (size_t)b*SS*SS;
    int tx = threadIdx.x & 31, ty = threadIdx.x >> 5;   // 32 x 8
    #pragma unroll
    for (int i = 0; i < 32; i += 8)
        t[ty+i][tx] = Ab[(size_t)(y0+ty+i)*SS + x0+tx];
    __syncthreads();
    #pragma unroll
    for (int i = 0; i < 32; i += 8)
        Tb[(size_t)(x0+ty+i)*SS + y0+tx] = __float2bfloat16(t[tx][ty+i]);
}

// ================= bf16 mma.sync batched NT GEMM =================
// D[m,n] = sum_k a[m,k]*b[n,k] (both operands k-major), 128x128 tile/CTA.
__device__ __forceinline__ uint32_t s2u(const void* p) {
    uint32_t a;
    asm("{ .reg .u64 t; cvta.to.shared.u64 t, %1; cvt.u32.u64 %0, t; }" : "=r"(a) : "l"(p));
    return a;
}
#define SWZ(o) ((o) ^ (((o)>>3)&0x70))

__device__ __forceinline__ void cp16(uint32_t dst, const void* src) {
    asm volatile("cp.async.cg.shared.global [%0], [%1], 16;" :: "r"(dst), "l"(src));
}
__device__ __forceinline__ void cp_commit() { asm volatile("cp.async.commit_group;" ::: "memory"); }
#define CP_WAIT(n) asm volatile("cp.async.wait_group %0;" :: "n"(n) : "memory")

__device__ __forceinline__ void ldsm4(uint32_t* r, uint32_t addr) {
    asm volatile("ldmatrix.sync.aligned.m8n8.x4.shared.b16 {%0,%1,%2,%3}, [%4];"
        : "=r"(r[0]), "=r"(r[1]), "=r"(r[2]), "=r"(r[3]) : "r"(addr));
}
__device__ __forceinline__ void mma_bf16(float* c, const uint32_t* a,
                                         uint32_t b0, uint32_t b1) {
    asm volatile(
        "mma.sync.aligned.m16n8k16.row.col.f32.bf16.bf16.f32 "
        "{%0,%1,%2,%3},{%4,%5,%6,%7},{%8,%9},{%0,%1,%2,%3};"
        : "+f"(c[0]), "+f"(c[1]), "+f"(c[2]), "+f"(c[3])
        : "r"(a[0]), "r"(a[1]), "r"(a[2]), "r"(a[3]), "r"(b0), "r"(b1));
}

#define STG 3
#define CK 64                        // k per chunk (bf16): 128B per row
#define NCH (SS/CK)                  // 16
#define STAGE_BYTES 32768            // A rows [0,128) 16KB | B rows [0,128) 16KB
#define GEMM_DSMEM (STG*STAGE_BYTES) // 98304

__global__ __launch_bounds__(256, 1)
void gemm_bf16_kernel(int phase)
{
    extern __shared__ __align__(16) char dsmem[];
    uint32_t sb = s2u(dsmem);
    int tid = threadIdx.x;
    int warp = tid >> 5, lane = tid & 31;

    int z = blockIdx.z;
    const __nv_bfloat16 *Ag, *Bg;
    float* Cg;
    __nv_bfloat16* Chg = nullptr;
    {
        int b, g;
        if (phase == 0) { b = z/3; g = z%3; }
        else            { b = z/2; g = z%2; }
        size_t off = (size_t)b*SS*SS;
        if (phase == 0) {
            if (g == 0)      { Ag=g_Ah+off; Bg=g_Ah+off; Cg=g_P +off; Chg=g_Ph +off; } // P
            else if (g == 1) { Ag=g_Th+off; Bg=g_Th+off; Cg=g_Qm+off; Chg=g_Qmh+off; } // Qm
            else             { Ag=g_Ah+off; Bg=g_Th+off; Cg=g_A2+off; }                 // A2
        } else {
            if (g == 0)      { Ag=g_Ph +off; Bg=g_Ph +off; Cg=g_P2+off; }               // P2
            else             { Ag=g_Qmh+off; Bg=g_Qmh+off; Cg=g_Q2+off; }               // Q2
        }
    }
    int m0 = blockIdx.y*128, n0 = blockIdx.x*128;

    // warp tile: 2x4 warps, each 64(m) x 32(n)
    int wm = (warp >> 2)*64, wn = (warp & 3)*32;
    int rlane = (lane & 7) + ((lane >> 3) & 1)*8;   // ldmatrix row within 16
    int clane = (lane >> 4) & 1;                    // ldmatrix k-half (chunk of 8)

    float acc[4][4][4];
    #pragma unroll
    for (int i = 0; i < 4; i++)
        #pragma unroll
        for (int j = 0; j < 4; j++) {
            acc[i][j][0]=0; acc[i][j][1]=0; acc[i][j][2]=0; acc[i][j][3]=0;
        }

    // ---- chunk loader: 256 rows x 128B, cp.async 16B each ----
    auto load_chunk = [&](int c) {
        uint32_t stg = sb + (uint32_t)(c % STG) * STAGE_BYTES;
        int k0 = c * CK;
        #pragma unroll
        for (int it = 0; it < 8; it++) {
            int u = tid + it*256;            // 0..2047
            int r = u >> 3;                  // 0..255
            int ch = u & 7;                  // 16B chunk within row
            const __nv_bfloat16* gsrc;
            uint32_t dloc;
            if (r < 128) {
                gsrc = Ag + (size_t)(m0 + r)*SS + k0 + ch*8;
                dloc = SWZ((uint32_t)(r*128 + ch*16));
            } else {
                gsrc = Bg + (size_t)(n0 + (r-128))*SS + k0 + ch*8;
                dloc = 16384u + SWZ((uint32_t)((r-128)*128 + ch*16));
            }
            cp16(stg + dloc, gsrc);
        }
    };

    for (int c = 0; c < STG-1; c++) { load_chunk(c); cp_commit(); }

    for (int c = 0; c < NCH; c++) {
        int lc = c + STG - 1;
        if (lc < NCH) load_chunk(lc);
        cp_commit();
        CP_WAIT(STG-1);
        __syncthreads();
        uint32_t stg = sb + (uint32_t)(c % STG) * STAGE_BYTES;
        #pragma unroll
        for (int ks = 0; ks < CK/16; ks++) {
            uint32_t af[4][4], bfr[2][4];
            int kch = ks*2 + clane;          // 16B chunk index for this lane
            #pragma unroll
            for (int mi = 0; mi < 4; mi++) {
                int r = wm + mi*16 + rlane;
                ldsm4(af[mi], stg + SWZ((uint32_t)(r*128 + kch*16)));
            }
            #pragma unroll
            for (int nt = 0; nt < 2; nt++) {
                int r = wn + nt*16 + rlane;
                ldsm4(bfr[nt], stg + 16384u + SWZ((uint32_t)(r*128 + kch*16)));
            }
            #pragma unroll
            for (int mi = 0; mi < 4; mi++)
                #pragma unroll
                for (int nj = 0; nj < 4; nj++) {
                    int nt = nj >> 1, sel = nj & 1;
                    mma_bf16(acc[mi][nj], af[mi], bfr[nt][sel], bfr[nt][sel+2]);
                }
        }
        __syncthreads();
    }

    // ---- epilogue ----
    int rr = lane >> 2, cc2 = (lane & 3)*2;
    #pragma unroll
    for (int mi = 0; mi < 4; mi++) {
        #pragma unroll
        for (int nj = 0; nj < 4; nj++) {
            int row = m0 + wm + mi*16 + rr;
            int col = n0 + wn + nj*8 + cc2;
            float2 v01 = make_float2(acc[mi][nj][0], acc[mi][nj][1]);
            float2 v23 = make_float2(acc[mi][nj][2], acc[mi][nj][3]);
            *(float2*)&Cg[(size_t)row*SS + col]     = v01;
            *(float2*)&Cg[(size_t)(row+8)*SS + col] = v23;
            if (Chg) {
                *(__nv_bfloat162*)&Chg[(size_t)row*SS + col] =
                    __floats2bfloat162_rn(v01.x, v01.y);
                *(__nv_bfloat162*)&Chg[(size_t)(row+8)*SS + col] =
                    __floats2bfloat162_rn(v23.x, v23.y);
            }
        }
    }
}

// ---------------- 7) rowsums of P,Qm,A2,P2,Q2 ----------------
__global__ __launch_bounds__(256) void rowsum_kernel()
{
    int m = blockIdx.y;
    const float* Mp = matsel(m + 1);
    size_t row = blockIdx.x;
    int tid = threadIdx.x;
    int wid = tid >> 5, lane = tid & 31;
    __shared__ float sm[8];
    float4 v = ((const float4*)(Mp + row*SS))[tid];
    float s = v.x + v.y + v.z + v.w;
    s = warp_sum(s);
    if (lane == 0) sm[wid] = s;
    __syncthreads();
    if (tid == 0) {
        float t = 0.f;
        #pragma unroll
        for (int i = 0; i < 8; i++) t += sm[i];
        g_rs[(size_t)(m+1)*NTOK + row] = t;
    }
}

// ---------------- 8) fused epilogue ----------------
__global__ __launch_bounds__(256) void fused_kernel(
    const float* __restrict__ fusion_w, const float* __restrict__ fusion_b, int hop)
{
    __shared__ float fs[16][65];
    __shared__ float vs[64][65];
    __shared__ float rsf[16];
    __shared__ float irs_s[16], irs_c[16], irs_p[16];

    int b = blockIdx.y;
    int sr0 = blockIdx.x * 16;
    int tid = threadIdx.x;
    const float *Ms, *Mc, *Mp;
    int rbase;
    if (hop == 0) { Ms = g_A;  Mc = g_P;  Mp = g_Qm; rbase = 0; }
    else          { Ms = g_A2; Mc = g_P2; Mp = g_Q2; rbase = 3; }
    float w0 = fusion_w[hop*3 + 0];
    float w1 = fusion_w[hop*3 + 1];
    float w2 = fusion_w[hop*3 + 2];
    float fb = fusion_b[hop];
    size_t rowbase = (size_t)b*SS + sr0;

    if (tid < 16) {
        irs_s[tid] = 1.f / (g_rs[(size_t)(rbase+0)*NTOK + rowbase + tid] + EPSV);
        irs_c[tid] = 1.f / (g_rs[(size_t)(rbase+1)*NTOK + rowbase + tid] + EPSV);
        irs_p[tid] = 1.f / (g_rs[(size_t)(rbase+2)*NTOK + rowbase + tid] + EPSV);
    }
    __syncthreads();

    int r2 = tid >> 5;
    int e2 = tid & 31;
    float acc00 = 0, acc01 = 0, acc10 = 0, acc11 = 0;
    float rsum0 = 0, rsum1 = 0;
    const float* hv_base = g_hopv + (size_t)hop*NTOK*DD + (size_t)b*SS*DD;

    for (int tc = 0; tc < 16; tc++) {
        int t0 = tc * 64;
        const float* hv = hv_base + (size_t)t0*DD;
        #pragma unroll
        for (int e = tid; e < 64*64; e += 256) vs[e>>6][e&63] = hv[e];
        #pragma unroll
        for (int e = tid; e < 16*64; e += 256) {
            int r = e >> 6, t = e & 63;
            size_t off = (rowbase + r)*SS + t0 + t;
            float ps = fminf(fmaxf(Ms[off]*irs_s[r], EPSV), 1.f-EPSV);
            float pc = fminf(fmaxf(Mc[off]*irs_c[r], EPSV), 1.f-EPSV);
            float pp = fminf(fmaxf(Mp[off]*irs_p[r], EPSV), 1.f-EPSV);
            float L0 = logf(ps/(1.f-ps+EPSV));
            float L1 = logf(pc/(1.f-pc+EPSV));
            float L2 = logf(pp/(1.f-pp+EPSV));
            float logit = fb + w0*L0 + w1*L1 + w2*L2;
            fs[r][t] = 1.f/(1.f+expf(-logit));
        }
        __syncthreads();
        #pragma unroll 8
        for (int t = 0; t < 64; t++) {
            float f0 = fs[2*r2][t],   f1 = fs[2*r2+1][t];
            float v0 = vs[t][2*e2],   v1 = vs[t][2*e2+1];
            acc00 += f0*v0; acc01 += f0*v1;
            acc10 += f1*v0; acc11 += f1*v1;
            if (e2 == 0) { rsum0 += f0; rsum1 += f1; }
        }
        __syncthreads();
    }
    if (e2 == 0) { rsf[2*r2] = rsum0; rsf[2*r2+1] = rsum1; }
    __syncthreads();
    float gt0 = g_gate[(rowbase + 2*r2)*2 + hop];
    float gt1 = g_gate[(rowbase + 2*r2 + 1)*2 + hop];
    float sc0 = gt0 / (rsf[2*r2] + EPSV);
    float sc1 = gt1 / (rsf[2*r2+1] + EPSV);
    float* C0 = g_comb + (rowbase + 2*r2)*DD + 2*e2;
    float* C1 = g_comb + (rowbase + 2*r2 + 1)*DD + 2*e2;
    if (hop == 0) {
        C0[0] = acc00*sc0; C0[1] = acc01*sc0;
        C1[0] = acc10*sc1; C1[1] = acc11*sc1;
    } else {
        C0[0] += acc00*sc0; C0[1] += acc01*sc0;
        C1[0] += acc10*sc1; C1[1] += acc11*sc1;
    }
}

// ---------------- 9) out = combined @ out_W^T ----------------
__global__ __launch_bounds__(256) void outproj_kernel(
    const float* __restrict__ outW, float* __restrict__ out)
{
    __shared__ float cs[16][65];
    __shared__ float ws[128][65];
    int tb = blockIdx.x * 16;
    int tid = threadIdx.x;
    #pragma unroll
    for (int e = tid; e < 16*64; e += 256) cs[e>>6][e&63] = g_comb[(size_t)tb*DD + e];
    int tk2 = tid >> 5;
    int h4  = tid & 31;
    for (int hc = 0; hc < 4; hc++) {
        __syncthreads();
        #pragma unroll
        for (int e = tid; e < 128*64; e += 256)
            ws[e>>6][e&63] = outW[(size_t)hc*128*DD + e];
        __syncthreads();
        float a0[4] = {0,0,0,0}, a1[4] = {0,0,0,0};
        #pragma unroll 4
        for (int d = 0; d < 64; d++) {
            float c0 = cs[2*tk2][d], c1 = cs[2*tk2+1][d];
            #pragma unroll
            for (int j = 0; j < 4; j++) {
                float w = ws[h4*4 + j][d];
                a0[j] += c0*w; a1[j] += c1*w;
            }
        }
        *(float4*)&out[(size_t)(tb + 2*tk2)*HID + hc*128 + h4*4] =
            make_float4(a0[0], a0[1], a0[2], a0[3]);
        *(float4*)&out[(size_t)(tb + 2*tk2 + 1)*HID + hc*128 + h4*4] =
            make_float4(a1[0], a1[1], a1[2], a1[3]);
    }
}

// ---------------- launch ----------------
extern "C" void kernel_launch(void* const* d_in, const int* in_sizes, int n_in,
                              void* d_out, int out_size)
{
    const float* x      = (const float*)d_in[0];
    const float* Wq     = (const float*)d_in[1];
    const float* Wk     = (const float*)d_in[2];
    const float* Wv     = (const float*)d_in[3];
    const float* btab   = (const float*)d_in[4];
    const float* fw     = (const float*)d_in[5];
    const float* fbias  = (const float*)d_in[6];
    const float* hopW   = (const float*)d_in[7];
    const float* gateW  = (const float*)d_in[8];
    const float* gateb  = (const float*)d_in[9];
    const float* outW   = (const float*)d_in[10];
    const float* temp   = (const float*)d_in[11];
    const int*   relidx = (const int*)d_in[12];
    float* out = (float*)d_out;

    cudaFuncSetAttribute(gemm_bf16_kernel,
                         cudaFuncAttributeMaxDynamicSharedMemorySize, GEMM_DSMEM);

    proj_kernel<<<NTOK/TOK_PB, 256>>>(x, Wq, Wk, Wv, gateW);
    rope_kernel<<<(NTOK*32)/256, 256>>>();
    hopv_gate_kernel<<<(NTOK*DD)/256, 256>>>(hopW, gateb);
    scores_kernel<<<dim3(16,16,NB), 256>>>(btab, relidx, temp);
    softmax_kernel<<<NTOK, 256>>>();
    transpose_kernel<<<dim3(32,32,NB), 256>>>();

    gemm_bf16_kernel<<<dim3(8,8,NB*3), 256, GEMM_DSMEM>>>(0);  // P, Qm, A2
    gemm_bf16_kernel<<<dim3(8,8,NB*2), 256, GEMM_DSMEM>>>(1);  // P2, Q2

    rowsum_kernel<<<dim3(NTOK, 5), 256>>>();
    fused_kernel<<<dim3(SS/16, NB), 256>>>(fw, fbias, 0);
    fused_kernel<<<dim3(SS/16, NB), 256>>>(fw, fbias, 1);
    outproj_kernel<<<NTOK/16, 256>>>(outW, out);
}

// round 6
// speedup vs baseline: 1.4316x; 1.0427x over previous
#include <cuda_runtime.h>
#include <cuda_bf16.h>
#include <cstdint>

#define NB 8
#define SS 1024
#define DD 64
#define HID 512
#define NTOK (NB*SS)          // 8192
#define EPSV 1e-6f

// ---------------- device scratch (no allocation allowed) ----------------
__device__ float g_Q[NTOK*DD];
__device__ float g_K[NTOK*DD];
__device__ float g_V[NTOK*DD];
__device__ float g_hopv[2*NTOK*DD];
__device__ float g_gate[NTOK*2];
__device__ float g_comb[NTOK*DD];
__device__ float g_rs[6*NTOK];           // rowsums: 0=A 1=P 2=Qm 3=A2 4=P2 5=Q2
__device__ float g_A [(size_t)NB*SS*SS]; // softmax attention
__device__ float g_P [(size_t)NB*SS*SS]; // A A^T
__device__ float g_Qm[(size_t)NB*SS*SS]; // A^T A
__device__ float g_A2[(size_t)NB*SS*SS]; // A A
__device__ float g_P2[(size_t)NB*SS*SS]; // P P
__device__ float g_Q2[(size_t)NB*SS*SS]; // Qm Qm
// bf16 GEMM operands
__device__ __nv_bfloat16 g_Ah [(size_t)NB*SS*SS];
__device__ __nv_bfloat16 g_Th [(size_t)NB*SS*SS];
__device__ __nv_bfloat16 g_Ph [(size_t)NB*SS*SS];
__device__ __nv_bfloat16 g_Qmh[(size_t)NB*SS*SS];

__device__ __forceinline__ float* matsel(int s) {
    switch (s) {
        case 0: return g_A;
        case 1: return g_P;
        case 2: return g_Qm;
        case 3: return g_A2;
        case 4: return g_P2;
        default: return g_Q2;
    }
}
__device__ __forceinline__ __nv_bfloat16* hmatsel(int s) {
    switch (s) {
        case 0: return g_Ah;
        case 1: return g_Th;
        case 2: return g_Ph;
        default: return g_Qmh;
    }
}

__device__ __forceinline__ float warp_max(float v) {
    #pragma unroll
    for (int o = 16; o > 0; o >>= 1) v = fmaxf(v, __shfl_xor_sync(0xffffffffu, v, o));
    return v;
}
__device__ __forceinline__ float warp_sum(float v) {
    #pragma unroll
    for (int o = 16; o > 0; o >>= 1) v += __shfl_xor_sync(0xffffffffu, v, o);
    return v;
}

// ---------------- 1) QKV + gate-logit projection ----------------
#define TOK_PB 16
__global__ __launch_bounds__(256) void proj_kernel(
    const float* __restrict__ x, const float* __restrict__ Wq,
    const float* __restrict__ Wk, const float* __restrict__ Wv,
    const float* __restrict__ gW)
{
    __shared__ float xs[TOK_PB*HID];
    int tb = blockIdx.x * TOK_PB;
    int tid = threadIdx.x;
    const float4* xg = (const float4*)(x + (size_t)tb*HID);
    float4* xs4 = (float4*)xs;
    #pragma unroll
    for (int i = tid; i < TOK_PB*HID/4; i += 256) xs4[i] = xg[i];
    __syncthreads();

    for (int o = tid; o < TOK_PB*194; o += 256) {
        int tok = o / 194, ch = o % 194;
        const float* w;
        if (ch < 64)       w = Wq + ch*HID;
        else if (ch < 128) w = Wk + (ch-64)*HID;
        else if (ch < 192) w = Wv + (ch-128)*HID;
        else               w = gW + (ch-192)*HID;
        const float4* w4  = (const float4*)w;
        const float4* xv4 = (const float4*)(xs + tok*HID);
        float acc = 0.f;
        #pragma unroll 8
        for (int k = 0; k < HID/4; k++) {
            float4 a = xv4[k];
            float4 b = __ldg(&w4[k]);
            acc += a.x*b.x + a.y*b.y + a.z*b.z + a.w*b.w;
        }
        size_t gt = tb + tok;
        if (ch < 64)       g_Q[gt*DD + ch]        = acc;
        else if (ch < 128) g_K[gt*DD + (ch-64)]   = acc;
        else if (ch < 192) g_V[gt*DD + (ch-128)]  = acc;
        else               g_gate[gt*2 + (ch-192)] = acc;
    }
}

// ---------------- 2) RoPE in place on Q,K ----------------
__global__ void rope_kernel()
{
    int gid = blockIdx.x*256 + threadIdx.x;
    if (gid >= NTOK*32) return;
    int tok = gid >> 5, j = gid & 31;
    int s = tok & (SS-1);
    float invf = (float)exp(-log(10000.0) * (double)j / 32.0);
    float ang = (float)s * invf;
    float sn, cs;
    sincosf(ang, &sn, &cs);
    size_t base = (size_t)tok * DD;
    float q0 = g_Q[base+j], q1 = g_Q[base+j+32];
    g_Q[base+j]    = q0*cs - q1*sn;
    g_Q[base+j+32] = q1*cs + q0*sn;
    float k0 = g_K[base+j], k1 = g_K[base+j+32];
    g_K[base+j]    = k0*cs - k1*sn;
    g_K[base+j+32] = k1*cs + k0*sn;
}

// ---------------- 3) hop_v = V @ hop_W[h]^T ; gate softmax ----------------
__global__ void hopv_gate_kernel(const float* __restrict__ hopW,
                                 const float* __restrict__ gateb)
{
    int gid = blockIdx.x*256 + threadIdx.x;
    if (gid >= NTOK*DD) return;
    int tok = gid >> 6, e = gid & 63;
    const float* vrow = g_V + (size_t)tok*DD;
    float a0 = 0.f, a1 = 0.f;
    #pragma unroll
    for (int d = 0; d < DD; d++) {
        float v = vrow[d];
        a0 += v * __ldg(&hopW[e*DD + d]);
        a1 += v * __ldg(&hopW[DD*DD + e*DD + d]);
    }
    g_hopv[(size_t)tok*DD + e]              = a0;
    g_hopv[(size_t)NTOK*DD + (size_t)tok*DD + e] = a1;
    if (e == 0) {
        float l0 = g_gate[tok*2]   + gateb[0];
        float l1 = g_gate[tok*2+1] + gateb[1];
        float m = fmaxf(l0, l1);
        float e0 = expf(l0-m), e1 = expf(l1-m);
        float inv = 1.f/(e0+e1);
        g_gate[tok*2]   = e0*inv;
        g_gate[tok*2+1] = e1*inv;
    }
}

// ---------------- 4) scores ----------------
__global__ __launch_bounds__(256) void scores_kernel(
    const float* __restrict__ bias_table, const int* __restrict__ rel_idx,
    const float* __restrict__ temperature)
{
    __shared__ float qs[64][65];
    __shared__ float ks[64][65];
    int b = blockIdx.z;
    int s0 = blockIdx.y * 64, t0 = blockIdx.x * 64;
    int tid = threadIdx.x;
    const float* Qb = g_Q + ((size_t)b*SS + s0)*DD;
    const float* Kb = g_K + ((size_t)b*SS + t0)*DD;
    #pragma unroll
    for (int e = tid; e < 64*64; e += 256) {
        qs[e>>6][e&63] = Qb[e];
        ks[e>>6][e&63] = Kb[e];
    }
    __syncthreads();
    int ty = tid >> 4, tx = tid & 15;
    float c[4][4];
    #pragma unroll
    for (int i=0;i<4;i++) { c[i][0]=0;c[i][1]=0;c[i][2]=0;c[i][3]=0; }
    #pragma unroll 4
    for (int d = 0; d < 64; d++) {
        float rq[4], rk[4];
        #pragma unroll
        for (int i=0;i<4;i++) { rq[i] = qs[ty*4+i][d]; rk[i] = ks[tx*4+i][d]; }
        #pragma unroll
        for (int i=0;i<4;i++)
            #pragma unroll
            for (int j=0;j<4;j++) c[i][j] += rq[i]*rk[j];
    }
    float inv_t = 1.f / fmaxf(temperature[0], 0.1f);
    const float scale = 0.125f;
    float* Ab = g_A + (size_t)b*SS*SS;
    #pragma unroll
    for (int i = 0; i < 4; i++) {
        int s = s0 + ty*4 + i;
        int4 idx = *(const int4*)(rel_idx + (size_t)s*SS + t0 + tx*4);
        float4 out;
        out.x = (c[i][0]*scale + __ldg(&bias_table[idx.x])) * inv_t;
        out.y = (c[i][1]*scale + __ldg(&bias_table[idx.y])) * inv_t;
        out.z = (c[i][2]*scale + __ldg(&bias_table[idx.z])) * inv_t;
        out.w = (c[i][3]*scale + __ldg(&bias_table[idx.w])) * inv_t;
        *(float4*)(Ab + (size_t)s*SS + t0 + tx*4) = out;
    }
}

// ---------------- 5) row softmax in place on g_A (+ bf16 copy) ----------------
__global__ __launch_bounds__(256) void softmax_kernel()
{
    size_t row = blockIdx.x;
    float* Ar = g_A + row*SS;
    __nv_bfloat16* Ah = g_Ah + row*SS;
    int tid = threadIdx.x;
    int wid = tid >> 5, lane = tid & 31;
    __shared__ float sm[8];
    float4 v = ((float4*)Ar)[tid];
    float m = fmaxf(fmaxf(v.x, v.y), fmaxf(v.z, v.w));
    m = warp_max(m);
    if (lane == 0) sm[wid] = m;
    __syncthreads();
    if (wid == 0) {
        float t = (lane < 8) ? sm[lane] : -3.4e38f;
        t = warp_max(t);
        if (lane == 0) sm[0] = t;
    }
    __syncthreads();
    m = sm[0];
    __syncthreads();
    float e0 = expf(v.x-m), e1 = expf(v.y-m), e2 = expf(v.z-m), e3 = expf(v.w-m);
    float s = e0+e1+e2+e3;
    s = warp_sum(s);
    if (lane == 0) sm[wid] = s;
    __syncthreads();
    if (wid == 0) {
        float t = (lane < 8) ? sm[lane] : 0.f;
        t = warp_sum(t);
        if (lane == 0) sm[0] = t;
    }
    __syncthreads();
    float inv = 1.f / sm[0];
    float4 o = make_float4(e0*inv, e1*inv, e2*inv, e3*inv);
    ((float4*)Ar)[tid] = o;
    __nv_bfloat162 h0 = __floats2bfloat162_rn(o.x, o.y);
    __nv_bfloat162 h1 = __floats2bfloat162_rn(o.z, o.w);
    ((__nv_bfloat162*)Ah)[tid*2]   = h0;
    ((__nv_bfloat162*)Ah)[tid*2+1] = h1;
    if (tid == 0) g_rs[row] = 1.0f;
}

// ---------------- 5b) transpose: g_Th = bf16(A^T) per batch ----------------
__global__ __launch_bounds__(256) void transpose_kernel()
{
    __shared__ float t[32][33];
    int b = blockIdx.z;
    int x0 = blockIdx.x*32, y0 = blockIdx.y*32;
    const float* Ab = g_A + (size_t)b*SS*SS;
    __nv_bfloat16* Tb = g_Th + (size_t)b*SS*SS;
    int tx = threadIdx.x & 31, ty = threadIdx.x >> 5;   // 32 x 8
    #pragma unroll
    for (int i = 0; i < 32; i += 8)
        t[ty+i][tx] = Ab[(size_t)(y0+ty+i)*SS + x0+tx];
    __syncthreads();
    #pragma unroll
    for (int i = 0; i < 32; i += 8)
        Tb[(size_t)(x0+ty+i)*SS + y0+tx] = __float2bfloat16(t[tx][ty+i]);
}

// ================= bf16 mma.sync batched NT GEMM =================
// D[m,n] = sum_k a[m,k]*b[n,k] (both operands k-major), 128x128 tile/CTA.
// tri=1: compute only upper-triangle blocks (bi<=bj) of a symmetric product.
__device__ __forceinline__ uint32_t s2u(const void* p) {
    uint32_t a;
    asm("{ .reg .u64 t; cvta.to.shared.u64 t, %1; cvt.u32.u64 %0, t; }" : "=r"(a) : "l"(p));
    return a;
}
#define SWZ(o) ((o) ^ (((o)>>3)&0x70))

__device__ __forceinline__ void cp16(uint32_t dst, const void* src) {
    asm volatile("cp.async.cg.shared.global [%0], [%1], 16;" :: "r"(dst), "l"(src));
}
__device__ __forceinline__ void cp_commit() { asm volatile("cp.async.commit_group;" ::: "memory"); }
#define CP_WAIT(n) asm volatile("cp.async.wait_group %0;" :: "n"(n) : "memory")

__device__ __forceinline__ void ldsm4(uint32_t* r, uint32_t addr) {
    asm volatile("ldmatrix.sync.aligned.m8n8.x4.shared.b16 {%0,%1,%2,%3}, [%4];"
        : "=r"(r[0]), "=r"(r[1]), "=r"(r[2]), "=r"(r[3]) : "r"(addr));
}
__device__ __forceinline__ void mma_bf16(float* c, const uint32_t* a,
                                         uint32_t b0, uint32_t b1) {
    asm volatile(
        "mma.sync.aligned.m16n8k16.row.col.f32.bf16.bf16.f32 "
        "{%0,%1,%2,%3},{%4,%5,%6,%7},{%8,%9},{%0,%1,%2,%3};"
        : "+f"(c[0]), "+f"(c[1]), "+f"(c[2]), "+f"(c[3])
        : "r"(a[0]), "r"(a[1]), "r"(a[2]), "r"(a[3]), "r"(b0), "r"(b1));
}

#define STG 3
#define CK 64                        // k per chunk (bf16): 128B per row
#define NCH (SS/CK)                  // 16
#define STAGE_BYTES 32768            // A rows [0,128) 16KB | B rows [0,128) 16KB
#define GEMM_DSMEM (STG*STAGE_BYTES) // 98304

__global__ __launch_bounds__(256, 2)
void gemm_bf16_kernel(int asel, int bsel, int cfsel, int chsel, int tri)
{
    extern __shared__ __align__(16) char dsmem[];
    uint32_t sb = s2u(dsmem);
    int tid = threadIdx.x;
    int warp = tid >> 5, lane = tid & 31;

    size_t off = (size_t)blockIdx.z*SS*SS;
    const __nv_bfloat16* Ag = hmatsel(asel) + off;
    const __nv_bfloat16* Bg = hmatsel(bsel) + off;
    float* Cg = matsel(cfsel) + off;
    __nv_bfloat16* Chg = (chsel >= 0) ? hmatsel(chsel) + off : nullptr;

    int bi, bj;
    if (tri) {
        int t = blockIdx.x, i = 0;
        while (t >= 8 - i) { t -= 8 - i; i++; }
        bi = i; bj = i + t;
    } else {
        bi = blockIdx.x >> 3; bj = blockIdx.x & 7;
    }
    int m0 = bi*128, n0 = bj*128;
    bool same = (tri != 0) && (bi == bj) && (asel == bsel);
    uint32_t bBase = same ? 0u : 16384u;

    // warp tile: 2x4 warps, each 64(m) x 32(n)
    int wm = (warp >> 2)*64, wn = (warp & 3)*32;
    int rlane = (lane & 7) + ((lane >> 3) & 1)*8;   // ldmatrix row within 16
    int clane = (lane >> 4) & 1;                    // ldmatrix k-half (chunk of 8)

    float acc[4][4][4];
    #pragma unroll
    for (int i = 0; i < 4; i++)
        #pragma unroll
        for (int j = 0; j < 4; j++) {
            acc[i][j][0]=0; acc[i][j][1]=0; acc[i][j][2]=0; acc[i][j][3]=0;
        }

    // ---- chunk loader: (A 128 rows [+ B 128 rows]) x 128B, cp.async 16B ----
    auto load_chunk = [&](int c) {
        uint32_t stg = sb + (uint32_t)(c % STG) * STAGE_BYTES;
        int k0 = c * CK;
        #pragma unroll
        for (int it = 0; it < 8; it++) {
            int u = tid + it*256;            // 0..2047
            int r = u >> 3;                  // 0..255
            int ch = u & 7;                  // 16B chunk within row
            if (r < 128) {
                const __nv_bfloat16* gsrc = Ag + (size_t)(m0 + r)*SS + k0 + ch*8;
                cp16(stg + SWZ((uint32_t)(r*128 + ch*16)), gsrc);
            } else if (!same) {
                const __nv_bfloat16* gsrc = Bg + (size_t)(n0 + (r-128))*SS + k0 + ch*8;
                cp16(stg + 16384u + SWZ((uint32_t)((r-128)*128 + ch*16)), gsrc);
            }
        }
    };

    for (int c = 0; c < STG-1; c++) { load_chunk(c); cp_commit(); }

    for (int c = 0; c < NCH; c++) {
        int lc = c + STG - 1;
        if (lc < NCH) load_chunk(lc);
        cp_commit();
        CP_WAIT(STG-1);
        __syncthreads();
        uint32_t stg = sb + (uint32_t)(c % STG) * STAGE_BYTES;
        #pragma unroll
        for (int ks = 0; ks < CK/16; ks++) {
            uint32_t af[4][4], bfr[2][4];
            int kch = ks*2 + clane;          // 16B chunk index for this lane
            #pragma unroll
            for (int mi = 0; mi < 4; mi++) {
                int r = wm + mi*16 + rlane;
                ldsm4(af[mi], stg + SWZ((uint32_t)(r*128 + kch*16)));
            }
            #pragma unroll
            for (int nt = 0; nt < 2; nt++) {
                int r = wn + nt*16 + rlane;
                ldsm4(bfr[nt], stg + bBase + SWZ((uint32_t)(r*128 + kch*16)));
            }
            #pragma unroll
            for (int mi = 0; mi < 4; mi++)
                #pragma unroll
                for (int nj = 0; nj < 4; nj++) {
                    int nt = nj >> 1, sel = nj & 1;
                    mma_bf16(acc[mi][nj], af[mi], bfr[nt][sel], bfr[nt][sel+2]);
                }
        }
        __syncthreads();
    }

    // ---- epilogue ----
    int rr = lane >> 2, cc2 = (lane & 3)*2;
    #pragma unroll
    for (int mi = 0; mi < 4; mi++) {
        #pragma unroll
        for (int nj = 0; nj < 4; nj++) {
            int row = m0 + wm + mi*16 + rr;
            int col = n0 + wn + nj*8 + cc2;
            float2 v01 = make_float2(acc[mi][nj][0], acc[mi][nj][1]);
            float2 v23 = make_float2(acc[mi][nj][2], acc[mi][nj][3]);
            *(float2*)&Cg[(size_t)row*SS + col]     = v01;
            *(float2*)&Cg[(size_t)(row+8)*SS + col] = v23;
            if (Chg) {
                *(__nv_bfloat162*)&Chg[(size_t)row*SS + col] =
                    __floats2bfloat162_rn(v01.x, v01.y);
                *(__nv_bfloat162*)&Chg[(size_t)(row+8)*SS + col] =
                    __floats2bfloat162_rn(v23.x, v23.y);
            }
        }
    }
}

// ---------------- 6b) mirror lower triangle of symmetric matrix ----------------
// grid: x = 28 block-pairs (bi<bj), y = 16 subtiles (4x4 of 32), z = batch
__global__ __launch_bounds__(256) void mirror_kernel(int msel, int hsel)
{
    __shared__ float t[32][33];
    size_t off = (size_t)blockIdx.z*SS*SS;
    float* M = matsel(msel) + off;
    __nv_bfloat16* Mh = (hsel >= 0) ? hmatsel(hsel) + off : nullptr;

    int p = blockIdx.x, i = 0;
    while (p >= 7 - i) { p -= 7 - i; i++; }
    int j = i + 1 + p;
    int sub = blockIdx.y;
    int y0 = i*128 + (sub >> 2)*32;     // source rows
    int x0 = j*128 + (sub & 3)*32;      // source cols
    int tx = threadIdx.x & 31, ty = threadIdx.x >> 5;  // 32 x 8
    #pragma unroll
    for (int k = 0; k < 32; k += 8)
        t[ty+k][tx] = M[(size_t)(y0+ty+k)*SS + x0+tx];
    __syncthreads();
    #pragma unroll
    for (int k = 0; k < 32; k += 8) {
        float v = t[tx][ty+k];
        size_t dst = (size_t)(x0+ty+k)*SS + y0+tx;
        M[dst] = v;
        if (Mh) Mh[dst] = __float2bfloat16(v);
    }
}

// ---------------- 7) rowsums of P,Qm,A2,P2,Q2 ----------------
__global__ __launch_bounds__(256) void rowsum_kernel()
{
    int m = blockIdx.y;
    const float* Mp = matsel(m + 1);
    size_t row = blockIdx.x;
    int tid = threadIdx.x;
    int wid = tid >> 5, lane = tid & 31;
    __shared__ float sm[8];
    float4 v = ((const float4*)(Mp + row*SS))[tid];
    float s = v.x + v.y + v.z + v.w;
    s = warp_sum(s);
    if (lane == 0) sm[wid] = s;
    __syncthreads();
    if (tid == 0) {
        float t = 0.f;
        #pragma unroll
        for (int i = 0; i < 8; i++) t += sm[i];
        g_rs[(size_t)(m+1)*NTOK + row] = t;
    }
}

// ---------------- 8) fused epilogue ----------------
__global__ __launch_bounds__(256) void fused_kernel(
    const float* __restrict__ fusion_w, const float* __restrict__ fusion_b, int hop)
{
    __shared__ float fs[16][65];
    __shared__ float vs[64][65];
    __shared__ float rsf[16];
    __shared__ float irs_s[16], irs_c[16], irs_p[16];

    int b = blockIdx.y;
    int sr0 = blockIdx.x * 16;
    int tid = threadIdx.x;
    const float *Ms, *Mc, *Mp;
    int rbase;
    if (hop == 0) { Ms = g_A;  Mc = g_P;  Mp = g_Qm; rbase = 0; }
    else          { Ms = g_A2; Mc = g_P2; Mp = g_Q2; rbase = 3; }
    float w0 = fusion_w[hop*3 + 0];
    float w1 = fusion_w[hop*3 + 1];
    float w2 = fusion_w[hop*3 + 2];
    float fb = fusion_b[hop];
    size_t rowbase = (size_t)b*SS + sr0;

    if (tid < 16) {
        irs_s[tid] = 1.f / (g_rs[(size_t)(rbase+0)*NTOK + rowbase + tid] + EPSV);
        irs_c[tid] = 1.f / (g_rs[(size_t)(rbase+1)*NTOK + rowbase + tid] + EPSV);
        irs_p[tid] = 1.f / (g_rs[(size_t)(rbase+2)*NTOK + rowbase + tid] + EPSV);
    }
    __syncthreads();

    int r2 = tid >> 5;
    int e2 = tid & 31;
    float acc00 = 0, acc01 = 0, acc10 = 0, acc11 = 0;
    float rsum0 = 0, rsum1 = 0;
    const float* hv_base = g_hopv + (size_t)hop*NTOK*DD + (size_t)b*SS*DD;

    for (int tc = 0; tc < 16; tc++) {
        int t0 = tc * 64;
        const float* hv = hv_base + (size_t)t0*DD;
        #pragma unroll
        for (int e = tid; e < 64*64; e += 256) vs[e>>6][e&63] = hv[e];
        #pragma unroll
        for (int e = tid; e < 16*64; e += 256) {
            int r = e >> 6, t = e & 63;
            size_t off = (rowbase + r)*SS + t0 + t;
            float ps = fminf(fmaxf(Ms[off]*irs_s[r], EPSV), 1.f-EPSV);
            float pc = fminf(fmaxf(Mc[off]*irs_c[r], EPSV), 1.f-EPSV);
            float pp = fminf(fmaxf(Mp[off]*irs_p[r], EPSV), 1.f-EPSV);
            float L0 = logf(ps/(1.f-ps+EPSV));
            float L1 = logf(pc/(1.f-pc+EPSV));
            float L2 = logf(pp/(1.f-pp+EPSV));
            float logit = fb + w0*L0 + w1*L1 + w2*L2;
            fs[r][t] = 1.f/(1.f+expf(-logit));
        }
        __syncthreads();
        #pragma unroll 8
        for (int t = 0; t < 64; t++) {
            float f0 = fs[2*r2][t],   f1 = fs[2*r2+1][t];
            float v0 = vs[t][2*e2],   v1 = vs[t][2*e2+1];
            acc00 += f0*v0; acc01 += f0*v1;
            acc10 += f1*v0; acc11 += f1*v1;
            if (e2 == 0) { rsum0 += f0; rsum1 += f1; }
        }
        __syncthreads();
    }
    if (e2 == 0) { rsf[2*r2] = rsum0; rsf[2*r2+1] = rsum1; }
    __syncthreads();
    float gt0 = g_gate[(rowbase + 2*r2)*2 + hop];
    float gt1 = g_gate[(rowbase + 2*r2 + 1)*2 + hop];
    float sc0 = gt0 / (rsf[2*r2] + EPSV);
    float sc1 = gt1 / (rsf[2*r2+1] + EPSV);
    float* C0 = g_comb + (rowbase + 2*r2)*DD + 2*e2;
    float* C1 = g_comb + (rowbase + 2*r2 + 1)*DD + 2*e2;
    if (hop == 0) {
        C0[0] = acc00*sc0; C0[1] = acc01*sc0;
        C1[0] = acc10*sc1; C1[1] = acc11*sc1;
    } else {
        C0[0] += acc00*sc0; C0[1] += acc01*sc0;
        C1[0] += acc10*sc1; C1[1] += acc11*sc1;
    }
}

// ---------------- 9) out = combined @ out_W^T ----------------
__global__ __launch_bounds__(256) void outproj_kernel(
    const float* __restrict__ outW, float* __restrict__ out)
{
    __shared__ float cs[16][65];
    __shared__ float ws[128][65];
    int tb = blockIdx.x * 16;
    int tid = threadIdx.x;
    #pragma unroll
    for (int e = tid; e < 16*64; e += 256) cs[e>>6][e&63] = g_comb[(size_t)tb*DD + e];
    int tk2 = tid >> 5;
    int h4  = tid & 31;
    for (int hc = 0; hc < 4; hc++) {
        __syncthreads();
        #pragma unroll
        for (int e = tid; e < 128*64; e += 256)
            ws[e>>6][e&63] = outW[(size_t)hc*128*DD + e];
        __syncthreads();
        float a0[4] = {0,0,0,0}, a1[4] = {0,0,0,0};
        #pragma unroll 4
        for (int d = 0; d < 64; d++) {
            float c0 = cs[2*tk2][d], c1 = cs[2*tk2+1][d];
            #pragma unroll
            for (int j = 0; j < 4; j++) {
                float w = ws[h4*4 + j][d];
                a0[j] += c0*w; a1[j] += c1*w;
            }
        }
        *(float4*)&out[(size_t)(tb + 2*tk2)*HID + hc*128 + h4*4] =
            make_float4(a0[0], a0[1], a0[2], a0[3]);
        *(float4*)&out[(size_t)(tb + 2*tk2 + 1)*HID + hc*128 + h4*4] =
            make_float4(a1[0], a1[1], a1[2], a1[3]);
    }
}

// ---------------- launch ----------------
extern "C" void kernel_launch(void* const* d_in, const int* in_sizes, int n_in,
                              void* d_out, int out_size)
{
    const float* x      = (const float*)d_in[0];
    const float* Wq     = (const float*)d_in[1];
    const float* Wk     = (const float*)d_in[2];
    const float* Wv     = (const float*)d_in[3];
    const float* btab   = (const float*)d_in[4];
    const float* fw     = (const float*)d_in[5];
    const float* fbias  = (const float*)d_in[6];
    const float* hopW   = (const float*)d_in[7];
    const float* gateW  = (const float*)d_in[8];
    const float* gateb  = (const float*)d_in[9];
    const float* outW   = (const float*)d_in[10];
    const float* temp   = (const float*)d_in[11];
    const int*   relidx = (const int*)d_in[12];
    float* out = (float*)d_out;

    cudaFuncSetAttribute(gemm_bf16_kernel,
                         cudaFuncAttributeMaxDynamicSharedMemorySize, GEMM_DSMEM);

    proj_kernel<<<NTOK/TOK_PB, 256>>>(x, Wq, Wk, Wv, gateW);
    rope_kernel<<<(NTOK*32)/256, 256>>>();
    hopv_gate_kernel<<<(NTOK*DD)/256, 256>>>(hopW, gateb);
    scores_kernel<<<dim3(16,16,NB), 256>>>(btab, relidx, temp);
    softmax_kernel<<<NTOK, 256>>>();
    transpose_kernel<<<dim3(32,32,NB), 256>>>();

    // hmat: 0=Ah 1=Th 2=Ph 3=Qmh ; mat: 1=P 2=Qm 3=A2 4=P2 5=Q2
    gemm_bf16_kernel<<<dim3(36,1,NB), 256, GEMM_DSMEM>>>(0,0,1, 2, 1); // P  = Ah Ah^T (tri)
    gemm_bf16_kernel<<<dim3(36,1,NB), 256, GEMM_DSMEM>>>(1,1,2, 3, 1); // Qm = Th Th^T (tri)
    gemm_bf16_kernel<<<dim3(64,1,NB), 256, GEMM_DSMEM>>>(0,1,3,-1, 0); // A2 = Ah Th^T (full)
    mirror_kernel<<<dim3(28,16,NB), 256>>>(1, 2);  // P  (+Ph)
    mirror_kernel<<<dim3(28,16,NB), 256>>>(2, 3);  // Qm (+Qmh)
    gemm_bf16_kernel<<<dim3(36,1,NB), 256, GEMM_DSMEM>>>(2,2,4,-1, 1); // P2 = Ph Ph^T (tri)
    gemm_bf16_kernel<<<dim3(36,1,NB), 256, GEMM_DSMEM>>>(3,3,5,-1, 1); // Q2 = Qmh Qmh^T (tri)
    mirror_kernel<<<dim3(28,16,NB), 256>>>(4, -1); // P2
    mirror_kernel<<<dim3(28,16,NB), 256>>>(5, -1); // Q2

    rowsum_kernel<<<dim3(NTOK, 5), 256>>>();
    fused_kernel<<<dim3(SS/16, NB), 256>>>(fw, fbias, 0);
    fused_kernel<<<dim3(SS/16, NB), 256>>>(fw, fbias, 1);
    outproj_kernel<<<NTOK/16, 256>>>(outW, out);
}

// round 7
// speedup vs baseline: 1.5722x; 1.0982x over previous
#include <cuda_runtime.h>
#include <cuda_bf16.h>
#include <cstdint>

#define NB 8
#define SS 1024
#define DD 64
#define HID 512
#define NTOK (NB*SS)          // 8192
#define EPSV 1e-6f

// ---------------- device scratch (no allocation allowed) ----------------
__device__ float g_Q[NTOK*DD];
__device__ float g_K[NTOK*DD];
__device__ float g_V[NTOK*DD];
__device__ float g_hopv[2*NTOK*DD];
__device__ float g_gate[NTOK*2];
__device__ float g_comb[NTOK*DD];
__device__ float g_rs[6*NTOK];           // rowsums: 0=A 1=P 2=Qm 3=A2 4=P2 5=Q2
__device__ float g_A [(size_t)NB*SS*SS]; // softmax attention
__device__ float g_P [(size_t)NB*SS*SS]; // A A^T
__device__ float g_Qm[(size_t)NB*SS*SS]; // A^T A
__device__ float g_A2[(size_t)NB*SS*SS]; // A A
__device__ float g_P2[(size_t)NB*SS*SS]; // P P
__device__ float g_Q2[(size_t)NB*SS*SS]; // Qm Qm
// bf16 GEMM operands
__device__ __nv_bfloat16 g_Ah [(size_t)NB*SS*SS];
__device__ __nv_bfloat16 g_Th [(size_t)NB*SS*SS];
__device__ __nv_bfloat16 g_Ph [(size_t)NB*SS*SS];
__device__ __nv_bfloat16 g_Qmh[(size_t)NB*SS*SS];

__device__ __forceinline__ float* matsel(int s) {
    switch (s) {
        case 0: return g_A;
        case 1: return g_P;
        case 2: return g_Qm;
        case 3: return g_A2;
        case 4: return g_P2;
        default: return g_Q2;
    }
}
__device__ __forceinline__ __nv_bfloat16* hmatsel(int s) {
    switch (s) {
        case 0: return g_Ah;
        case 1: return g_Th;
        case 2: return g_Ph;
        default: return g_Qmh;
    }
}

__device__ __forceinline__ float warp_max(float v) {
    #pragma unroll
    for (int o = 16; o > 0; o >>= 1) v = fmaxf(v, __shfl_xor_sync(0xffffffffu, v, o));
    return v;
}
__device__ __forceinline__ float warp_sum(float v) {
    #pragma unroll
    for (int o = 16; o > 0; o >>= 1) v += __shfl_xor_sync(0xffffffffu, v, o);
    return v;
}

// ---------------- 1) QKV + gate-logit projection ----------------
#define TOK_PB 16
__global__ __launch_bounds__(256) void proj_kernel(
    const float* __restrict__ x, const float* __restrict__ Wq,
    const float* __restrict__ Wk, const float* __restrict__ Wv,
    const float* __restrict__ gW)
{
    __shared__ float xs[TOK_PB*HID];
    int tb = blockIdx.x * TOK_PB;
    int tid = threadIdx.x;
    const float4* xg = (const float4*)(x + (size_t)tb*HID);
    float4* xs4 = (float4*)xs;
    #pragma unroll
    for (int i = tid; i < TOK_PB*HID/4; i += 256) xs4[i] = xg[i];
    __syncthreads();

    for (int o = tid; o < TOK_PB*194; o += 256) {
        int tok = o / 194, ch = o % 194;
        const float* w;
        if (ch < 64)       w = Wq + ch*HID;
        else if (ch < 128) w = Wk + (ch-64)*HID;
        else if (ch < 192) w = Wv + (ch-128)*HID;
        else               w = gW + (ch-192)*HID;
        const float4* w4  = (const float4*)w;
        const float4* xv4 = (const float4*)(xs + tok*HID);
        float acc = 0.f;
        #pragma unroll 8
        for (int k = 0; k < HID/4; k++) {
            float4 a = xv4[k];
            float4 b = __ldg(&w4[k]);
            acc += a.x*b.x + a.y*b.y + a.z*b.z + a.w*b.w;
        }
        size_t gt = tb + tok;
        if (ch < 64)       g_Q[gt*DD + ch]        = acc;
        else if (ch < 128) g_K[gt*DD + (ch-64)]   = acc;
        else if (ch < 192) g_V[gt*DD + (ch-128)]  = acc;
        else               g_gate[gt*2 + (ch-192)] = acc;
    }
}

// ---------------- 2) RoPE in place on Q,K ----------------
__global__ void rope_kernel()
{
    int gid = blockIdx.x*256 + threadIdx.x;
    if (gid >= NTOK*32) return;
    int tok = gid >> 5, j = gid & 31;
    int s = tok & (SS-1);
    float invf = (float)exp(-log(10000.0) * (double)j / 32.0);
    float ang = (float)s * invf;
    float sn, cs;
    sincosf(ang, &sn, &cs);
    size_t base = (size_t)tok * DD;
    float q0 = g_Q[base+j], q1 = g_Q[base+j+32];
    g_Q[base+j]    = q0*cs - q1*sn;
    g_Q[base+j+32] = q1*cs + q0*sn;
    float k0 = g_K[base+j], k1 = g_K[base+j+32];
    g_K[base+j]    = k0*cs - k1*sn;
    g_K[base+j+32] = k1*cs + k0*sn;
}

// ---------------- 3) hop_v = V @ hop_W[h]^T ; gate softmax ----------------
__global__ void hopv_gate_kernel(const float* __restrict__ hopW,
                                 const float* __restrict__ gateb)
{
    int gid = blockIdx.x*256 + threadIdx.x;
    if (gid >= NTOK*DD) return;
    int tok = gid >> 6, e = gid & 63;
    const float* vrow = g_V + (size_t)tok*DD;
    float a0 = 0.f, a1 = 0.f;
    #pragma unroll
    for (int d = 0; d < DD; d++) {
        float v = vrow[d];
        a0 += v * __ldg(&hopW[e*DD + d]);
        a1 += v * __ldg(&hopW[DD*DD + e*DD + d]);
    }
    g_hopv[(size_t)tok*DD + e]              = a0;
    g_hopv[(size_t)NTOK*DD + (size_t)tok*DD + e] = a1;
    if (e == 0) {
        float l0 = g_gate[tok*2]   + gateb[0];
        float l1 = g_gate[tok*2+1] + gateb[1];
        float m = fmaxf(l0, l1);
        float e0 = __expf(l0-m), e1 = __expf(l1-m);
        float inv = 1.f/(e0+e1);
        g_gate[tok*2]   = e0*inv;
        g_gate[tok*2+1] = e1*inv;
    }
}

// ---------------- 4) scores ----------------
__global__ __launch_bounds__(256) void scores_kernel(
    const float* __restrict__ bias_table, const int* __restrict__ rel_idx,
    const float* __restrict__ temperature)
{
    __shared__ float qs[64][65];
    __shared__ float ks[64][65];
    int b = blockIdx.z;
    int s0 = blockIdx.y * 64, t0 = blockIdx.x * 64;
    int tid = threadIdx.x;
    const float* Qb = g_Q + ((size_t)b*SS + s0)*DD;
    const float* Kb = g_K + ((size_t)b*SS + t0)*DD;
    #pragma unroll
    for (int e = tid; e < 64*64; e += 256) {
        qs[e>>6][e&63] = Qb[e];
        ks[e>>6][e&63] = Kb[e];
    }
    __syncthreads();
    int ty = tid >> 4, tx = tid & 15;
    float c[4][4];
    #pragma unroll
    for (int i=0;i<4;i++) { c[i][0]=0;c[i][1]=0;c[i][2]=0;c[i][3]=0; }
    #pragma unroll 4
    for (int d = 0; d < 64; d++) {
        float rq[4], rk[4];
        #pragma unroll
        for (int i=0;i<4;i++) { rq[i] = qs[ty*4+i][d]; rk[i] = ks[tx*4+i][d]; }
        #pragma unroll
        for (int i=0;i<4;i++)
            #pragma unroll
            for (int j=0;j<4;j++) c[i][j] += rq[i]*rk[j];
    }
    float inv_t = 1.f / fmaxf(temperature[0], 0.1f);
    const float scale = 0.125f;
    float* Ab = g_A + (size_t)b*SS*SS;
    #pragma unroll
    for (int i = 0; i < 4; i++) {
        int s = s0 + ty*4 + i;
        int4 idx = *(const int4*)(rel_idx + (size_t)s*SS + t0 + tx*4);
        float4 out;
        out.x = (c[i][0]*scale + __ldg(&bias_table[idx.x])) * inv_t;
        out.y = (c[i][1]*scale + __ldg(&bias_table[idx.y])) * inv_t;
        out.z = (c[i][2]*scale + __ldg(&bias_table[idx.z])) * inv_t;
        out.w = (c[i][3]*scale + __ldg(&bias_table[idx.w])) * inv_t;
        *(float4*)(Ab + (size_t)s*SS + t0 + tx*4) = out;
    }
}

// ---------------- 5) row softmax in place on g_A (+ bf16 copy) ----------------
__global__ __launch_bounds__(256) void softmax_kernel()
{
    size_t row = blockIdx.x;
    float* Ar = g_A + row*SS;
    __nv_bfloat16* Ah = g_Ah + row*SS;
    int tid = threadIdx.x;
    int wid = tid >> 5, lane = tid & 31;
    __shared__ float sm[8];
    float4 v = ((float4*)Ar)[tid];
    float m = fmaxf(fmaxf(v.x, v.y), fmaxf(v.z, v.w));
    m = warp_max(m);
    if (lane == 0) sm[wid] = m;
    __syncthreads();
    if (wid == 0) {
        float t = (lane < 8) ? sm[lane] : -3.4e38f;
        t = warp_max(t);
        if (lane == 0) sm[0] = t;
    }
    __syncthreads();
    m = sm[0];
    __syncthreads();
    float e0 = __expf(v.x-m), e1 = __expf(v.y-m), e2 = __expf(v.z-m), e3 = __expf(v.w-m);
    float s = e0+e1+e2+e3;
    s = warp_sum(s);
    if (lane == 0) sm[wid] = s;
    __syncthreads();
    if (wid == 0) {
        float t = (lane < 8) ? sm[lane] : 0.f;
        t = warp_sum(t);
        if (lane == 0) sm[0] = t;
    }
    __syncthreads();
    float inv = 1.f / sm[0];
    float4 o = make_float4(e0*inv, e1*inv, e2*inv, e3*inv);
    ((float4*)Ar)[tid] = o;
    __nv_bfloat162 h0 = __floats2bfloat162_rn(o.x, o.y);
    __nv_bfloat162 h1 = __floats2bfloat162_rn(o.z, o.w);
    ((__nv_bfloat162*)Ah)[tid*2]   = h0;
    ((__nv_bfloat162*)Ah)[tid*2+1] = h1;
    if (tid == 0) g_rs[row] = 1.0f;
}

// ---------------- 5b) transpose: g_Th = bf16(A^T) per batch ----------------
__global__ __launch_bounds__(256) void transpose_kernel()
{
    __shared__ float t[32][33];
    int b = blockIdx.z;
    int x0 = blockIdx.x*32, y0 = blockIdx.y*32;
    const float* Ab = g_A + (size_t)b*SS*SS;
    __nv_bfloat16* Tb = g_Th + (size_t)b*SS*SS;
    int tx = threadIdx.x & 31, ty = threadIdx.x >> 5;   // 32 x 8
    #pragma unroll
    for (int i = 0; i < 32; i += 8)
        t[ty+i][tx] = Ab[(size_t)(y0+ty+i)*SS + x0+tx];
    __syncthreads();
    #pragma unroll
    for (int i = 0; i < 32; i += 8)
        Tb[(size_t)(x0+ty+i)*SS + y0+tx] = __float2bfloat16(t[tx][ty+i]);
}

// ================= bf16 mma.sync batched NT GEMM =================
__device__ __forceinline__ uint32_t s2u(const void* p) {
    uint32_t a;
    asm("{ .reg .u64 t; cvta.to.shared.u64 t, %1; cvt.u32.u64 %0, t; }" : "=r"(a) : "l"(p));
    return a;
}
#define SWZ(o) ((o) ^ (((o)>>3)&0x70))

__device__ __forceinline__ void cp16(uint32_t dst, const void* src) {
    asm volatile("cp.async.cg.shared.global [%0], [%1], 16;" :: "r"(dst), "l"(src));
}
__device__ __forceinline__ void cp_commit() { asm volatile("cp.async.commit_group;" ::: "memory"); }
#define CP_WAIT(n) asm volatile("cp.async.wait_group %0;" :: "n"(n) : "memory")

__device__ __forceinline__ void ldsm4(uint32_t* r, uint32_t addr) {
    asm volatile("ldmatrix.sync.aligned.m8n8.x4.shared.b16 {%0,%1,%2,%3}, [%4];"
        : "=r"(r[0]), "=r"(r[1]), "=r"(r[2]), "=r"(r[3]) : "r"(addr));
}
__device__ __forceinline__ void mma_bf16(float* c, const uint32_t* a,
                                         uint32_t b0, uint32_t b1) {
    asm volatile(
        "mma.sync.aligned.m16n8k16.row.col.f32.bf16.bf16.f32 "
        "{%0,%1,%2,%3},{%4,%5,%6,%7},{%8,%9},{%0,%1,%2,%3};"
        : "+f"(c[0]), "+f"(c[1]), "+f"(c[2]), "+f"(c[3])
        : "r"(a[0]), "r"(a[1]), "r"(a[2]), "r"(a[3]), "r"(b0), "r"(b1));
}

#define STG 3
#define CK 64                        // k per chunk (bf16): 128B per row
#define NCH (SS/CK)                  // 16
#define STAGE_BYTES 32768
#define GEMM_DSMEM (STG*STAGE_BYTES) // 98304

__global__ __launch_bounds__(256, 2)
void gemm_bf16_kernel(int asel, int bsel, int cfsel, int chsel, int tri)
{
    extern __shared__ __align__(16) char dsmem[];
    uint32_t sb = s2u(dsmem);
    int tid = threadIdx.x;
    int warp = tid >> 5, lane = tid & 31;

    size_t off = (size_t)blockIdx.z*SS*SS;
    const __nv_bfloat16* Ag = hmatsel(asel) + off;
    const __nv_bfloat16* Bg = hmatsel(bsel) + off;
    float* Cg = matsel(cfsel) + off;
    __nv_bfloat16* Chg = (chsel >= 0) ? hmatsel(chsel) + off : nullptr;

    int bi, bj;
    if (tri) {
        int t = blockIdx.x, i = 0;
        while (t >= 8 - i) { t -= 8 - i; i++; }
        bi = i; bj = i + t;
    } else {
        bi = blockIdx.x >> 3; bj = blockIdx.x & 7;
    }
    int m0 = bi*128, n0 = bj*128;
    bool same = (tri != 0) && (bi == bj) && (asel == bsel);
    uint32_t bBase = same ? 0u : 16384u;

    int wm = (warp >> 2)*64, wn = (warp & 3)*32;
    int rlane = (lane & 7) + ((lane >> 3) & 1)*8;
    int clane = (lane >> 4) & 1;

    float acc[4][4][4];
    #pragma unroll
    for (int i = 0; i < 4; i++)
        #pragma unroll
        for (int j = 0; j < 4; j++) {
            acc[i][j][0]=0; acc[i][j][1]=0; acc[i][j][2]=0; acc[i][j][3]=0;
        }

    auto load_chunk = [&](int c) {
        uint32_t stg = sb + (uint32_t)(c % STG) * STAGE_BYTES;
        int k0 = c * CK;
        #pragma unroll
        for (int it = 0; it < 8; it++) {
            int u = tid + it*256;
            int r = u >> 3;
            int ch = u & 7;
            if (r < 128) {
                const __nv_bfloat16* gsrc = Ag + (size_t)(m0 + r)*SS + k0 + ch*8;
                cp16(stg + SWZ((uint32_t)(r*128 + ch*16)), gsrc);
            } else if (!same) {
                const __nv_bfloat16* gsrc = Bg + (size_t)(n0 + (r-128))*SS + k0 + ch*8;
                cp16(stg + 16384u + SWZ((uint32_t)((r-128)*128 + ch*16)), gsrc);
            }
        }
    };

    for (int c = 0; c < STG-1; c++) { load_chunk(c); cp_commit(); }

    for (int c = 0; c < NCH; c++) {
        int lc = c + STG - 1;
        if (lc < NCH) load_chunk(lc);
        cp_commit();
        CP_WAIT(STG-1);
        __syncthreads();
        uint32_t stg = sb + (uint32_t)(c % STG) * STAGE_BYTES;
        #pragma unroll
        for (int ks = 0; ks < CK/16; ks++) {
            uint32_t af[4][4], bfr[2][4];
            int kch = ks*2 + clane;
            #pragma unroll
            for (int mi = 0; mi < 4; mi++) {
                int r = wm + mi*16 + rlane;
                ldsm4(af[mi], stg + SWZ((uint32_t)(r*128 + kch*16)));
            }
            #pragma unroll
            for (int nt = 0; nt < 2; nt++) {
                int r = wn + nt*16 + rlane;
                ldsm4(bfr[nt], stg + bBase + SWZ((uint32_t)(r*128 + kch*16)));
            }
            #pragma unroll
            for (int mi = 0; mi < 4; mi++)
                #pragma unroll
                for (int nj = 0; nj < 4; nj++) {
                    int nt = nj >> 1, sel = nj & 1;
                    mma_bf16(acc[mi][nj], af[mi], bfr[nt][sel], bfr[nt][sel+2]);
                }
        }
        __syncthreads();
    }

    int rr = lane >> 2, cc2 = (lane & 3)*2;
    #pragma unroll
    for (int mi = 0; mi < 4; mi++) {
        #pragma unroll
        for (int nj = 0; nj < 4; nj++) {
            int row = m0 + wm + mi*16 + rr;
            int col = n0 + wn + nj*8 + cc2;
            float2 v01 = make_float2(acc[mi][nj][0], acc[mi][nj][1]);
            float2 v23 = make_float2(acc[mi][nj][2], acc[mi][nj][3]);
            *(float2*)&Cg[(size_t)row*SS + col]     = v01;
            *(float2*)&Cg[(size_t)(row+8)*SS + col] = v23;
            if (Chg) {
                *(__nv_bfloat162*)&Chg[(size_t)row*SS + col] =
                    __floats2bfloat162_rn(v01.x, v01.y);
                *(__nv_bfloat162*)&Chg[(size_t)(row+8)*SS + col] =
                    __floats2bfloat162_rn(v23.x, v23.y);
            }
        }
    }
}

// ---------------- 6b) mirror lower triangle of symmetric matrix ----------------
__global__ __launch_bounds__(256) void mirror_kernel(int msel, int hsel)
{
    __shared__ float t[32][33];
    size_t off = (size_t)blockIdx.z*SS*SS;
    float* M = matsel(msel) + off;
    __nv_bfloat16* Mh = (hsel >= 0) ? hmatsel(hsel) + off : nullptr;

    int p = blockIdx.x, i = 0;
    while (p >= 7 - i) { p -= 7 - i; i++; }
    int j = i + 1 + p;
    int sub = blockIdx.y;
    int y0 = i*128 + (sub >> 2)*32;
    int x0 = j*128 + (sub & 3)*32;
    int tx = threadIdx.x & 31, ty = threadIdx.x >> 5;
    #pragma unroll
    for (int k = 0; k < 32; k += 8)
        t[ty+k][tx] = M[(size_t)(y0+ty+k)*SS + x0+tx];
    __syncthreads();
    #pragma unroll
    for (int k = 0; k < 32; k += 8) {
        float v = t[tx][ty+k];
        size_t dst = (size_t)(x0+ty+k)*SS + y0+tx;
        M[dst] = v;
        if (Mh) Mh[dst] = __float2bfloat16(v);
    }
}

// ---------------- 7) rowsums of P,Qm,A2,P2,Q2 ----------------
__global__ __launch_bounds__(256) void rowsum_kernel()
{
    int m = blockIdx.y;
    const float* Mp = matsel(m + 1);
    size_t row = blockIdx.x;
    int tid = threadIdx.x;
    int wid = tid >> 5, lane = tid & 31;
    __shared__ float sm[8];
    float4 v = ((const float4*)(Mp + row*SS))[tid];
    float s = v.x + v.y + v.z + v.w;
    s = warp_sum(s);
    if (lane == 0) sm[wid] = s;
    __syncthreads();
    if (tid == 0) {
        float t = 0.f;
        #pragma unroll
        for (int i = 0; i < 8; i++) t += sm[i];
        g_rs[(size_t)(m+1)*NTOK + row] = t;
    }
}

// ---------------- 8) fused epilogue (both hops, fast-math) ----------------
__global__ __launch_bounds__(256) void fused_kernel(
    const float* __restrict__ fusion_w, const float* __restrict__ fusion_b)
{
    __shared__ float fs[16][65];
    __shared__ float vs[64][65];
    __shared__ float rsf[16];
    __shared__ float irs_s[16], irs_c[16], irs_p[16];

    int hop = blockIdx.z;
    int b = blockIdx.y;
    int sr0 = blockIdx.x * 16;
    int tid = threadIdx.x;
    const float *Ms, *Mc, *Mp;
    int rbase;
    if (hop == 0) { Ms = g_A;  Mc = g_P;  Mp = g_Qm; rbase = 0; }
    else          { Ms = g_A2; Mc = g_P2; Mp = g_Q2; rbase = 3; }
    float w0 = fusion_w[hop*3 + 0];
    float w1 = fusion_w[hop*3 + 1];
    float w2 = fusion_w[hop*3 + 2];
    float fb = fusion_b[hop];
    size_t rowbase = (size_t)b*SS + sr0;

    if (tid < 16) {
        irs_s[tid] = 1.f / (g_rs[(size_t)(rbase+0)*NTOK + rowbase + tid] + EPSV);
        irs_c[tid] = 1.f / (g_rs[(size_t)(rbase+1)*NTOK + rowbase + tid] + EPSV);
        irs_p[tid] = 1.f / (g_rs[(size_t)(rbase+2)*NTOK + rowbase + tid] + EPSV);
    }
    __syncthreads();

    int r2 = tid >> 5;
    int e2 = tid & 31;
    float acc00 = 0, acc01 = 0, acc10 = 0, acc11 = 0;
    float rsum0 = 0, rsum1 = 0;
    const float* hv_base = g_hopv + (size_t)hop*NTOK*DD + (size_t)b*SS*DD;

    for (int tc = 0; tc < 16; tc++) {
        int t0 = tc * 64;
        const float* hv = hv_base + (size_t)t0*DD;
        #pragma unroll
        for (int e = tid; e < 64*64; e += 256) vs[e>>6][e&63] = hv[e];
        #pragma unroll
        for (int e = tid; e < 16*64; e += 256) {
            int r = e >> 6, t = e & 63;
            size_t off = (rowbase + r)*SS + t0 + t;
            float ps = fminf(fmaxf(Ms[off]*irs_s[r], EPSV), 1.f-EPSV);
            float pc = fminf(fmaxf(Mc[off]*irs_c[r], EPSV), 1.f-EPSV);
            float pp = fminf(fmaxf(Mp[off]*irs_p[r], EPSV), 1.f-EPSV);
            float L0 = __logf(__fdividef(ps, 1.f-ps+EPSV));
            float L1 = __logf(__fdividef(pc, 1.f-pc+EPSV));
            float L2 = __logf(__fdividef(pp, 1.f-pp+EPSV));
            float logit = fb + w0*L0 + w1*L1 + w2*L2;
            fs[r][t] = __fdividef(1.f, 1.f+__expf(-logit));
        }
        __syncthreads();
        #pragma unroll 8
        for (int t = 0; t < 64; t++) {
            float f0 = fs[2*r2][t],   f1 = fs[2*r2+1][t];
            float v0 = vs[t][2*e2],   v1 = vs[t][2*e2+1];
            acc00 += f0*v0; acc01 += f0*v1;
            acc10 += f1*v0; acc11 += f1*v1;
            if (e2 == 0) { rsum0 += f0; rsum1 += f1; }
        }
        __syncthreads();
    }
    if (e2 == 0) { rsf[2*r2] = rsum0; rsf[2*r2+1] = rsum1; }
    __syncthreads();
    float gt0 = g_gate[(rowbase + 2*r2)*2 + hop];
    float gt1 = g_gate[(rowbase + 2*r2 + 1)*2 + hop];
    float sc0 = gt0 / (rsf[2*r2] + EPSV);
    float sc1 = gt1 / (rsf[2*r2+1] + EPSV);
    float* C0 = g_comb + (rowbase + 2*r2)*DD + 2*e2;
    float* C1 = g_comb + (rowbase + 2*r2 + 1)*DD + 2*e2;
    // both hops write concurrently -> atomic accumulate (g_comb pre-zeroed)
    atomicAdd(&C0[0], acc00*sc0); atomicAdd(&C0[1], acc01*sc0);
    atomicAdd(&C1[0], acc10*sc1); atomicAdd(&C1[1], acc11*sc1);
}

__global__ void zero_comb_kernel()
{
    int gid = blockIdx.x*256 + threadIdx.x;
    ((float4*)g_comb)[gid] = make_float4(0.f, 0.f, 0.f, 0.f);
}

// ---------------- 9) out = combined @ out_W^T ----------------
__global__ __launch_bounds__(256) void outproj_kernel(
    const float* __restrict__ outW, float* __restrict__ out)
{
    __shared__ float cs[16][65];
    __shared__ float ws[128][65];
    int tb = blockIdx.x * 16;
    int tid = threadIdx.x;
    #pragma unroll
    for (int e = tid; e < 16*64; e += 256) cs[e>>6][e&63] = g_comb[(size_t)tb*DD + e];
    int tk2 = tid >> 5;
    int h4  = tid & 31;
    for (int hc = 0; hc < 4; hc++) {
        __syncthreads();
        #pragma unroll
        for (int e = tid; e < 128*64; e += 256)
            ws[e>>6][e&63] = outW[(size_t)hc*128*DD + e];
        __syncthreads();
        float a0[4] = {0,0,0,0}, a1[4] = {0,0,0,0};
        #pragma unroll 4
        for (int d = 0; d < 64; d++) {
            float c0 = cs[2*tk2][d], c1 = cs[2*tk2+1][d];
            #pragma unroll
            for (int j = 0; j < 4; j++) {
                float w = ws[h4*4 + j][d];
                a0[j] += c0*w; a1[j] += c1*w;
            }
        }
        *(float4*)&out[(size_t)(tb + 2*tk2)*HID + hc*128 + h4*4] =
            make_float4(a0[0], a0[1], a0[2], a0[3]);
        *(float4*)&out[(size_t)(tb + 2*tk2 + 1)*HID + hc*128 + h4*4] =
            make_float4(a1[0], a1[1], a1[2], a1[3]);
    }
}

// ---------------- launch ----------------
extern "C" void kernel_launch(void* const* d_in, const int* in_sizes, int n_in,
                              void* d_out, int out_size)
{
    const float* x      = (const float*)d_in[0];
    const float* Wq     = (const float*)d_in[1];
    const float* Wk     = (const float*)d_in[2];
    const float* Wv     = (const float*)d_in[3];
    const float* btab   = (const float*)d_in[4];
    const float* fw     = (const float*)d_in[5];
    const float* fbias  = (const float*)d_in[6];
    const float* hopW   = (const float*)d_in[7];
    const float* gateW  = (const float*)d_in[8];
    const float* gateb  = (const float*)d_in[9];
    const float* outW   = (const float*)d_in[10];
    const float* temp   = (const float*)d_in[11];
    const int*   relidx = (const int*)d_in[12];
    float* out = (float*)d_out;

    cudaFuncSetAttribute(gemm_bf16_kernel,
                         cudaFuncAttributeMaxDynamicSharedMemorySize, GEMM_DSMEM);

    proj_kernel<<<NTOK/TOK_PB, 256>>>(x, Wq, Wk, Wv, gateW);
    rope_kernel<<<(NTOK*32)/256, 256>>>();
    hopv_gate_kernel<<<(NTOK*DD)/256, 256>>>(hopW, gateb);
    scores_kernel<<<dim3(16,16,NB), 256>>>(btab, relidx, temp);
    softmax_kernel<<<NTOK, 256>>>();
    transpose_kernel<<<dim3(32,32,NB), 256>>>();

    // hmat: 0=Ah 1=Th 2=Ph 3=Qmh ; mat: 1=P 2=Qm 3=A2 4=P2 5=Q2
    gemm_bf16_kernel<<<dim3(36,1,NB), 256, GEMM_DSMEM>>>(0,0,1, 2, 1); // P  = Ah Ah^T (tri)
    gemm_bf16_kernel<<<dim3(36,1,NB), 256, GEMM_DSMEM>>>(1,1,2, 3, 1); // Qm = Th Th^T (tri)
    gemm_bf16_kernel<<<dim3(64,1,NB), 256, GEMM_DSMEM>>>(0,1,3,-1, 0); // A2 = Ah Th^T (full)
    mirror_kernel<<<dim3(28,16,NB), 256>>>(1, 2);  // P  (+Ph)
    mirror_kernel<<<dim3(28,16,NB), 256>>>(2, 3);  // Qm (+Qmh)
    gemm_bf16_kernel<<<dim3(36,1,NB), 256, GEMM_DSMEM>>>(2,2,4,-1, 1); // P2 = Ph Ph^T (tri)
    gemm_bf16_kernel<<<dim3(36,1,NB), 256, GEMM_DSMEM>>>(3,3,5,-1, 1); // Q2 = Qmh Qmh^T (tri)
    mirror_kernel<<<dim3(28,16,NB), 256>>>(4, -1); // P2
    mirror_kernel<<<dim3(28,16,NB), 256>>>(5, -1); // Q2

    rowsum_kernel<<<dim3(NTOK, 5), 256>>>();
    zero_comb_kernel<<<NTOK*DD/4/256, 256>>>();
    fused_kernel<<<dim3(SS/16, NB, 2), 256>>>(fw, fbias);
    outproj_kernel<<<NTOK/16, 256>>>(outW, out);
}

// round 8
// speedup vs baseline: 1.5740x; 1.0011x over previous
#include <cuda_runtime.h>
#include <cuda_bf16.h>
#include <cstdint>

#define NB 8
#define SS 1024
#define DD 64
#define HID 512
#define NTOK (NB*SS)          // 8192
#define EPSV 1e-6f

// ---------------- device scratch (no allocation allowed) ----------------
__device__ float g_Q[NTOK*DD];
__device__ float g_K[NTOK*DD];
__device__ float g_V[NTOK*DD];
__device__ float g_hopv[2*NTOK*DD];
__device__ float g_gate[NTOK*2];
__device__ float g_comb[NTOK*DD];
__device__ float g_rs[6*NTOK];           // rowsums: 0=A 1=P 2=Qm 3=A2 4=P2 5=Q2
__device__ float g_A [(size_t)NB*SS*SS]; // softmax attention
__device__ float g_P [(size_t)NB*SS*SS]; // A A^T
__device__ float g_Qm[(size_t)NB*SS*SS]; // A^T A
__device__ float g_A2[(size_t)NB*SS*SS]; // A A
__device__ float g_P2[(size_t)NB*SS*SS]; // P P
__device__ float g_Q2[(size_t)NB*SS*SS]; // Qm Qm
// bf16 GEMM operands
__device__ __nv_bfloat16 g_Ah [(size_t)NB*SS*SS];
__device__ __nv_bfloat16 g_Th [(size_t)NB*SS*SS];
__device__ __nv_bfloat16 g_Ph [(size_t)NB*SS*SS];
__device__ __nv_bfloat16 g_Qmh[(size_t)NB*SS*SS];

__device__ __forceinline__ float* matsel(int s) {
    switch (s) {
        case 0: return g_A;
        case 1: return g_P;
        case 2: return g_Qm;
        case 3: return g_A2;
        case 4: return g_P2;
        default: return g_Q2;
    }
}
__device__ __forceinline__ __nv_bfloat16* hmatsel(int s) {
    switch (s) {
        case 0: return g_Ah;
        case 1: return g_Th;
        case 2: return g_Ph;
        default: return g_Qmh;
    }
}

__device__ __forceinline__ float warp_max(float v) {
    #pragma unroll
    for (int o = 16; o > 0; o >>= 1) v = fmaxf(v, __shfl_xor_sync(0xffffffffu, v, o));
    return v;
}
__device__ __forceinline__ float warp_sum(float v) {
    #pragma unroll
    for (int o = 16; o > 0; o >>= 1) v += __shfl_xor_sync(0xffffffffu, v, o);
    return v;
}

// ---------------- 1) QKV + gate-logit projection ----------------
#define TOK_PB 16
__global__ __launch_bounds__(256) void proj_kernel(
    const float* __restrict__ x, const float* __restrict__ Wq,
    const float* __restrict__ Wk, const float* __restrict__ Wv,
    const float* __restrict__ gW)
{
    __shared__ float xs[TOK_PB*HID];
    int tb = blockIdx.x * TOK_PB;
    int tid = threadIdx.x;
    const float4* xg = (const float4*)(x + (size_t)tb*HID);
    float4* xs4 = (float4*)xs;
    #pragma unroll
    for (int i = tid; i < TOK_PB*HID/4; i += 256) xs4[i] = xg[i];
    __syncthreads();

    for (int o = tid; o < TOK_PB*194; o += 256) {
        int tok = o / 194, ch = o % 194;
        const float* w;
        if (ch < 64)       w = Wq + ch*HID;
        else if (ch < 128) w = Wk + (ch-64)*HID;
        else if (ch < 192) w = Wv + (ch-128)*HID;
        else               w = gW + (ch-192)*HID;
        const float4* w4  = (const float4*)w;
        const float4* xv4 = (const float4*)(xs + tok*HID);
        float acc = 0.f;
        #pragma unroll 8
        for (int k = 0; k < HID/4; k++) {
            float4 a = xv4[k];
            float4 b = __ldg(&w4[k]);
            acc += a.x*b.x + a.y*b.y + a.z*b.z + a.w*b.w;
        }
        size_t gt = tb + tok;
        if (ch < 64)       g_Q[gt*DD + ch]        = acc;
        else if (ch < 128) g_K[gt*DD + (ch-64)]   = acc;
        else if (ch < 192) g_V[gt*DD + (ch-128)]  = acc;
        else               g_gate[gt*2 + (ch-192)] = acc;
    }
}

// ---------------- 2) RoPE in place on Q,K ----------------
__global__ void rope_kernel()
{
    int gid = blockIdx.x*256 + threadIdx.x;
    if (gid >= NTOK*32) return;
    int tok = gid >> 5, j = gid & 31;
    int s = tok & (SS-1);
    float invf = (float)exp(-log(10000.0) * (double)j / 32.0);
    float ang = (float)s * invf;
    float sn, cs;
    sincosf(ang, &sn, &cs);
    size_t base = (size_t)tok * DD;
    float q0 = g_Q[base+j], q1 = g_Q[base+j+32];
    g_Q[base+j]    = q0*cs - q1*sn;
    g_Q[base+j+32] = q1*cs + q0*sn;
    float k0 = g_K[base+j], k1 = g_K[base+j+32];
    g_K[base+j]    = k0*cs - k1*sn;
    g_K[base+j+32] = k1*cs + k0*sn;
}

// ---------------- 3) hop_v = V @ hop_W[h]^T ; gate softmax ----------------
__global__ void hopv_gate_kernel(const float* __restrict__ hopW,
                                 const float* __restrict__ gateb)
{
    int gid = blockIdx.x*256 + threadIdx.x;
    if (gid >= NTOK*DD) return;
    int tok = gid >> 6, e = gid & 63;
    const float* vrow = g_V + (size_t)tok*DD;
    float a0 = 0.f, a1 = 0.f;
    #pragma unroll
    for (int d = 0; d < DD; d++) {
        float v = vrow[d];
        a0 += v * __ldg(&hopW[e*DD + d]);
        a1 += v * __ldg(&hopW[DD*DD + e*DD + d]);
    }
    g_hopv[(size_t)tok*DD + e]              = a0;
    g_hopv[(size_t)NTOK*DD + (size_t)tok*DD + e] = a1;
    if (e == 0) {
        float l0 = g_gate[tok*2]   + gateb[0];
        float l1 = g_gate[tok*2+1] + gateb[1];
        float m = fmaxf(l0, l1);
        float e0 = __expf(l0-m), e1 = __expf(l1-m);
        float inv = 1.f/(e0+e1);
        g_gate[tok*2]   = e0*inv;
        g_gate[tok*2+1] = e1*inv;
    }
}

// ---------------- 4) scores ----------------
__global__ __launch_bounds__(256) void scores_kernel(
    const float* __restrict__ bias_table, const int* __restrict__ rel_idx,
    const float* __restrict__ temperature)
{
    __shared__ float qs[64][65];
    __shared__ float ks[64][65];
    int b = blockIdx.z;
    int s0 = blockIdx.y * 64, t0 = blockIdx.x * 64;
    int tid = threadIdx.x;
    const float* Qb = g_Q + ((size_t)b*SS + s0)*DD;
    const float* Kb = g_K + ((size_t)b*SS + t0)*DD;
    #pragma unroll
    for (int e = tid; e < 64*64; e += 256) {
        qs[e>>6][e&63] = Qb[e];
        ks[e>>6][e&63] = Kb[e];
    }
    __syncthreads();
    int ty = tid >> 4, tx = tid & 15;
    float c[4][4];
    #pragma unroll
    for (int i=0;i<4;i++) { c[i][0]=0;c[i][1]=0;c[i][2]=0;c[i][3]=0; }
    #pragma unroll 4
    for (int d = 0; d < 64; d++) {
        float rq[4], rk[4];
        #pragma unroll
        for (int i=0;i<4;i++) { rq[i] = qs[ty*4+i][d]; rk[i] = ks[tx*4+i][d]; }
        #pragma unroll
        for (int i=0;i<4;i++)
            #pragma unroll
            for (int j=0;j<4;j++) c[i][j] += rq[i]*rk[j];
    }
    float inv_t = 1.f / fmaxf(temperature[0], 0.1f);
    const float scale = 0.125f;
    float* Ab = g_A + (size_t)b*SS*SS;
    #pragma unroll
    for (int i = 0; i < 4; i++) {
        int s = s0 + ty*4 + i;
        int4 idx = *(const int4*)(rel_idx + (size_t)s*SS + t0 + tx*4);
        float4 out;
        out.x = (c[i][0]*scale + __ldg(&bias_table[idx.x])) * inv_t;
        out.y = (c[i][1]*scale + __ldg(&bias_table[idx.y])) * inv_t;
        out.z = (c[i][2]*scale + __ldg(&bias_table[idx.z])) * inv_t;
        out.w = (c[i][3]*scale + __ldg(&bias_table[idx.w])) * inv_t;
        *(float4*)(Ab + (size_t)s*SS + t0 + tx*4) = out;
    }
}

// ---------------- 5) row softmax in place on g_A (+ bf16 copy) ----------------
__global__ __launch_bounds__(256) void softmax_kernel()
{
    size_t row = blockIdx.x;
    float* Ar = g_A + row*SS;
    __nv_bfloat16* Ah = g_Ah + row*SS;
    int tid = threadIdx.x;
    int wid = tid >> 5, lane = tid & 31;
    __shared__ float sm[8];
    float4 v = ((float4*)Ar)[tid];
    float m = fmaxf(fmaxf(v.x, v.y), fmaxf(v.z, v.w));
    m = warp_max(m);
    if (lane == 0) sm[wid] = m;
    __syncthreads();
    if (wid == 0) {
        float t = (lane < 8) ? sm[lane] : -3.4e38f;
        t = warp_max(t);
        if (lane == 0) sm[0] = t;
    }
    __syncthreads();
    m = sm[0];
    __syncthreads();
    float e0 = __expf(v.x-m), e1 = __expf(v.y-m), e2 = __expf(v.z-m), e3 = __expf(v.w-m);
    float s = e0+e1+e2+e3;
    s = warp_sum(s);
    if (lane == 0) sm[wid] = s;
    __syncthreads();
    if (wid == 0) {
        float t = (lane < 8) ? sm[lane] : 0.f;
        t = warp_sum(t);
        if (lane == 0) sm[0] = t;
    }
    __syncthreads();
    float inv = 1.f / sm[0];
    float4 o = make_float4(e0*inv, e1*inv, e2*inv, e3*inv);
    ((float4*)Ar)[tid] = o;
    __nv_bfloat162 h0 = __floats2bfloat162_rn(o.x, o.y);
    __nv_bfloat162 h1 = __floats2bfloat162_rn(o.z, o.w);
    ((__nv_bfloat162*)Ah)[tid*2]   = h0;
    ((__nv_bfloat162*)Ah)[tid*2+1] = h1;
    if (tid == 0) g_rs[row] = 1.0f;
}

// ---------------- 5b) transpose: g_Th = bf16(A^T) per batch ----------------
__global__ __launch_bounds__(256) void transpose_kernel()
{
    __shared__ float t[32][33];
    int b = blockIdx.z;
    int x0 = blockIdx.x*32, y0 = blockIdx.y*32;
    const float* Ab = g_A + (size_t)b*SS*SS;
    __nv_bfloat16* Tb = g_Th + (size_t)b*SS*SS;
    int tx = threadIdx.x & 31, ty = threadIdx.x >> 5;   // 32 x 8
    #pragma unroll
    for (int i = 0; i < 32; i += 8)
        t[ty+i][tx] = Ab[(size_t)(y0+ty+i)*SS + x0+tx];
    __syncthreads();
    #pragma unroll
    for (int i = 0; i < 32; i += 8)
        Tb[(size_t)(x0+ty+i)*SS + y0+tx] = __float2bfloat16(t[tx][ty+i]);
}

// ================= bf16 mma.sync batched NT GEMM =================
__device__ __forceinline__ uint32_t s2u(const void* p) {
    uint32_t a;
    asm("{ .reg .u64 t; cvta.to.shared.u64 t, %1; cvt.u32.u64 %0, t; }" : "=r"(a) : "l"(p));
    return a;
}
#define SWZ(o) ((o) ^ (((o)>>3)&0x70))

__device__ __forceinline__ void cp16(uint32_t dst, const void* src) {
    asm volatile("cp.async.cg.shared.global [%0], [%1], 16;" :: "r"(dst), "l"(src));
}
__device__ __forceinline__ void cp_commit() { asm volatile("cp.async.commit_group;" ::: "memory"); }
#define CP_WAIT(n) asm volatile("cp.async.wait_group %0;" :: "n"(n) : "memory")

__device__ __forceinline__ void ldsm4(uint32_t* r, uint32_t addr) {
    asm volatile("ldmatrix.sync.aligned.m8n8.x4.shared.b16 {%0,%1,%2,%3}, [%4];"
        : "=r"(r[0]), "=r"(r[1]), "=r"(r[2]), "=r"(r[3]) : "r"(addr));
}
__device__ __forceinline__ void mma_bf16(float* c, const uint32_t* a,
                                         uint32_t b0, uint32_t b1) {
    asm volatile(
        "mma.sync.aligned.m16n8k16.row.col.f32.bf16.bf16.f32 "
        "{%0,%1,%2,%3},{%4,%5,%6,%7},{%8,%9},{%0,%1,%2,%3};"
        : "+f"(c[0]), "+f"(c[1]), "+f"(c[2]), "+f"(c[3])
        : "r"(a[0]), "r"(a[1]), "r"(a[2]), "r"(a[3]), "r"(b0), "r"(b1));
}

#define STG 3
#define CK 64                        // k per chunk (bf16): 128B per row
#define NCH (SS/CK)                  // 16
#define STAGE_BYTES 32768
#define GEMM_DSMEM (STG*STAGE_BYTES) // 98304

__global__ __launch_bounds__(256, 2)
void gemm_bf16_kernel(int asel, int bsel, int cfsel, int chsel, int tri)
{
    extern __shared__ __align__(16) char dsmem[];
    uint32_t sb = s2u(dsmem);
    int tid = threadIdx.x;
    int warp = tid >> 5, lane = tid & 31;

    size_t off = (size_t)blockIdx.z*SS*SS;
    const __nv_bfloat16* Ag = hmatsel(asel) + off;
    const __nv_bfloat16* Bg = hmatsel(bsel) + off;
    float* Cg = matsel(cfsel) + off;
    __nv_bfloat16* Chg = (chsel >= 0) ? hmatsel(chsel) + off : nullptr;

    int bi, bj;
    if (tri) {
        int t = blockIdx.x, i = 0;
        while (t >= 8 - i) { t -= 8 - i; i++; }
        bi = i; bj = i + t;
    } else {
        bi = blockIdx.x >> 3; bj = blockIdx.x & 7;
    }
    int m0 = bi*128, n0 = bj*128;
    bool same = (tri != 0) && (bi == bj) && (asel == bsel);
    uint32_t bBase = same ? 0u : 16384u;

    int wm = (warp >> 2)*64, wn = (warp & 3)*32;
    int rlane = (lane & 7) + ((lane >> 3) & 1)*8;
    int clane = (lane >> 4) & 1;

    float acc[4][4][4];
    #pragma unroll
    for (int i = 0; i < 4; i++)
        #pragma unroll
        for (int j = 0; j < 4; j++) {
            acc[i][j][0]=0; acc[i][j][1]=0; acc[i][j][2]=0; acc[i][j][3]=0;
        }

    auto load_chunk = [&](int c) {
        uint32_t stg = sb + (uint32_t)(c % STG) * STAGE_BYTES;
        int k0 = c * CK;
        #pragma unroll
        for (int it = 0; it < 8; it++) {
            int u = tid + it*256;
            int r = u >> 3;
            int ch = u & 7;
            if (r < 128) {
                const __nv_bfloat16* gsrc = Ag + (size_t)(m0 + r)*SS + k0 + ch*8;
                cp16(stg + SWZ((uint32_t)(r*128 + ch*16)), gsrc);
            } else if (!same) {
                const __nv_bfloat16* gsrc = Bg + (size_t)(n0 + (r-128))*SS + k0 + ch*8;
                cp16(stg + 16384u + SWZ((uint32_t)((r-128)*128 + ch*16)), gsrc);
            }
        }
    };

    for (int c = 0; c < STG-1; c++) { load_chunk(c); cp_commit(); }

    for (int c = 0; c < NCH; c++) {
        int lc = c + STG - 1;
        if (lc < NCH) load_chunk(lc);
        cp_commit();
        CP_WAIT(STG-1);
        __syncthreads();
        uint32_t stg = sb + (uint32_t)(c % STG) * STAGE_BYTES;
        #pragma unroll
        for (int ks = 0; ks < CK/16; ks++) {
            uint32_t af[4][4], bfr[2][4];
            int kch = ks*2 + clane;
            #pragma unroll
            for (int mi = 0; mi < 4; mi++) {
                int r = wm + mi*16 + rlane;
                ldsm4(af[mi], stg + SWZ((uint32_t)(r*128 + kch*16)));
            }
            #pragma unroll
            for (int nt = 0; nt < 2; nt++) {
                int r = wn + nt*16 + rlane;
                ldsm4(bfr[nt], stg + bBase + SWZ((uint32_t)(r*128 + kch*16)));
            }
            #pragma unroll
            for (int mi = 0; mi < 4; mi++)
                #pragma unroll
                for (int nj = 0; nj < 4; nj++) {
                    int nt = nj >> 1, sel = nj & 1;
                    mma_bf16(acc[mi][nj], af[mi], bfr[nt][sel], bfr[nt][sel+2]);
                }
        }
        __syncthreads();
    }

    int rr = lane >> 2, cc2 = (lane & 3)*2;
    #pragma unroll
    for (int mi = 0; mi < 4; mi++) {
        #pragma unroll
        for (int nj = 0; nj < 4; nj++) {
            int row = m0 + wm + mi*16 + rr;
            int col = n0 + wn + nj*8 + cc2;
            float2 v01 = make_float2(acc[mi][nj][0], acc[mi][nj][1]);
            float2 v23 = make_float2(acc[mi][nj][2], acc[mi][nj][3]);
            *(float2*)&Cg[(size_t)row*SS + col]     = v01;
            *(float2*)&Cg[(size_t)(row+8)*SS + col] = v23;
            if (Chg) {
                *(__nv_bfloat162*)&Chg[(size_t)row*SS + col] =
                    __floats2bfloat162_rn(v01.x, v01.y);
                *(__nv_bfloat162*)&Chg[(size_t)(row+8)*SS + col] =
                    __floats2bfloat162_rn(v23.x, v23.y);
            }
        }
    }
}

// ---------------- 6b) mirror lower triangle of symmetric matrix ----------------
__global__ __launch_bounds__(256) void mirror_kernel(int msel, int hsel)
{
    __shared__ float t[32][33];
    size_t off = (size_t)blockIdx.z*SS*SS;
    float* M = matsel(msel) + off;
    __nv_bfloat16* Mh = (hsel >= 0) ? hmatsel(hsel) + off : nullptr;

    int p = blockIdx.x, i = 0;
    while (p >= 7 - i) { p -= 7 - i; i++; }
    int j = i + 1 + p;
    int sub = blockIdx.y;
    int y0 = i*128 + (sub >> 2)*32;
    int x0 = j*128 + (sub & 3)*32;
    int tx = threadIdx.x & 31, ty = threadIdx.x >> 5;
    #pragma unroll
    for (int k = 0; k < 32; k += 8)
        t[ty+k][tx] = M[(size_t)(y0+ty+k)*SS + x0+tx];
    __syncthreads();
    #pragma unroll
    for (int k = 0; k < 32; k += 8) {
        float v = t[tx][ty+k];
        size_t dst = (size_t)(x0+ty+k)*SS + y0+tx;
        M[dst] = v;
        if (Mh) Mh[dst] = __float2bfloat16(v);
    }
}

// ---------------- 7) rowsums of P,Qm,A2,P2,Q2 ----------------
__global__ __launch_bounds__(256) void rowsum_kernel()
{
    int m = blockIdx.y;
    const float* Mp = matsel(m + 1);
    size_t row = blockIdx.x;
    int tid = threadIdx.x;
    int wid = tid >> 5, lane = tid & 31;
    __shared__ float sm[8];
    float4 v = ((const float4*)(Mp + row*SS))[tid];
    float s = v.x + v.y + v.z + v.w;
    s = warp_sum(s);
    if (lane == 0) sm[wid] = s;
    __syncthreads();
    if (tid == 0) {
        float t = 0.f;
        #pragma unroll
        for (int i = 0; i < 8; i++) t += sm[i];
        g_rs[(size_t)(m+1)*NTOK + row] = t;
    }
}

// ---------------- 8) fused epilogue (both hops, product-form sigmoid) ----------------
__global__ __launch_bounds__(256) void fused_kernel(
    const float* __restrict__ fusion_w, const float* __restrict__ fusion_b)
{
    __shared__ float fs[16][65];
    __shared__ float vs[64][65];
    __shared__ float rsf[16];
    __shared__ float irs_s[16], irs_c[16], irs_p[16];

    int hop = blockIdx.z;
    int b = blockIdx.y;
    int sr0 = blockIdx.x * 16;
    int tid = threadIdx.x;
    const float *Ms, *Mc, *Mp;
    int rbase;
    if (hop == 0) { Ms = g_A;  Mc = g_P;  Mp = g_Qm; rbase = 0; }
    else          { Ms = g_A2; Mc = g_P2; Mp = g_Q2; rbase = 3; }
    float w0 = fusion_w[hop*3 + 0];
    float w1 = fusion_w[hop*3 + 1];
    float w2 = fusion_w[hop*3 + 2];
    float fb = fusion_b[hop];
    // fast path: sigmoid(L0+L1+L2) = p0p1p2 / (p0p1p2 + q0q1q2), qi = 1-pi+eps
    bool unitw = (w0 == 1.f) && (w1 == 1.f) && (w2 == 1.f) && (fb == 0.f);
    size_t rowbase = (size_t)b*SS + sr0;

    if (tid < 16) {
        irs_s[tid] = 1.f / (g_rs[(size_t)(rbase+0)*NTOK + rowbase + tid] + EPSV);
        irs_c[tid] = 1.f / (g_rs[(size_t)(rbase+1)*NTOK + rowbase + tid] + EPSV);
        irs_p[tid] = 1.f / (g_rs[(size_t)(rbase+2)*NTOK + rowbase + tid] + EPSV);
    }
    __syncthreads();

    int r2 = tid >> 5;
    int e2 = tid & 31;
    float acc00 = 0, acc01 = 0, acc10 = 0, acc11 = 0;
    float rsum0 = 0, rsum1 = 0;
    const float* hv_base = g_hopv + (size_t)hop*NTOK*DD + (size_t)b*SS*DD;

    for (int tc = 0; tc < 16; tc++) {
        int t0 = tc * 64;
        const float* hv = hv_base + (size_t)t0*DD;
        #pragma unroll
        for (int e = tid; e < 64*64; e += 256) vs[e>>6][e&63] = hv[e];
        if (unitw) {
            #pragma unroll
            for (int e = tid; e < 16*64; e += 256) {
                int r = e >> 6, t = e & 63;
                size_t off = (rowbase + r)*SS + t0 + t;
                float ps = fminf(fmaxf(Ms[off]*irs_s[r], EPSV), 1.f-EPSV);
                float pc = fminf(fmaxf(Mc[off]*irs_c[r], EPSV), 1.f-EPSV);
                float pp = fminf(fmaxf(Mp[off]*irs_p[r], EPSV), 1.f-EPSV);
                float num = ps*pc*pp;
                float den = (1.f-ps+EPSV)*(1.f-pc+EPSV)*(1.f-pp+EPSV);
                fs[r][t] = __fdividef(num, num + den);
            }
        } else {
            #pragma unroll
            for (int e = tid; e < 16*64; e += 256) {
                int r = e >> 6, t = e & 63;
                size_t off = (rowbase + r)*SS + t0 + t;
                float ps = fminf(fmaxf(Ms[off]*irs_s[r], EPSV), 1.f-EPSV);
                float pc = fminf(fmaxf(Mc[off]*irs_c[r], EPSV), 1.f-EPSV);
                float pp = fminf(fmaxf(Mp[off]*irs_p[r], EPSV), 1.f-EPSV);
                float L0 = __logf(__fdividef(ps, 1.f-ps+EPSV));
                float L1 = __logf(__fdividef(pc, 1.f-pc+EPSV));
                float L2 = __logf(__fdividef(pp, 1.f-pp+EPSV));
                float logit = fb + w0*L0 + w1*L1 + w2*L2;
                fs[r][t] = __fdividef(1.f, 1.f+__expf(-logit));
            }
        }
        __syncthreads();
        #pragma unroll 8
        for (int t = 0; t < 64; t++) {
            float f0 = fs[2*r2][t],   f1 = fs[2*r2+1][t];
            float v0 = vs[t][2*e2],   v1 = vs[t][2*e2+1];
            acc00 += f0*v0; acc01 += f0*v1;
            acc10 += f1*v0; acc11 += f1*v1;
            if (e2 == 0) { rsum0 += f0; rsum1 += f1; }
        }
        __syncthreads();
    }
    if (e2 == 0) { rsf[2*r2] = rsum0; rsf[2*r2+1] = rsum1; }
    __syncthreads();
    float gt0 = g_gate[(rowbase + 2*r2)*2 + hop];
    float gt1 = g_gate[(rowbase + 2*r2 + 1)*2 + hop];
    float sc0 = gt0 / (rsf[2*r2] + EPSV);
    float sc1 = gt1 / (rsf[2*r2+1] + EPSV);
    float* C0 = g_comb + (rowbase + 2*r2)*DD + 2*e2;
    float* C1 = g_comb + (rowbase + 2*r2 + 1)*DD + 2*e2;
    atomicAdd(&C0[0], acc00*sc0); atomicAdd(&C0[1], acc01*sc0);
    atomicAdd(&C1[0], acc10*sc1); atomicAdd(&C1[1], acc11*sc1);
}

__global__ void zero_comb_kernel()
{
    int gid = blockIdx.x*256 + threadIdx.x;
    ((float4*)g_comb)[gid] = make_float4(0.f, 0.f, 0.f, 0.f);
}

// ---------------- 9) out = combined @ out_W^T ----------------
__global__ __launch_bounds__(256) void outproj_kernel(
    const float* __restrict__ outW, float* __restrict__ out)
{
    __shared__ float cs[16][65];
    __shared__ float ws[128][65];
    int tb = blockIdx.x * 16;
    int tid = threadIdx.x;
    #pragma unroll
    for (int e = tid; e < 16*64; e += 256) cs[e>>6][e&63] = g_comb[(size_t)tb*DD + e];
    int tk2 = tid >> 5;
    int h4  = tid & 31;
    for (int hc = 0; hc < 4; hc++) {
        __syncthreads();
        #pragma unroll
        for (int e = tid; e < 128*64; e += 256)
            ws[e>>6][e&63] = outW[(size_t)hc*128*DD + e];
        __syncthreads();
        float a0[4] = {0,0,0,0}, a1[4] = {0,0,0,0};
        #pragma unroll 4
        for (int d = 0; d < 64; d++) {
            float c0 = cs[2*tk2][d], c1 = cs[2*tk2+1][d];
            #pragma unroll
            for (int j = 0; j < 4; j++) {
                float w = ws[h4*4 + j][d];
                a0[j] += c0*w; a1[j] += c1*w;
            }
        }
        *(float4*)&out[(size_t)(tb + 2*tk2)*HID + hc*128 + h4*4] =
            make_float4(a0[0], a0[1], a0[2], a0[3]);
        *(float4*)&out[(size_t)(tb + 2*tk2 + 1)*HID + hc*128 + h4*4] =
            make_float4(a1[0], a1[1], a1[2], a1[3]);
    }
}

// ---------------- launch ----------------
extern "C" void kernel_launch(void* const* d_in, const int* in_sizes, int n_in,
                              void* d_out, int out_size)
{
    const float* x      = (const float*)d_in[0];
    const float* Wq     = (const float*)d_in[1];
    const float* Wk     = (const float*)d_in[2];
    const float* Wv     = (const float*)d_in[3];
    const float* btab   = (const float*)d_in[4];
    const float* fw     = (const float*)d_in[5];
    const float* fbias  = (const float*)d_in[6];
    const float* hopW   = (const float*)d_in[7];
    const float* gateW  = (const float*)d_in[8];
    const float* gateb  = (const float*)d_in[9];
    const float* outW   = (const float*)d_in[10];
    const float* temp   = (const float*)d_in[11];
    const int*   relidx = (const int*)d_in[12];
    float* out = (float*)d_out;

    cudaFuncSetAttribute(gemm_bf16_kernel,
                         cudaFuncAttributeMaxDynamicSharedMemorySize, GEMM_DSMEM);

    proj_kernel<<<NTOK/TOK_PB, 256>>>(x, Wq, Wk, Wv, gateW);
    rope_kernel<<<(NTOK*32)/256, 256>>>();
    hopv_gate_kernel<<<(NTOK*DD)/256, 256>>>(hopW, gateb);
    scores_kernel<<<dim3(16,16,NB), 256>>>(btab, relidx, temp);
    softmax_kernel<<<NTOK, 256>>>();
    transpose_kernel<<<dim3(32,32,NB), 256>>>();

    // hmat: 0=Ah 1=Th 2=Ph 3=Qmh ; mat: 1=P 2=Qm 3=A2 4=P2 5=Q2
    gemm_bf16_kernel<<<dim3(36,1,NB), 256, GEMM_DSMEM>>>(0,0,1, 2, 1); // P  = Ah Ah^T (tri)
    gemm_bf16_kernel<<<dim3(36,1,NB), 256, GEMM_DSMEM>>>(1,1,2, 3, 1); // Qm = Th Th^T (tri)
    gemm_bf16_kernel<<<dim3(64,1,NB), 256, GEMM_DSMEM>>>(0,1,3,-1, 0); // A2 = Ah Th^T (full)
    mirror_kernel<<<dim3(28,16,NB), 256>>>(1, 2);  // P  (+Ph)
    mirror_kernel<<<dim3(28,16,NB), 256>>>(2, 3);  // Qm (+Qmh)
    gemm_bf16_kernel<<<dim3(36,1,NB), 256, GEMM_DSMEM>>>(2,2,4,-1, 1); // P2 = Ph Ph^T (tri)
    gemm_bf16_kernel<<<dim3(36,1,NB), 256, GEMM_DSMEM>>>(3,3,5,-1, 1); // Q2 = Qmh Qmh^T (tri)
    mirror_kernel<<<dim3(28,16,NB), 256>>>(4, -1); // P2
    mirror_kernel<<<dim3(28,16,NB), 256>>>(5, -1); // Q2

    rowsum_kernel<<<dim3(NTOK, 5), 256>>>();
    zero_comb_kernel<<<NTOK*DD/4/256, 256>>>();
    fused_kernel<<<dim3(SS/16, NB, 2), 256>>>(fw, fbias);
    outproj_kernel<<<NTOK/16, 256>>>(outW, out);
}

// round 10
// speedup vs baseline: 1.6380x; 1.0406x over previous
#include <cuda_runtime.h>
#include <cuda_bf16.h>
#include <cstdint>

#define NB 8
#define SS 1024
#define DD 64
#define HID 512
#define NTOK (NB*SS)          // 8192
#define EPSV 1e-6f

// ---------------- device scratch (no allocation allowed) ----------------
__device__ float g_Q[NTOK*DD];
__device__ float g_K[NTOK*DD];
__device__ float g_V[NTOK*DD];
__device__ float g_gate[NTOK*2];
__device__ float g_rs[6*NTOK];           // rowsums: 0=A 1=P 2=Qm 3=A2 4=P2 5=Q2
__device__ float g_frs[2*NTOK];          // rowsums of fused matrices
__device__ float g_H[2*NTOK*DD];         // hop outputs (pre-norm)
__device__ float g_A [(size_t)NB*SS*SS]; // softmax attention
__device__ float g_P [(size_t)NB*SS*SS]; // A A^T
__device__ float g_Qm[(size_t)NB*SS*SS]; // A^T A
__device__ float g_A2[(size_t)NB*SS*SS]; // A A
__device__ float g_P2[(size_t)NB*SS*SS]; // P P
__device__ float g_Q2[(size_t)NB*SS*SS]; // Qm Qm
__device__ float g_F [2*(size_t)NB*SS*SS]; // fused matrices fp32
__device__ float g_hopvT[2*(size_t)NB*DD*SS]; // hopv transposed, k-major, fp32
// bf16 GEMM operands
__device__ __nv_bfloat16 g_Ah [(size_t)NB*SS*SS];
__device__ __nv_bfloat16 g_Th [(size_t)NB*SS*SS];
__device__ __nv_bfloat16 g_Ph [(size_t)NB*SS*SS];
__device__ __nv_bfloat16 g_Qmh[(size_t)NB*SS*SS];

__device__ __forceinline__ float* matsel(int s) {
    switch (s) {
        case 0: return g_A;
        case 1: return g_P;
        case 2: return g_Qm;
        case 3: return g_A2;
        case 4: return g_P2;
        default: return g_Q2;
    }
}
__device__ __forceinline__ __nv_bfloat16* hmatsel(int s) {
    switch (s) {
        case 0: return g_Ah;
        case 1: return g_Th;
        case 2: return g_Ph;
        default: return g_Qmh;
    }
}

__device__ __forceinline__ float warp_max(float v) {
    #pragma unroll
    for (int o = 16; o > 0; o >>= 1) v = fmaxf(v, __shfl_xor_sync(0xffffffffu, v, o));
    return v;
}
__device__ __forceinline__ float warp_sum(float v) {
    #pragma unroll
    for (int o = 16; o > 0; o >>= 1) v += __shfl_xor_sync(0xffffffffu, v, o);
    return v;
}

// ---------------- 1) QKV + gate-logit projection ----------------
#define TOK_PB 16
__global__ __launch_bounds__(256) void proj_kernel(
    const float* __restrict__ x, const float* __restrict__ Wq,
    const float* __restrict__ Wk, const float* __restrict__ Wv,
    const float* __restrict__ gW)
{
    __shared__ float xs[TOK_PB*HID];
    int tb = blockIdx.x * TOK_PB;
    int tid = threadIdx.x;
    const float4* xg = (const float4*)(x + (size_t)tb*HID);
    float4* xs4 = (float4*)xs;
    #pragma unroll
    for (int i = tid; i < TOK_PB*HID/4; i += 256) xs4[i] = xg[i];
    __syncthreads();

    for (int o = tid; o < TOK_PB*194; o += 256) {
        int tok = o / 194, ch = o % 194;
        const float* w;
        if (ch < 64)       w = Wq + ch*HID;
        else if (ch < 128) w = Wk + (ch-64)*HID;
        else if (ch < 192) w = Wv + (ch-128)*HID;
        else               w = gW + (ch-192)*HID;
        const float4* w4  = (const float4*)w;
        const float4* xv4 = (const float4*)(xs + tok*HID);
        float acc = 0.f;
        #pragma unroll 8
        for (int k = 0; k < HID/4; k++) {
            float4 a = xv4[k];
            float4 b = __ldg(&w4[k]);
            acc += a.x*b.x + a.y*b.y + a.z*b.z + a.w*b.w;
        }
        size_t gt = tb + tok;
        if (ch < 64)       g_Q[gt*DD + ch]        = acc;
        else if (ch < 128) g_K[gt*DD + (ch-64)]   = acc;
        else if (ch < 192) g_V[gt*DD + (ch-128)]  = acc;
        else               g_gate[gt*2 + (ch-192)] = acc;
    }
}

// ---------------- 2) RoPE in place on Q,K ----------------
__global__ void rope_kernel()
{
    int gid = blockIdx.x*256 + threadIdx.x;
    if (gid >= NTOK*32) return;
    int tok = gid >> 5, j = gid & 31;
    int s = tok & (SS-1);
    float invf = (float)exp(-log(10000.0) * (double)j / 32.0);
    float ang = (float)s * invf;
    float sn, cs;
    sincosf(ang, &sn, &cs);
    size_t base = (size_t)tok * DD;
    float q0 = g_Q[base+j], q1 = g_Q[base+j+32];
    g_Q[base+j]    = q0*cs - q1*sn;
    g_Q[base+j+32] = q1*cs + q0*sn;
    float k0 = g_K[base+j], k1 = g_K[base+j+32];
    g_K[base+j]    = k0*cs - k1*sn;
    g_K[base+j+32] = k1*cs + k0*sn;
}

// ---------------- 3) hopvT (fp32, k-major) ; gate softmax ----------------
__global__ void hopv_gate_kernel(const float* __restrict__ hopW,
                                 const float* __restrict__ gateb)
{
    int gid = blockIdx.x*256 + threadIdx.x;
    if (gid >= NTOK*DD) return;
    int tok = gid >> 6, e = gid & 63;
    int b = tok >> 10, s = tok & (SS-1);
    const float* vrow = g_V + (size_t)tok*DD;
    float a0 = 0.f, a1 = 0.f;
    #pragma unroll
    for (int d = 0; d < DD; d++) {
        float v = vrow[d];
        a0 += v * __ldg(&hopW[e*DD + d]);
        a1 += v * __ldg(&hopW[DD*DD + e*DD + d]);
    }
    g_hopvT[((size_t)(0*NB + b)*DD + e)*SS + s] = a0;
    g_hopvT[((size_t)(1*NB + b)*DD + e)*SS + s] = a1;
    if (e == 0) {
        float l0 = g_gate[tok*2]   + gateb[0];
        float l1 = g_gate[tok*2+1] + gateb[1];
        float m = fmaxf(l0, l1);
        float e0 = __expf(l0-m), e1 = __expf(l1-m);
        float inv = 1.f/(e0+e1);
        g_gate[tok*2]   = e0*inv;
        g_gate[tok*2+1] = e1*inv;
    }
}

// ---------------- 4) scores ----------------
__global__ __launch_bounds__(256) void scores_kernel(
    const float* __restrict__ bias_table, const int* __restrict__ rel_idx,
    const float* __restrict__ temperature)
{
    __shared__ float qs[64][65];
    __shared__ float ks[64][65];
    int b = blockIdx.z;
    int s0 = blockIdx.y * 64, t0 = blockIdx.x * 64;
    int tid = threadIdx.x;
    const float* Qb = g_Q + ((size_t)b*SS + s0)*DD;
    const float* Kb = g_K + ((size_t)b*SS + t0)*DD;
    #pragma unroll
    for (int e = tid; e < 64*64; e += 256) {
        qs[e>>6][e&63] = Qb[e];
        ks[e>>6][e&63] = Kb[e];
    }
    __syncthreads();
    int ty = tid >> 4, tx = tid & 15;
    float c[4][4];
    #pragma unroll
    for (int i=0;i<4;i++) { c[i][0]=0;c[i][1]=0;c[i][2]=0;c[i][3]=0; }
    #pragma unroll 4
    for (int d = 0; d < 64; d++) {
        float rq[4], rk[4];
        #pragma unroll
        for (int i=0;i<4;i++) { rq[i] = qs[ty*4+i][d]; rk[i] = ks[tx*4+i][d]; }
        #pragma unroll
        for (int i=0;i<4;i++)
            #pragma unroll
            for (int j=0;j<4;j++) c[i][j] += rq[i]*rk[j];
    }
    float inv_t = 1.f / fmaxf(temperature[0], 0.1f);
    const float scale = 0.125f;
    float* Ab = g_A + (size_t)b*SS*SS;
    #pragma unroll
    for (int i = 0; i < 4; i++) {
        int s = s0 + ty*4 + i;
        int4 idx = *(const int4*)(rel_idx + (size_t)s*SS + t0 + tx*4);
        float4 out;
        out.x = (c[i][0]*scale + __ldg(&bias_table[idx.x])) * inv_t;
        out.y = (c[i][1]*scale + __ldg(&bias_table[idx.y])) * inv_t;
        out.z = (c[i][2]*scale + __ldg(&bias_table[idx.z])) * inv_t;
        out.w = (c[i][3]*scale + __ldg(&bias_table[idx.w])) * inv_t;
        *(float4*)(Ab + (size_t)s*SS + t0 + tx*4) = out;
    }
}

// ---------------- 5) row softmax in place on g_A (+ bf16 copy) ----------------
__global__ __launch_bounds__(256) void softmax_kernel()
{
    size_t row = blockIdx.x;
    float* Ar = g_A + row*SS;
    __nv_bfloat16* Ah = g_Ah + row*SS;
    int tid = threadIdx.x;
    int wid = tid >> 5, lane = tid & 31;
    __shared__ float sm[8];
    float4 v = ((float4*)Ar)[tid];
    float m = fmaxf(fmaxf(v.x, v.y), fmaxf(v.z, v.w));
    m = warp_max(m);
    if (lane == 0) sm[wid] = m;
    __syncthreads();
    if (wid == 0) {
        float t = (lane < 8) ? sm[lane] : -3.4e38f;
        t = warp_max(t);
        if (lane == 0) sm[0] = t;
    }
    __syncthreads();
    m = sm[0];
    __syncthreads();
    float e0 = __expf(v.x-m), e1 = __expf(v.y-m), e2 = __expf(v.z-m), e3 = __expf(v.w-m);
    float s = e0+e1+e2+e3;
    s = warp_sum(s);
    if (lane == 0) sm[wid] = s;
    __syncthreads();
    if (wid == 0) {
        float t = (lane < 8) ? sm[lane] : 0.f;
        t = warp_sum(t);
        if (lane == 0) sm[0] = t;
    }
    __syncthreads();
    float inv = 1.f / sm[0];
    float4 o = make_float4(e0*inv, e1*inv, e2*inv, e3*inv);
    ((float4*)Ar)[tid] = o;
    __nv_bfloat162 h0 = __floats2bfloat162_rn(o.x, o.y);
    __nv_bfloat162 h1 = __floats2bfloat162_rn(o.z, o.w);
    ((__nv_bfloat162*)Ah)[tid*2]   = h0;
    ((__nv_bfloat162*)Ah)[tid*2+1] = h1;
    if (tid == 0) g_rs[row] = 1.0f;
}

// ---------------- 5b) transpose: g_Th = bf16(A^T) per batch ----------------
__global__ __launch_bounds__(256) void transpose_kernel()
{
    __shared__ float t[32][33];
    int b = blockIdx.z;
    int x0 = blockIdx.x*32, y0 = blockIdx.y*32;
    const float* Ab = g_A + (size_t)b*SS*SS;
    __nv_bfloat16* Tb = g_Th + (size_t)b*SS*SS;
    int tx = threadIdx.x & 31, ty = threadIdx.x >> 5;   // 32 x 8
    #pragma unroll
    for (int i = 0; i < 32; i += 8)
        t[ty+i][tx] = Ab[(size_t)(y0+ty+i)*SS + x0+tx];
    __syncthreads();
    #pragma unroll
    for (int i = 0; i < 32; i += 8)
        Tb[(size_t)(x0+ty+i)*SS + y0+tx] = __float2bfloat16(t[tx][ty+i]);
}

// ================= bf16 mma.sync batched NT GEMM =================
__device__ __forceinline__ uint32_t s2u(const void* p) {
    uint32_t a;
    asm("{ .reg .u64 t; cvta.to.shared.u64 t, %1; cvt.u32.u64 %0, t; }" : "=r"(a) : "l"(p));
    return a;
}
#define SWZ(o) ((o) ^ (((o)>>3)&0x70))

__device__ __forceinline__ void cp16(uint32_t dst, const void* src) {
    asm volatile("cp.async.cg.shared.global [%0], [%1], 16;" :: "r"(dst), "l"(src));
}
__device__ __forceinline__ void cp_commit() { asm volatile("cp.async.commit_group;" ::: "memory"); }
#define CP_WAIT(n) asm volatile("cp.async.wait_group %0;" :: "n"(n) : "memory")

__device__ __forceinline__ void ldsm4(uint32_t* r, uint32_t addr) {
    asm volatile("ldmatrix.sync.aligned.m8n8.x4.shared.b16 {%0,%1,%2,%3}, [%4];"
        : "=r"(r[0]), "=r"(r[1]), "=r"(r[2]), "=r"(r[3]) : "r"(addr));
}
__device__ __forceinline__ void mma_bf16(float* c, const uint32_t* a,
                                         uint32_t b0, uint32_t b1) {
    asm volatile(
        "mma.sync.aligned.m16n8k16.row.col.f32.bf16.bf16.f32 "
        "{%0,%1,%2,%3},{%4,%5,%6,%7},{%8,%9},{%0,%1,%2,%3};"
        : "+f"(c[0]), "+f"(c[1]), "+f"(c[2]), "+f"(c[3])
        : "r"(a[0]), "r"(a[1]), "r"(a[2]), "r"(a[3]), "r"(b0), "r"(b1));
}

#define STG 3
#define CK 64                        // k per chunk (bf16): 128B per row
#define NCH (SS/CK)                  // 16
#define STAGE_BYTES 32768
#define GEMM_DSMEM (STG*STAGE_BYTES) // 98304

__global__ __launch_bounds__(256, 2)
void gemm_bf16_kernel(int asel, int bsel, int cfsel, int chsel, int tri)
{
    extern __shared__ __align__(16) char dsmem[];
    uint32_t sb = s2u(dsmem);
    int tid = threadIdx.x;
    int warp = tid >> 5, lane = tid & 31;

    size_t off = (size_t)blockIdx.z*SS*SS;
    const __nv_bfloat16* Ag = hmatsel(asel) + off;
    const __nv_bfloat16* Bg = hmatsel(bsel) + off;
    float* Cg = matsel(cfsel) + off;
    __nv_bfloat16* Chg = (chsel >= 0) ? hmatsel(chsel) + off : nullptr;

    int bi, bj;
    if (tri) {
        int t = blockIdx.x, i = 0;
        while (t >= 8 - i) { t -= 8 - i; i++; }
        bi = i; bj = i + t;
    } else {
        bi = blockIdx.x >> 3; bj = blockIdx.x & 7;
    }
    int m0 = bi*128, n0 = bj*128;
    bool same = (tri != 0) && (bi == bj) && (asel == bsel);
    uint32_t bBase = same ? 0u : 16384u;

    int wm = (warp >> 2)*64, wn = (warp & 3)*32;
    int rlane = (lane & 7) + ((lane >> 3) & 1)*8;
    int clane = (lane >> 4) & 1;

    float acc[4][4][4];
    #pragma unroll
    for (int i = 0; i < 4; i++)
        #pragma unroll
        for (int j = 0; j < 4; j++) {
            acc[i][j][0]=0; acc[i][j][1]=0; acc[i][j][2]=0; acc[i][j][3]=0;
        }

    auto load_chunk = [&](int c) {
        uint32_t stg = sb + (uint32_t)(c % STG) * STAGE_BYTES;
        int k0 = c * CK;
        #pragma unroll
        for (int it = 0; it < 8; it++) {
            int u = tid + it*256;
            int r = u >> 3;
            int ch = u & 7;
            if (r < 128) {
                const __nv_bfloat16* gsrc = Ag + (size_t)(m0 + r)*SS + k0 + ch*8;
                cp16(stg + SWZ((uint32_t)(r*128 + ch*16)), gsrc);
            } else if (!same) {
                const __nv_bfloat16* gsrc = Bg + (size_t)(n0 + (r-128))*SS + k0 + ch*8;
                cp16(stg + 16384u + SWZ((uint32_t)((r-128)*128 + ch*16)), gsrc);
            }
        }
    };

    for (int c = 0; c < STG-1; c++) { load_chunk(c); cp_commit(); }

    for (int c = 0; c < NCH; c++) {
        int lc = c + STG - 1;
        if (lc < NCH) load_chunk(lc);
        cp_commit();
        CP_WAIT(STG-1);
        __syncthreads();
        uint32_t stg = sb + (uint32_t)(c % STG) * STAGE_BYTES;
        #pragma unroll
        for (int ks = 0; ks < CK/16; ks++) {
            uint32_t af[4][4], bfr[2][4];
            int kch = ks*2 + clane;
            #pragma unroll
            for (int mi = 0; mi < 4; mi++) {
                int r = wm + mi*16 + rlane;
                ldsm4(af[mi], stg + SWZ((uint32_t)(r*128 + kch*16)));
            }
            #pragma unroll
            for (int nt = 0; nt < 2; nt++) {
                int r = wn + nt*16 + rlane;
                ldsm4(bfr[nt], stg + bBase + SWZ((uint32_t)(r*128 + kch*16)));
            }
            #pragma unroll
            for (int mi = 0; mi < 4; mi++)
                #pragma unroll
                for (int nj = 0; nj < 4; nj++) {
                    int nt = nj >> 1, sel = nj & 1;
                    mma_bf16(acc[mi][nj], af[mi], bfr[nt][sel], bfr[nt][sel+2]);
                }
        }
        __syncthreads();
    }

    int rr = lane >> 2, cc2 = (lane & 3)*2;
    #pragma unroll
    for (int mi = 0; mi < 4; mi++) {
        #pragma unroll
        for (int nj = 0; nj < 4; nj++) {
            int row = m0 + wm + mi*16 + rr;
            int col = n0 + wn + nj*8 + cc2;
            float2 v01 = make_float2(acc[mi][nj][0], acc[mi][nj][1]);
            float2 v23 = make_float2(acc[mi][nj][2], acc[mi][nj][3]);
            *(float2*)&Cg[(size_t)row*SS + col]     = v01;
            *(float2*)&Cg[(size_t)(row+8)*SS + col] = v23;
            if (Chg) {
                *(__nv_bfloat162*)&Chg[(size_t)row*SS + col] =
                    __floats2bfloat162_rn(v01.x, v01.y);
                *(__nv_bfloat162*)&Chg[(size_t)(row+8)*SS + col] =
                    __floats2bfloat162_rn(v23.x, v23.y);
            }
        }
    }
}

// ---------------- 6b) mirror lower triangle of symmetric matrix ----------------
__global__ __launch_bounds__(256) void mirror_kernel(int msel, int hsel)
{
    __shared__ float t[32][33];
    size_t off = (size_t)blockIdx.z*SS*SS;
    float* M = matsel(msel) + off;
    __nv_bfloat16* Mh = (hsel >= 0) ? hmatsel(hsel) + off : nullptr;

    int p = blockIdx.x, i = 0;
    while (p >= 7 - i) { p -= 7 - i; i++; }
    int j = i + 1 + p;
    int sub = blockIdx.y;
    int y0 = i*128 + (sub >> 2)*32;
    int x0 = j*128 + (sub & 3)*32;
    int tx = threadIdx.x & 31, ty = threadIdx.x >> 5;
    #pragma unroll
    for (int k = 0; k < 32; k += 8)
        t[ty+k][tx] = M[(size_t)(y0+ty+k)*SS + x0+tx];
    __syncthreads();
    #pragma unroll
    for (int k = 0; k < 32; k += 8) {
        float v = t[tx][ty+k];
        size_t dst = (size_t)(x0+ty+k)*SS + y0+tx;
        M[dst] = v;
        if (Mh) Mh[dst] = __float2bfloat16(v);
    }
}

// ---------------- 7) rowsums of P,Qm,A2,P2,Q2 ----------------
__global__ __launch_bounds__(256) void rowsum_kernel()
{
    int m = blockIdx.y;
    const float* Mp = matsel(m + 1);
    size_t row = blockIdx.x;
    int tid = threadIdx.x;
    int wid = tid >> 5, lane = tid & 31;
    __shared__ float sm[8];
    float4 v = ((const float4*)(Mp + row*SS))[tid];
    float s = v.x + v.y + v.z + v.w;
    s = warp_sum(s);
    if (lane == 0) sm[wid] = s;
    __syncthreads();
    if (tid == 0) {
        float t = 0.f;
        #pragma unroll
        for (int i = 0; i < 8; i++) t += sm[i];
        g_rs[(size_t)(m+1)*NTOK + row] = t;
    }
}

// ---------------- 8a) fused matrices: fp32 F + rowsums ----------------
__device__ __forceinline__ float fuse1(float a, float b, float c,
                                       float ia, float ib, float ic,
                                       bool unitw, float w0, float w1, float w2, float fb)
{
    float ps = fminf(fmaxf(a*ia, EPSV), 1.f-EPSV);
    float pc = fminf(fmaxf(b*ib, EPSV), 1.f-EPSV);
    float pp = fminf(fmaxf(c*ic, EPSV), 1.f-EPSV);
    if (unitw) {
        float num = ps*pc*pp;
        float den = (1.f-ps+EPSV)*(1.f-pc+EPSV)*(1.f-pp+EPSV);
        return __fdividef(num, num + den);
    }
    float L0 = __logf(__fdividef(ps, 1.f-ps+EPSV));
    float L1 = __logf(__fdividef(pc, 1.f-pc+EPSV));
    float L2 = __logf(__fdividef(pp, 1.f-pp+EPSV));
    float logit = fb + w0*L0 + w1*L1 + w2*L2;
    return __fdividef(1.f, 1.f+__expf(-logit));
}

__global__ __launch_bounds__(256) void fusedmat_kernel(
    const float* __restrict__ fusion_w, const float* __restrict__ fusion_b)
{
    __shared__ float irs_s[16], irs_c[16], irs_p[16];
    int hop = blockIdx.z, b = blockIdx.y, sr0 = blockIdx.x*16;
    int tid = threadIdx.x;
    const float *Ms, *Mc, *Mp;
    int rbase;
    if (hop == 0) { Ms = g_A;  Mc = g_P;  Mp = g_Qm; rbase = 0; }
    else          { Ms = g_A2; Mc = g_P2; Mp = g_Q2; rbase = 3; }
    float w0 = fusion_w[hop*3+0], w1 = fusion_w[hop*3+1], w2 = fusion_w[hop*3+2];
    float fb = fusion_b[hop];
    bool unitw = (w0 == 1.f) && (w1 == 1.f) && (w2 == 1.f) && (fb == 0.f);
    size_t rowbase = (size_t)b*SS + sr0;

    if (tid < 16) {
        irs_s[tid] = 1.f / (g_rs[(size_t)(rbase+0)*NTOK + rowbase + tid] + EPSV);
        irs_c[tid] = 1.f / (g_rs[(size_t)(rbase+1)*NTOK + rowbase + tid] + EPSV);
        irs_p[tid] = 1.f / (g_rs[(size_t)(rbase+2)*NTOK + rowbase + tid] + EPSV);
    }
    __syncthreads();

    int r = tid >> 4, c16 = tid & 15;
    float ia = irs_s[r], ib = irs_c[r], ic = irs_p[r];
    size_t rowoff = (rowbase + r)*SS;
    float* Fr = g_F + (size_t)hop*NB*SS*SS + rowoff;
    float sum = 0.f;
    #pragma unroll
    for (int j = 0; j < 16; j++) {
        int col = c16*4 + j*64;
        float4 ms = *(const float4*)(Ms + rowoff + col);
        float4 mc = *(const float4*)(Mc + rowoff + col);
        float4 mp = *(const float4*)(Mp + rowoff + col);
        float4 f;
        f.x = fuse1(ms.x, mc.x, mp.x, ia, ib, ic, unitw, w0, w1, w2, fb);
        f.y = fuse1(ms.y, mc.y, mp.y, ia, ib, ic, unitw, w0, w1, w2, fb);
        f.z = fuse1(ms.z, mc.z, mp.z, ia, ib, ic, unitw, w0, w1, w2, fb);
        f.w = fuse1(ms.w, mc.w, mp.w, ia, ib, ic, unitw, w0, w1, w2, fb);
        sum += (f.x+f.y) + (f.z+f.w);
        *(float4*)(Fr + col) = f;
    }
    // reduce over the 16 lanes of this row (contiguous within warp)
    #pragma unroll
    for (int o = 8; o > 0; o >>= 1) sum += __shfl_xor_sync(0xffffffffu, sum, o);
    if (c16 == 0) g_frs[(size_t)hop*NTOK + rowbase + r] = sum;
}

// ---------------- 8b) H[hop] = F @ hopvT^T  (TF32 mma, 128x64 tiles) ----------------
__device__ __forceinline__ float to_tf32(float x) {
    uint32_t u;
    asm("cvt.rna.tf32.f32 %0, %1;" : "=r"(u) : "f"(x));
    return __uint_as_float(u);
}
__device__ __forceinline__ void mma_tf32(float* c,
    uint32_t a0, uint32_t a1, uint32_t a2, uint32_t a3, uint32_t b0, uint32_t b1)
{
    asm volatile(
        "mma.sync.aligned.m16n8k8.row.col.f32.tf32.tf32.f32 "
        "{%0,%1,%2,%3},{%4,%5,%6,%7},{%8,%9},{%0,%1,%2,%3};"
        : "+f"(c[0]), "+f"(c[1]), "+f"(c[2]), "+f"(c[3])
        : "r"(a0), "r"(a1), "r"(a2), "r"(a3), "r"(b0), "r"(b1));
}

__global__ __launch_bounds__(256) void hop_gemm_kernel()
{
    __shared__ float As[16][132];   // [k][m]
    __shared__ float Bs[16][68];    // [k][n]
    int tid = threadIdx.x;
    int warp = tid >> 5, lane = tid & 31;
    int hop = blockIdx.z, b = blockIdx.y, m0 = blockIdx.x*128;

    const float* Ag = g_F + (size_t)hop*NB*SS*SS + (size_t)b*SS*SS;
    const float* Bg = g_hopvT + (size_t)(hop*NB + b)*DD*SS;
    float* Hg = g_H + (size_t)hop*NTOK*DD + (size_t)b*SS*DD;

    int wr = warp >> 1, wc = warp & 1;     // 4 x 2 warps, tile 32(m) x 32(n)
    int group = lane >> 2, tig = lane & 3;

    float acc[2][4][4];
    #pragma unroll
    for (int i = 0; i < 2; i++)
        #pragma unroll
        for (int j = 0; j < 4; j++) {
            acc[i][j][0]=0; acc[i][j][1]=0; acc[i][j][2]=0; acc[i][j][3]=0;
        }

    int kk = tid & 15, ms = tid >> 4;      // staging indices
    for (int k0 = 0; k0 < SS; k0 += 16) {
        #pragma unroll
        for (int p = 0; p < 8; p++)
            As[kk][ms + p*16] = to_tf32(Ag[(size_t)(m0 + ms + p*16)*SS + k0 + kk]);
        #pragma unroll
        for (int p = 0; p < 4; p++)
            Bs[kk][ms + p*16] = to_tf32(Bg[(size_t)(ms + p*16)*SS + k0 + kk]);
        __syncthreads();
        #pragma unroll
        for (int ks = 0; ks < 2; ks++) {
            int kb = ks * 8;
            uint32_t af[2][4], bf[4][2];
            #pragma unroll
            for (int mi = 0; mi < 2; mi++) {
                int mb = wr*32 + mi*16 + group;
                af[mi][0] = __float_as_uint(As[kb+tig  ][mb]);
                af[mi][1] = __float_as_uint(As[kb+tig  ][mb+8]);
                af[mi][2] = __float_as_uint(As[kb+tig+4][mb]);
                af[mi][3] = __float_as_uint(As[kb+tig+4][mb+8]);
            }
            #pragma unroll
            for (int nj = 0; nj < 4; nj++) {
                int nb = wc*32 + nj*8 + group;
                bf[nj][0] = __float_as_uint(Bs[kb+tig  ][nb]);
                bf[nj][1] = __float_as_uint(Bs[kb+tig+4][nb]);
            }
            #pragma unroll
            for (int mi = 0; mi < 2; mi++)
                #pragma unroll
                for (int nj = 0; nj < 4; nj++)
                    mma_tf32(acc[mi][nj], af[mi][0], af[mi][1], af[mi][2], af[mi][3],
                             bf[nj][0], bf[nj][1]);
        }
        __syncthreads();
    }

    #pragma unroll
    for (int mi = 0; mi < 2; mi++)
        #pragma unroll
        for (int nj = 0; nj < 4; nj++) {
            int row = m0 + wr*32 + mi*16 + group;
            int col = wc*32 + nj*8 + 2*tig;
            *(float2*)&Hg[(size_t)row*DD + col] =
                make_float2(acc[mi][nj][0], acc[mi][nj][1]);
            *(float2*)&Hg[(size_t)(row+8)*DD + col] =
                make_float2(acc[mi][nj][2], acc[mi][nj][3]);
        }
}

// ---------------- 9) out = (gate-combined H) @ out_W^T ----------------
__global__ __launch_bounds__(256) void outproj_kernel(
    const float* __restrict__ outW, float* __restrict__ out)
{
    __shared__ float cs[16][65];
    __shared__ float ws[128][65];
    int tb = blockIdx.x * 16;
    int tid = threadIdx.x;
    #pragma unroll
    for (int e = tid; e < 16*64; e += 256) {
        int tl = e >> 6, ee = e & 63;
        int tok = tb + tl;
        float s0 = __fdividef(g_gate[tok*2+0], g_frs[tok] + EPSV);
        float s1 = __fdividef(g_gate[tok*2+1], g_frs[NTOK + tok] + EPSV);
        cs[tl][ee] = s0*g_H[(size_t)tok*DD + ee]
                   + s1*g_H[(size_t)NTOK*DD + (size_t)tok*DD + ee];
    }
    int tk2 = tid >> 5;
    int h4  = tid & 31;
    for (int hc = 0; hc < 4; hc++) {
        __syncthreads();
        #pragma unroll
        for (int e = tid; e < 128*64; e += 256)
            ws[e>>6][e&63] = outW[(size_t)hc*128*DD + e];
        __syncthreads();
        float a0[4] = {0,0,0,0}, a1[4] = {0,0,0,0};
        #pragma unroll 4
        for (int d = 0; d < 64; d++) {
            float c0 = cs[2*tk2][d], c1 = cs[2*tk2+1][d];
            #pragma unroll
            for (int j = 0; j < 4; j++) {
                float w = ws[h4*4 + j][d];
                a0[j] += c0*w; a1[j] += c1*w;
            }
        }
        *(float4*)&out[(size_t)(tb + 2*tk2)*HID + hc*128 + h4*4] =
            make_float4(a0[0], a0[1], a0[2], a0[3]);
        *(float4*)&out[(size_t)(tb + 2*tk2 + 1)*HID + hc*128 + h4*4] =
            make_float4(a1[0], a1[1], a1[2], a1[3]);
    }
}

// ---------------- launch ----------------
extern "C" void kernel_launch(void* const* d_in, const int* in_sizes, int n_in,
                              void* d_out, int out_size)
{
    const float* x      = (const float*)d_in[0];
    const float* Wq     = (const float*)d_in[1];
    const float* Wk     = (const float*)d_in[2];
    const float* Wv     = (const float*)d_in[3];
    const float* btab   = (const float*)d_in[4];
    const float* fw     = (const float*)d_in[5];
    const float* fbias  = (const float*)d_in[6];
    const float* hopW   = (const float*)d_in[7];
    const float* gateW  = (const float*)d_in[8];
    const float* gateb  = (const float*)d_in[9];
    const float* outW   = (const float*)d_in[10];
    const float* temp   = (const float*)d_in[11];
    const int*   relidx = (const int*)d_in[12];
    float* out = (float*)d_out;

    cudaFuncSetAttribute(gemm_bf16_kernel,
                         cudaFuncAttributeMaxDynamicSharedMemorySize, GEMM_DSMEM);

    proj_kernel<<<NTOK/TOK_PB, 256>>>(x, Wq, Wk, Wv, gateW);       // pos 0
    rope_kernel<<<(NTOK*32)/256, 256>>>();                          // pos 1
    hopv_gate_kernel<<<(NTOK*DD)/256, 256>>>(hopW, gateb);          // pos 2
    // pos 3: DIAGNOSTIC duplicate of the P GEMM (output fully overwritten
    // later by the real P GEMM + mirror) -> this is the launch ncu profiles.
    gemm_bf16_kernel<<<dim3(36,1,NB), 256, GEMM_DSMEM>>>(0,0,1, 2, 1);
    scores_kernel<<<dim3(16,16,NB), 256>>>(btab, relidx, temp);     // pos 4
    softmax_kernel<<<NTOK, 256>>>();
    transpose_kernel<<<dim3(32,32,NB), 256>>>();

    // hmat: 0=Ah 1=Th 2=Ph 3=Qmh ; mat: 1=P 2=Qm 3=A2 4=P2 5=Q2
    gemm_bf16_kernel<<<dim3(36,1,NB), 256, GEMM_DSMEM>>>(0,0,1, 2, 1); // P  = Ah Ah^T (tri)
    gemm_bf16_kernel<<<dim3(36,1,NB), 256, GEMM_DSMEM>>>(1,1,2, 3, 1); // Qm = Th Th^T (tri)
    gemm_bf16_kernel<<<dim3(64,1,NB), 256, GEMM_DSMEM>>>(0,1,3,-1, 0); // A2 = Ah Th^T (full)
    mirror_kernel<<<dim3(28,16,NB), 256>>>(1, 2);  // P  (+Ph)
    mirror_kernel<<<dim3(28,16,NB), 256>>>(2, 3);  // Qm (+Qmh)
    gemm_bf16_kernel<<<dim3(36,1,NB), 256, GEMM_DSMEM>>>(2,2,4,-1, 1); // P2 = Ph Ph^T (tri)
    gemm_bf16_kernel<<<dim3(36,1,NB), 256, GEMM_DSMEM>>>(3,3,5,-1, 1); // Q2 = Qmh Qmh^T (tri)
    mirror_kernel<<<dim3(28,16,NB), 256>>>(4, -1); // P2
    mirror_kernel<<<dim3(28,16,NB), 256>>>(5, -1); // Q2

    rowsum_kernel<<<dim3(NTOK, 5), 256>>>();
    fusedmat_kernel<<<dim3(SS/16, NB, 2), 256>>>(fw, fbias);
    hop_gemm_kernel<<<dim3(8, NB, 2), 256>>>();
    outproj_kernel<<<NTOK/16, 256>>>(outW, out);
}

// round 11
// speedup vs baseline: 1.8123x; 1.1064x over previous
#include <cuda_runtime.h>
#include <cuda_bf16.h>
#include <cstdint>

#define NB 8
#define SS 1024
#define DD 64
#define HID 512
#define NTOK (NB*SS)          // 8192
#define EPSV 1e-6f

// ---------------- device scratch (no allocation allowed) ----------------
__device__ float g_Q[NTOK*DD];
__device__ float g_K[NTOK*DD];
__device__ float g_V[NTOK*DD];
__device__ float g_gate[NTOK*2];
__device__ float g_frs[2*NTOK];          // rowsums of fused matrices
__device__ float g_H[2*NTOK*DD];         // hop outputs (pre-norm)
__device__ float g_A [(size_t)NB*SS*SS]; // softmax attention
__device__ float g_P [(size_t)NB*SS*SS]; // A A^T
__device__ float g_Qm[(size_t)NB*SS*SS]; // A^T A
__device__ float g_A2[(size_t)NB*SS*SS]; // A A
__device__ float g_P2[(size_t)NB*SS*SS]; // P P
__device__ float g_Q2[(size_t)NB*SS*SS]; // Qm Qm
__device__ float g_F [2*(size_t)NB*SS*SS]; // fused matrices fp32
__device__ float g_hopvT[2*(size_t)NB*DD*SS]; // hopv transposed, k-major, fp32
// bf16 GEMM operands
__device__ __nv_bfloat16 g_Ah [(size_t)NB*SS*SS];
__device__ __nv_bfloat16 g_Th [(size_t)NB*SS*SS];
__device__ __nv_bfloat16 g_Ph [(size_t)NB*SS*SS];
__device__ __nv_bfloat16 g_Qmh[(size_t)NB*SS*SS];

__device__ __forceinline__ float* matsel(int s) {
    switch (s) {
        case 0: return g_A;
        case 1: return g_P;
        case 2: return g_Qm;
        case 3: return g_A2;
        case 4: return g_P2;
        default: return g_Q2;
    }
}
__device__ __forceinline__ __nv_bfloat16* hmatsel(int s) {
    switch (s) {
        case 0: return g_Ah;
        case 1: return g_Th;
        case 2: return g_Ph;
        default: return g_Qmh;
    }
}

__device__ __forceinline__ float warp_max(float v) {
    #pragma unroll
    for (int o = 16; o > 0; o >>= 1) v = fmaxf(v, __shfl_xor_sync(0xffffffffu, v, o));
    return v;
}
__device__ __forceinline__ float warp_sum(float v) {
    #pragma unroll
    for (int o = 16; o > 0; o >>= 1) v += __shfl_xor_sync(0xffffffffu, v, o);
    return v;
}

// ---------------- 1) QKV + gate-logit projection ----------------
#define TOK_PB 16
__global__ __launch_bounds__(256) void proj_kernel(
    const float* __restrict__ x, const float* __restrict__ Wq,
    const float* __restrict__ Wk, const float* __restrict__ Wv,
    const float* __restrict__ gW)
{
    __shared__ float xs[TOK_PB*HID];
    int tb = blockIdx.x * TOK_PB;
    int tid = threadIdx.x;
    const float4* xg = (const float4*)(x + (size_t)tb*HID);
    float4* xs4 = (float4*)xs;
    #pragma unroll
    for (int i = tid; i < TOK_PB*HID/4; i += 256) xs4[i] = xg[i];
    __syncthreads();

    for (int o = tid; o < TOK_PB*194; o += 256) {
        int tok = o / 194, ch = o % 194;
        const float* w;
        if (ch < 64)       w = Wq + ch*HID;
        else if (ch < 128) w = Wk + (ch-64)*HID;
        else if (ch < 192) w = Wv + (ch-128)*HID;
        else               w = gW + (ch-192)*HID;
        const float4* w4  = (const float4*)w;
        const float4* xv4 = (const float4*)(xs + tok*HID);
        float acc = 0.f;
        #pragma unroll 8
        for (int k = 0; k < HID/4; k++) {
            float4 a = xv4[k];
            float4 b = __ldg(&w4[k]);
            acc += a.x*b.x + a.y*b.y + a.z*b.z + a.w*b.w;
        }
        size_t gt = tb + tok;
        if (ch < 64)       g_Q[gt*DD + ch]        = acc;
        else if (ch < 128) g_K[gt*DD + (ch-64)]   = acc;
        else if (ch < 192) g_V[gt*DD + (ch-128)]  = acc;
        else               g_gate[gt*2 + (ch-192)] = acc;
    }
}

// ---------------- 2) RoPE in place on Q,K ----------------
__global__ void rope_kernel()
{
    int gid = blockIdx.x*256 + threadIdx.x;
    if (gid >= NTOK*32) return;
    int tok = gid >> 5, j = gid & 31;
    int s = tok & (SS-1);
    float invf = (float)exp(-log(10000.0) * (double)j / 32.0);
    float ang = (float)s * invf;
    float sn, cs;
    sincosf(ang, &sn, &cs);
    size_t base = (size_t)tok * DD;
    float q0 = g_Q[base+j], q1 = g_Q[base+j+32];
    g_Q[base+j]    = q0*cs - q1*sn;
    g_Q[base+j+32] = q1*cs + q0*sn;
    float k0 = g_K[base+j], k1 = g_K[base+j+32];
    g_K[base+j]    = k0*cs - k1*sn;
    g_K[base+j+32] = k1*cs + k0*sn;
}

// ---------------- 3) hopvT (fp32, k-major, coalesced) ; gate softmax ----------------
__global__ void hopv_gate_kernel(const float* __restrict__ hopW,
                                 const float* __restrict__ gateb)
{
    int gid = blockIdx.x*256 + threadIdx.x;
    if (gid >= NTOK*DD) return;
    int e = gid >> 13;             // 0..63  (same e across 8192-thread span)
    int tok = gid & (NTOK-1);
    int b = tok >> 10, s = tok & (SS-1);
    const float* vrow = g_V + (size_t)tok*DD;
    float a0 = 0.f, a1 = 0.f;
    #pragma unroll
    for (int d = 0; d < DD; d++) {
        float v = vrow[d];
        a0 += v * __ldg(&hopW[e*DD + d]);
        a1 += v * __ldg(&hopW[DD*DD + e*DD + d]);
    }
    g_hopvT[((size_t)(0*NB + b)*DD + e)*SS + s] = a0;
    g_hopvT[((size_t)(1*NB + b)*DD + e)*SS + s] = a1;
    if (e == 0) {
        float l0 = g_gate[tok*2]   + gateb[0];
        float l1 = g_gate[tok*2+1] + gateb[1];
        float m = fmaxf(l0, l1);
        float e0 = __expf(l0-m), e1 = __expf(l1-m);
        float inv = 1.f/(e0+e1);
        g_gate[tok*2]   = e0*inv;
        g_gate[tok*2+1] = e1*inv;
    }
}

// ---------------- 4) scores ----------------
__global__ __launch_bounds__(256) void scores_kernel(
    const float* __restrict__ bias_table, const int* __restrict__ rel_idx,
    const float* __restrict__ temperature)
{
    __shared__ float qs[64][65];
    __shared__ float ks[64][65];
    int b = blockIdx.z;
    int s0 = blockIdx.y * 64, t0 = blockIdx.x * 64;
    int tid = threadIdx.x;
    const float* Qb = g_Q + ((size_t)b*SS + s0)*DD;
    const float* Kb = g_K + ((size_t)b*SS + t0)*DD;
    #pragma unroll
    for (int e = tid; e < 64*64; e += 256) {
        qs[e>>6][e&63] = Qb[e];
        ks[e>>6][e&63] = Kb[e];
    }
    __syncthreads();
    int ty = tid >> 4, tx = tid & 15;
    float c[4][4];
    #pragma unroll
    for (int i=0;i<4;i++) { c[i][0]=0;c[i][1]=0;c[i][2]=0;c[i][3]=0; }
    #pragma unroll 4
    for (int d = 0; d < 64; d++) {
        float rq[4], rk[4];
        #pragma unroll
        for (int i=0;i<4;i++) { rq[i] = qs[ty*4+i][d]; rk[i] = ks[tx*4+i][d]; }
        #pragma unroll
        for (int i=0;i<4;i++)
            #pragma unroll
            for (int j=0;j<4;j++) c[i][j] += rq[i]*rk[j];
    }
    float inv_t = 1.f / fmaxf(temperature[0], 0.1f);
    const float scale = 0.125f;
    float* Ab = g_A + (size_t)b*SS*SS;
    #pragma unroll
    for (int i = 0; i < 4; i++) {
        int s = s0 + ty*4 + i;
        int4 idx = *(const int4*)(rel_idx + (size_t)s*SS + t0 + tx*4);
        float4 out;
        out.x = (c[i][0]*scale + __ldg(&bias_table[idx.x])) * inv_t;
        out.y = (c[i][1]*scale + __ldg(&bias_table[idx.y])) * inv_t;
        out.z = (c[i][2]*scale + __ldg(&bias_table[idx.z])) * inv_t;
        out.w = (c[i][3]*scale + __ldg(&bias_table[idx.w])) * inv_t;
        *(float4*)(Ab + (size_t)s*SS + t0 + tx*4) = out;
    }
}

// ---------------- 5) row softmax in place on g_A (+ bf16 copy) ----------------
__global__ __launch_bounds__(256) void softmax_kernel()
{
    size_t row = blockIdx.x;
    float* Ar = g_A + row*SS;
    __nv_bfloat16* Ah = g_Ah + row*SS;
    int tid = threadIdx.x;
    int wid = tid >> 5, lane = tid & 31;
    __shared__ float sm[8];
    float4 v = ((float4*)Ar)[tid];
    float m = fmaxf(fmaxf(v.x, v.y), fmaxf(v.z, v.w));
    m = warp_max(m);
    if (lane == 0) sm[wid] = m;
    __syncthreads();
    if (wid == 0) {
        float t = (lane < 8) ? sm[lane] : -3.4e38f;
        t = warp_max(t);
        if (lane == 0) sm[0] = t;
    }
    __syncthreads();
    m = sm[0];
    __syncthreads();
    float e0 = __expf(v.x-m), e1 = __expf(v.y-m), e2 = __expf(v.z-m), e3 = __expf(v.w-m);
    float s = e0+e1+e2+e3;
    s = warp_sum(s);
    if (lane == 0) sm[wid] = s;
    __syncthreads();
    if (wid == 0) {
        float t = (lane < 8) ? sm[lane] : 0.f;
        t = warp_sum(t);
        if (lane == 0) sm[0] = t;
    }
    __syncthreads();
    float inv = 1.f / sm[0];
    float4 o = make_float4(e0*inv, e1*inv, e2*inv, e3*inv);
    ((float4*)Ar)[tid] = o;
    __nv_bfloat162 h0 = __floats2bfloat162_rn(o.x, o.y);
    __nv_bfloat162 h1 = __floats2bfloat162_rn(o.z, o.w);
    ((__nv_bfloat162*)Ah)[tid*2]   = h0;
    ((__nv_bfloat162*)Ah)[tid*2+1] = h1;
}

// ---------------- 5b) transpose: g_Th = (g_Ah)^T per batch (bf16 in/out) ----------------
__global__ __launch_bounds__(256) void transpose_kernel()
{
    __shared__ __nv_bfloat16 t[32][34];
    int b = blockIdx.z;
    int x0 = blockIdx.x*32, y0 = blockIdx.y*32;
    const __nv_bfloat16* Ab = g_Ah + (size_t)b*SS*SS;
    __nv_bfloat16* Tb = g_Th + (size_t)b*SS*SS;
    int tx = threadIdx.x & 31, ty = threadIdx.x >> 5;   // 32 x 8
    #pragma unroll
    for (int i = 0; i < 32; i += 8)
        t[ty+i][tx] = Ab[(size_t)(y0+ty+i)*SS + x0+tx];
    __syncthreads();
    #pragma unroll
    for (int i = 0; i < 32; i += 8)
        Tb[(size_t)(x0+ty+i)*SS + y0+tx] = t[tx][ty+i];
}

// ================= bf16 mma.sync batched NT GEMM =================
__device__ __forceinline__ uint32_t s2u(const void* p) {
    uint32_t a;
    asm("{ .reg .u64 t; cvta.to.shared.u64 t, %1; cvt.u32.u64 %0, t; }" : "=r"(a) : "l"(p));
    return a;
}
#define SWZ(o) ((o) ^ (((o)>>3)&0x70))

__device__ __forceinline__ void cp16(uint32_t dst, const void* src) {
    asm volatile("cp.async.cg.shared.global [%0], [%1], 16;" :: "r"(dst), "l"(src));
}
__device__ __forceinline__ void cp_commit() { asm volatile("cp.async.commit_group;" ::: "memory"); }
#define CP_WAIT(n) asm volatile("cp.async.wait_group %0;" :: "n"(n) : "memory")

__device__ __forceinline__ void ldsm4(uint32_t* r, uint32_t addr) {
    asm volatile("ldmatrix.sync.aligned.m8n8.x4.shared.b16 {%0,%1,%2,%3}, [%4];"
        : "=r"(r[0]), "=r"(r[1]), "=r"(r[2]), "=r"(r[3]) : "r"(addr));
}
__device__ __forceinline__ void mma_bf16(float* c, const uint32_t* a,
                                         uint32_t b0, uint32_t b1) {
    asm volatile(
        "mma.sync.aligned.m16n8k16.row.col.f32.bf16.bf16.f32 "
        "{%0,%1,%2,%3},{%4,%5,%6,%7},{%8,%9},{%0,%1,%2,%3};"
        : "+f"(c[0]), "+f"(c[1]), "+f"(c[2]), "+f"(c[3])
        : "r"(a[0]), "r"(a[1]), "r"(a[2]), "r"(a[3]), "r"(b0), "r"(b1));
}

#define STG 3
#define CK 64                        // k per chunk (bf16): 128B per row
#define NCH (SS/CK)                  // 16
#define STAGE_BYTES 32768
#define GEMM_DSMEM (STG*STAGE_BYTES) // 98304

__global__ __launch_bounds__(256, 2)
void gemm_bf16_kernel(int asel, int bsel, int cfsel, int chsel, int tri)
{
    extern __shared__ __align__(16) char dsmem[];
    uint32_t sb = s2u(dsmem);
    int tid = threadIdx.x;
    int warp = tid >> 5, lane = tid & 31;

    size_t off = (size_t)blockIdx.z*SS*SS;
    const __nv_bfloat16* Ag = hmatsel(asel) + off;
    const __nv_bfloat16* Bg = hmatsel(bsel) + off;
    float* Cg = matsel(cfsel) + off;
    __nv_bfloat16* Chg = (chsel >= 0) ? hmatsel(chsel) + off : nullptr;

    int bi, bj;
    if (tri) {
        int t = blockIdx.x, i = 0;
        while (t >= 8 - i) { t -= 8 - i; i++; }
        bi = i; bj = i + t;
    } else {
        bi = blockIdx.x >> 3; bj = blockIdx.x & 7;
    }
    int m0 = bi*128, n0 = bj*128;
    bool same = (tri != 0) && (bi == bj) && (asel == bsel);
    uint32_t bBase = same ? 0u : 16384u;

    int wm = (warp >> 2)*64, wn = (warp & 3)*32;
    int rlane = (lane & 7) + ((lane >> 3) & 1)*8;
    int clane = (lane >> 4) & 1;

    float acc[4][4][4];
    #pragma unroll
    for (int i = 0; i < 4; i++)
        #pragma unroll
        for (int j = 0; j < 4; j++) {
            acc[i][j][0]=0; acc[i][j][1]=0; acc[i][j][2]=0; acc[i][j][3]=0;
        }

    auto load_chunk = [&](int c) {
        uint32_t stg = sb + (uint32_t)(c % STG) * STAGE_BYTES;
        int k0 = c * CK;
        #pragma unroll
        for (int it = 0; it < 8; it++) {
            int u = tid + it*256;
            int r = u >> 3;
            int ch = u & 7;
            if (r < 128) {
                const __nv_bfloat16* gsrc = Ag + (size_t)(m0 + r)*SS + k0 + ch*8;
                cp16(stg + SWZ((uint32_t)(r*128 + ch*16)), gsrc);
            } else if (!same) {
                const __nv_bfloat16* gsrc = Bg + (size_t)(n0 + (r-128))*SS + k0 + ch*8;
                cp16(stg + 16384u + SWZ((uint32_t)((r-128)*128 + ch*16)), gsrc);
            }
        }
    };

    for (int c = 0; c < STG-1; c++) { load_chunk(c); cp_commit(); }

    for (int c = 0; c < NCH; c++) {
        int lc = c + STG - 1;
        if (lc < NCH) load_chunk(lc);
        cp_commit();
        CP_WAIT(STG-1);
        __syncthreads();
        uint32_t stg = sb + (uint32_t)(c % STG) * STAGE_BYTES;
        #pragma unroll
        for (int ks = 0; ks < CK/16; ks++) {
            uint32_t af[4][4], bfr[2][4];
            int kch = ks*2 + clane;
            #pragma unroll
            for (int mi = 0; mi < 4; mi++) {
                int r = wm + mi*16 + rlane;
                ldsm4(af[mi], stg + SWZ((uint32_t)(r*128 + kch*16)));
            }
            #pragma unroll
            for (int nt = 0; nt < 2; nt++) {
                int r = wn + nt*16 + rlane;
                ldsm4(bfr[nt], stg + bBase + SWZ((uint32_t)(r*128 + kch*16)));
            }
            #pragma unroll
            for (int mi = 0; mi < 4; mi++)
                #pragma unroll
                for (int nj = 0; nj < 4; nj++) {
                    int nt = nj >> 1, sel = nj & 1;
                    mma_bf16(acc[mi][nj], af[mi], bfr[nt][sel], bfr[nt][sel+2]);
                }
        }
        __syncthreads();
    }

    int rr = lane >> 2, cc2 = (lane & 3)*2;
    #pragma unroll
    for (int mi = 0; mi < 4; mi++) {
        #pragma unroll
        for (int nj = 0; nj < 4; nj++) {
            int row = m0 + wm + mi*16 + rr;
            int col = n0 + wn + nj*8 + cc2;
            float2 v01 = make_float2(acc[mi][nj][0], acc[mi][nj][1]);
            float2 v23 = make_float2(acc[mi][nj][2], acc[mi][nj][3]);
            *(float2*)&Cg[(size_t)row*SS + col]     = v01;
            *(float2*)&Cg[(size_t)(row+8)*SS + col] = v23;
            if (Chg) {
                *(__nv_bfloat162*)&Chg[(size_t)row*SS + col] =
                    __floats2bfloat162_rn(v01.x, v01.y);
                *(__nv_bfloat162*)&Chg[(size_t)(row+8)*SS + col] =
                    __floats2bfloat162_rn(v23.x, v23.y);
            }
        }
    }
}

// ---------------- 6b) mirror lower triangle of two symmetric matrices ----------------
// grid: x = 28 block-pairs, y = 32 (16 subtiles x 2 matrices), z = batch
__global__ __launch_bounds__(256) void mirror2_kernel(
    int m0sel, int h0sel, int m1sel, int h1sel)
{
    __shared__ float t[32][33];
    size_t off = (size_t)blockIdx.z*SS*SS;
    int which = blockIdx.y >> 4;
    int msel = which ? m1sel : m0sel;
    int hsel = which ? h1sel : h0sel;
    float* M = matsel(msel) + off;
    __nv_bfloat16* Mh = (hsel >= 0) ? hmatsel(hsel) + off : nullptr;

    int p = blockIdx.x, i = 0;
    while (p >= 7 - i) { p -= 7 - i; i++; }
    int j = i + 1 + p;
    int sub = blockIdx.y & 15;
    int y0 = i*128 + (sub >> 2)*32;
    int x0 = j*128 + (sub & 3)*32;
    int tx = threadIdx.x & 31, ty = threadIdx.x >> 5;
    #pragma unroll
    for (int k = 0; k < 32; k += 8)
        t[ty+k][tx] = M[(size_t)(y0+ty+k)*SS + x0+tx];
    __syncthreads();
    #pragma unroll
    for (int k = 0; k < 32; k += 8) {
        float v = t[tx][ty+k];
        size_t dst = (size_t)(x0+ty+k)*SS + y0+tx;
        M[dst] = v;
        if (Mh) Mh[dst] = __float2bfloat16(v);
    }
}

// ---------------- 8a) fused matrices: fp32 F + self-computed rowsums ----------------
__device__ __forceinline__ float fuse1(float a, float b, float c,
                                       float ia, float ib, float ic,
                                       bool unitw, float w0, float w1, float w2, float fb)
{
    float ps = fminf(fmaxf(a*ia, EPSV), 1.f-EPSV);
    float pc = fminf(fmaxf(b*ib, EPSV), 1.f-EPSV);
    float pp = fminf(fmaxf(c*ic, EPSV), 1.f-EPSV);
    if (unitw) {
        float num = ps*pc*pp;
        float den = (1.f-ps+EPSV)*(1.f-pc+EPSV)*(1.f-pp+EPSV);
        return __fdividef(num, num + den);
    }
    float L0 = __logf(__fdividef(ps, 1.f-ps+EPSV));
    float L1 = __logf(__fdividef(pc, 1.f-pc+EPSV));
    float L2 = __logf(__fdividef(pp, 1.f-pp+EPSV));
    float logit = fb + w0*L0 + w1*L1 + w2*L2;
    return __fdividef(1.f, 1.f+__expf(-logit));
}

__global__ __launch_bounds__(256) void fusedmat_kernel(
    const float* __restrict__ fusion_w, const float* __restrict__ fusion_b)
{
    int hop = blockIdx.z, b = blockIdx.y, sr0 = blockIdx.x*16;
    int tid = threadIdx.x;
    const float *Ms, *Mc, *Mp;
    if (hop == 0) { Ms = g_A;  Mc = g_P;  Mp = g_Qm; }
    else          { Ms = g_A2; Mc = g_P2; Mp = g_Q2; }
    float w0 = fusion_w[hop*3+0], w1 = fusion_w[hop*3+1], w2 = fusion_w[hop*3+2];
    float fb = fusion_b[hop];
    bool unitw = (w0 == 1.f) && (w1 == 1.f) && (w2 == 1.f) && (fb == 0.f);
    size_t rowbase = (size_t)b*SS + sr0;

    int r = tid >> 4, c16 = tid & 15;
    size_t rowoff = (rowbase + r)*SS;

    // pass 1: row sums of the three source matrices for this row
    float sa = 0.f, sb2 = 0.f, sc = 0.f;
    #pragma unroll
    for (int j = 0; j < 16; j++) {
        int col = c16*4 + j*64;
        float4 ms = *(const float4*)(Ms + rowoff + col);
        float4 mc = *(const float4*)(Mc + rowoff + col);
        float4 mp = *(const float4*)(Mp + rowoff + col);
        sa  += (ms.x+ms.y) + (ms.z+ms.w);
        sb2 += (mc.x+mc.y) + (mc.z+mc.w);
        sc  += (mp.x+mp.y) + (mp.z+mp.w);
    }
    #pragma unroll
    for (int o = 8; o > 0; o >>= 1) {
        sa  += __shfl_xor_sync(0xffffffffu, sa,  o);
        sb2 += __shfl_xor_sync(0xffffffffu, sb2, o);
        sc  += __shfl_xor_sync(0xffffffffu, sc,  o);
    }
    float ia = 1.f/(sa + EPSV), ib = 1.f/(sb2 + EPSV), ic = 1.f/(sc + EPSV);

    // pass 2: fused matrix + its rowsum (re-reads hit L1/L2)
    float* Fr = g_F + (size_t)hop*NB*SS*SS + rowoff;
    float sum = 0.f;
    #pragma unroll
    for (int j = 0; j < 16; j++) {
        int col = c16*4 + j*64;
        float4 ms = *(const float4*)(Ms + rowoff + col);
        float4 mc = *(const float4*)(Mc + rowoff + col);
        float4 mp = *(const float4*)(Mp + rowoff + col);
        float4 f;
        f.x = fuse1(ms.x, mc.x, mp.x, ia, ib, ic, unitw, w0, w1, w2, fb);
        f.y = fuse1(ms.y, mc.y, mp.y, ia, ib, ic, unitw, w0, w1, w2, fb);
        f.z = fuse1(ms.z, mc.z, mp.z, ia, ib, ic, unitw, w0, w1, w2, fb);
        f.w = fuse1(ms.w, mc.w, mp.w, ia, ib, ic, unitw, w0, w1, w2, fb);
        sum += (f.x+f.y) + (f.z+f.w);
        *(float4*)(Fr + col) = f;
    }
    #pragma unroll
    for (int o = 8; o > 0; o >>= 1) sum += __shfl_xor_sync(0xffffffffu, sum, o);
    if (c16 == 0) g_frs[(size_t)hop*NTOK + rowbase + r] = sum;
}

// ---------------- 8b) H[hop] = F @ hopvT^T  (TF32 mma, 128x64 tiles) ----------------
__device__ __forceinline__ float to_tf32(float x) {
    uint32_t u;
    asm("cvt.rna.tf32.f32 %0, %1;" : "=r"(u) : "f"(x));
    return __uint_as_float(u);
}
__device__ __forceinline__ void mma_tf32(float* c,
    uint32_t a0, uint32_t a1, uint32_t a2, uint32_t a3, uint32_t b0, uint32_t b1)
{
    asm volatile(
        "mma.sync.aligned.m16n8k8.row.col.f32.tf32.tf32.f32 "
        "{%0,%1,%2,%3},{%4,%5,%6,%7},{%8,%9},{%0,%1,%2,%3};"
        : "+f"(c[0]), "+f"(c[1]), "+f"(c[2]), "+f"(c[3])
        : "r"(a0), "r"(a1), "r"(a2), "r"(a3), "r"(b0), "r"(b1));
}

__global__ __launch_bounds__(256) void hop_gemm_kernel()
{
    __shared__ float As[16][132];   // [k][m]
    __shared__ float Bs[16][68];    // [k][n]
    int tid = threadIdx.x;
    int warp = tid >> 5, lane = tid & 31;
    int hop = blockIdx.z, b = blockIdx.y, m0 = blockIdx.x*128;

    const float* Ag = g_F + (size_t)hop*NB*SS*SS + (size_t)b*SS*SS;
    const float* Bg = g_hopvT + (size_t)(hop*NB + b)*DD*SS;
    float* Hg = g_H + (size_t)hop*NTOK*DD + (size_t)b*SS*DD;

    int wr = warp >> 1, wc = warp & 1;     // 4 x 2 warps, tile 32(m) x 32(n)
    int group = lane >> 2, tig = lane & 3;

    float acc[2][4][4];
    #pragma unroll
    for (int i = 0; i < 2; i++)
        #pragma unroll
        for (int j = 0; j < 4; j++) {
            acc[i][j][0]=0; acc[i][j][1]=0; acc[i][j][2]=0; acc[i][j][3]=0;
        }

    int kk = tid & 15, ms = tid >> 4;      // staging indices
    for (int k0 = 0; k0 < SS; k0 += 16) {
        #pragma unroll
        for (int p = 0; p < 8; p++)
            As[kk][ms + p*16] = to_tf32(Ag[(size_t)(m0 + ms + p*16)*SS + k0 + kk]);
        #pragma unroll
        for (int p = 0; p < 4; p++)
            Bs[kk][ms + p*16] = to_tf32(Bg[(size_t)(ms + p*16)*SS + k0 + kk]);
        __syncthreads();
        #pragma unroll
        for (int ks = 0; ks < 2; ks++) {
            int kb = ks * 8;
            uint32_t af[2][4], bf[4][2];
            #pragma unroll
            for (int mi = 0; mi < 2; mi++) {
                int mb = wr*32 + mi*16 + group;
                af[mi][0] = __float_as_uint(As[kb+tig  ][mb]);
                af[mi][1] = __float_as_uint(As[kb+tig  ][mb+8]);
                af[mi][2] = __float_as_uint(As[kb+tig+4][mb]);
                af[mi][3] = __float_as_uint(As[kb+tig+4][mb+8]);
            }
            #pragma unroll
            for (int nj = 0; nj < 4; nj++) {
                int nb = wc*32 + nj*8 + group;
                bf[nj][0] = __float_as_uint(Bs[kb+tig  ][nb]);
                bf[nj][1] = __float_as_uint(Bs[kb+tig+4][nb]);
            }
            #pragma unroll
            for (int mi = 0; mi < 2; mi++)
                #pragma unroll
                for (int nj = 0; nj < 4; nj++)
                    mma_tf32(acc[mi][nj], af[mi][0], af[mi][1], af[mi][2], af[mi][3],
                             bf[nj][0], bf[nj][1]);
        }
        __syncthreads();
    }

    #pragma unroll
    for (int mi = 0; mi < 2; mi++)
        #pragma unroll
        for (int nj = 0; nj < 4; nj++) {
            int row = m0 + wr*32 + mi*16 + group;
            int col = wc*32 + nj*8 + 2*tig;
            *(float2*)&Hg[(size_t)row*DD + col] =
                make_float2(acc[mi][nj][0], acc[mi][nj][1]);
            *(float2*)&Hg[(size_t)(row+8)*DD + col] =
                make_float2(acc[mi][nj][2], acc[mi][nj][3]);
        }
}

// ---------------- 9) out = (gate-combined H) @ out_W^T ----------------
__global__ __launch_bounds__(256) void outproj_kernel(
    const float* __restrict__ outW, float* __restrict__ out)
{
    __shared__ float cs[16][65];
    __shared__ float ws[128][65];
    int tb = blockIdx.x * 16;
    int tid = threadIdx.x;
    #pragma unroll
    for (int e = tid; e < 16*64; e += 256) {
        int tl = e >> 6, ee = e & 63;
        int tok = tb + tl;
        float s0 = __fdividef(g_gate[tok*2+0], g_frs[tok] + EPSV);
        float s1 = __fdividef(g_gate[tok*2+1], g_frs[NTOK + tok] + EPSV);
        cs[tl][ee] = s0*g_H[(size_t)tok*DD + ee]
                   + s1*g_H[(size_t)NTOK*DD + (size_t)tok*DD + ee];
    }
    int tk2 = tid >> 5;
    int h4  = tid & 31;
    for (int hc = 0; hc < 4; hc++) {
        __syncthreads();
        #pragma unroll
        for (int e = tid; e < 128*64; e += 256)
            ws[e>>6][e&63] = outW[(size_t)hc*128*DD + e];
        __syncthreads();
        float a0[4] = {0,0,0,0}, a1[4] = {0,0,0,0};
        #pragma unroll 4
        for (int d = 0; d < 64; d++) {
            float c0 = cs[2*tk2][d], c1 = cs[2*tk2+1][d];
            #pragma unroll
            for (int j = 0; j < 4; j++) {
                float w = ws[h4*4 + j][d];
                a0[j] += c0*w; a1[j] += c1*w;
            }
        }
        *(float4*)&out[(size_t)(tb + 2*tk2)*HID + hc*128 + h4*4] =
            make_float4(a0[0], a0[1], a0[2], a0[3]);
        *(float4*)&out[(size_t)(tb + 2*tk2 + 1)*HID + hc*128 + h4*4] =
            make_float4(a1[0], a1[1], a1[2], a1[3]);
    }
}

// ---------------- launch ----------------
extern "C" void kernel_launch(void* const* d_in, const int* in_sizes, int n_in,
                              void* d_out, int out_size)
{
    const float* x      = (const float*)d_in[0];
    const float* Wq     = (const float*)d_in[1];
    const float* Wk     = (const float*)d_in[2];
    const float* Wv     = (const float*)d_in[3];
    const float* btab   = (const float*)d_in[4];
    const float* fw     = (const float*)d_in[5];
    const float* fbias  = (const float*)d_in[6];
    const float* hopW   = (const float*)d_in[7];
    const float* gateW  = (const float*)d_in[8];
    const float* gateb  = (const float*)d_in[9];
    const float* outW   = (const float*)d_in[10];
    const float* temp   = (const float*)d_in[11];
    const int*   relidx = (const int*)d_in[12];
    float* out = (float*)d_out;

    cudaFuncSetAttribute(gemm_bf16_kernel,
                         cudaFuncAttributeMaxDynamicSharedMemorySize, GEMM_DSMEM);

    proj_kernel<<<NTOK/TOK_PB, 256>>>(x, Wq, Wk, Wv, gateW);
    rope_kernel<<<(NTOK*32)/256, 256>>>();
    hopv_gate_kernel<<<(NTOK*DD)/256, 256>>>(hopW, gateb);
    scores_kernel<<<dim3(16,16,NB), 256>>>(btab, relidx, temp);
    softmax_kernel<<<NTOK, 256>>>();
    transpose_kernel<<<dim3(32,32,NB), 256>>>();

    // hmat: 0=Ah 1=Th 2=Ph 3=Qmh ; mat: 1=P 2=Qm 3=A2 4=P2 5=Q2
    gemm_bf16_kernel<<<dim3(36,1,NB), 256, GEMM_DSMEM>>>(0,0,1, 2, 1); // P  = Ah Ah^T (tri)
    gemm_bf16_kernel<<<dim3(36,1,NB), 256, GEMM_DSMEM>>>(1,1,2, 3, 1); // Qm = Th Th^T (tri)
    gemm_bf16_kernel<<<dim3(64,1,NB), 256, GEMM_DSMEM>>>(0,1,3,-1, 0); // A2 = Ah Th^T (full)
    mirror2_kernel<<<dim3(28,32,NB), 256>>>(1, 2, 2, 3);               // P(+Ph), Qm(+Qmh)
    gemm_bf16_kernel<<<dim3(36,1,NB), 256, GEMM_DSMEM>>>(2,2,4,-1, 1); // P2 = Ph Ph^T (tri)
    gemm_bf16_kernel<<<dim3(36,1,NB), 256, GEMM_DSMEM>>>(3,3,5,-1, 1); // Q2 = Qmh Qmh^T (tri)
    mirror2_kernel<<<dim3(28,32,NB), 256>>>(4, -1, 5, -1);             // P2, Q2

    fusedmat_kernel<<<dim3(SS/16, NB, 2), 256>>>(fw, fbias);
    hop_gemm_kernel<<<dim3(8, NB, 2), 256>>>();
    outproj_kernel<<<NTOK/16, 256>>>(outW, out);
}

// round 12
// speedup vs baseline: 1.8599x; 1.0263x over previous
#include <cuda_runtime.h>
#include <cuda_bf16.h>
#include <cstdint>

#define NB 8
#define SS 1024
#define DD 64
#define HID 512
#define NTOK (NB*SS)          // 8192
#define EPSV 1e-6f

// ---------------- device scratch (no allocation allowed) ----------------
__device__ float g_Q[NTOK*DD];
__device__ float g_K[NTOK*DD];
__device__ float g_V[NTOK*DD];
__device__ float g_gate[NTOK*2];
__device__ float g_rs[6*NTOK];           // rowsums: slots 1..5 = P,Qm,A2,P2,Q2
__device__ float g_frs[2*NTOK];          // rowsums of fused matrices
__device__ float g_H[2*NTOK*DD];         // hop outputs (pre-norm, atomically accumulated)
__device__ float g_A [(size_t)NB*SS*SS]; // softmax attention
__device__ float g_P [(size_t)NB*SS*SS]; // A A^T
__device__ float g_Qm[(size_t)NB*SS*SS]; // A^T A
__device__ float g_A2[(size_t)NB*SS*SS]; // A A
__device__ float g_P2[(size_t)NB*SS*SS]; // P P
__device__ float g_Q2[(size_t)NB*SS*SS]; // Qm Qm
__device__ float g_F [2*(size_t)NB*SS*SS]; // fused matrices fp32
__device__ float g_hopvT[2*(size_t)NB*DD*SS]; // hopv transposed, k-major, fp32
// bf16 GEMM operands
__device__ __nv_bfloat16 g_Ah [(size_t)NB*SS*SS];
__device__ __nv_bfloat16 g_Th [(size_t)NB*SS*SS];
__device__ __nv_bfloat16 g_Ph [(size_t)NB*SS*SS];
__device__ __nv_bfloat16 g_Qmh[(size_t)NB*SS*SS];

__device__ __forceinline__ float* matsel(int s) {
    switch (s) {
        case 0: return g_A;
        case 1: return g_P;
        case 2: return g_Qm;
        case 3: return g_A2;
        case 4: return g_P2;
        default: return g_Q2;
    }
}
__device__ __forceinline__ __nv_bfloat16* hmatsel(int s) {
    switch (s) {
        case 0: return g_Ah;
        case 1: return g_Th;
        case 2: return g_Ph;
        default: return g_Qmh;
    }
}

__device__ __forceinline__ float warp_max(float v) {
    #pragma unroll
    for (int o = 16; o > 0; o >>= 1) v = fmaxf(v, __shfl_xor_sync(0xffffffffu, v, o));
    return v;
}
__device__ __forceinline__ float warp_sum(float v) {
    #pragma unroll
    for (int o = 16; o > 0; o >>= 1) v += __shfl_xor_sync(0xffffffffu, v, o);
    return v;
}

// ---------------- 0) zero g_rs + g_H ----------------
__global__ void zero_kernel()
{
    int gid = blockIdx.x*256 + threadIdx.x;   // float4 index
    if (gid < 6*NTOK/4)
        ((float4*)g_rs)[gid] = make_float4(0.f,0.f,0.f,0.f);
    else
        ((float4*)g_H)[gid - 6*NTOK/4] = make_float4(0.f,0.f,0.f,0.f);
}
#define ZERO_BLOCKS ((6*NTOK/4 + 2*NTOK*DD/4 + 255)/256)

// ---------------- 1) QKV + gate-logit projection ----------------
#define TOK_PB 16
__global__ __launch_bounds__(256) void proj_kernel(
    const float* __restrict__ x, const float* __restrict__ Wq,
    const float* __restrict__ Wk, const float* __restrict__ Wv,
    const float* __restrict__ gW)
{
    __shared__ float xs[TOK_PB*HID];
    int tb = blockIdx.x * TOK_PB;
    int tid = threadIdx.x;
    const float4* xg = (const float4*)(x + (size_t)tb*HID);
    float4* xs4 = (float4*)xs;
    #pragma unroll
    for (int i = tid; i < TOK_PB*HID/4; i += 256) xs4[i] = xg[i];
    __syncthreads();

    for (int o = tid; o < TOK_PB*194; o += 256) {
        int tok = o / 194, ch = o % 194;
        const float* w;
        if (ch < 64)       w = Wq + ch*HID;
        else if (ch < 128) w = Wk + (ch-64)*HID;
        else if (ch < 192) w = Wv + (ch-128)*HID;
        else               w = gW + (ch-192)*HID;
        const float4* w4  = (const float4*)w;
        const float4* xv4 = (const float4*)(xs + tok*HID);
        float acc = 0.f;
        #pragma unroll 8
        for (int k = 0; k < HID/4; k++) {
            float4 a = xv4[k];
            float4 b = __ldg(&w4[k]);
            acc += a.x*b.x + a.y*b.y + a.z*b.z + a.w*b.w;
        }
        size_t gt = tb + tok;
        if (ch < 64)       g_Q[gt*DD + ch]        = acc;
        else if (ch < 128) g_K[gt*DD + (ch-64)]   = acc;
        else if (ch < 192) g_V[gt*DD + (ch-128)]  = acc;
        else               g_gate[gt*2 + (ch-192)] = acc;
    }
}

// ---------------- 2) RoPE in place on Q,K ----------------
__global__ void rope_kernel()
{
    int gid = blockIdx.x*256 + threadIdx.x;
    if (gid >= NTOK*32) return;
    int tok = gid >> 5, j = gid & 31;
    int s = tok & (SS-1);
    float invf = (float)exp(-log(10000.0) * (double)j / 32.0);
    float ang = (float)s * invf;
    float sn, cs;
    sincosf(ang, &sn, &cs);
    size_t base = (size_t)tok * DD;
    float q0 = g_Q[base+j], q1 = g_Q[base+j+32];
    g_Q[base+j]    = q0*cs - q1*sn;
    g_Q[base+j+32] = q1*cs + q0*sn;
    float k0 = g_K[base+j], k1 = g_K[base+j+32];
    g_K[base+j]    = k0*cs - k1*sn;
    g_K[base+j+32] = k1*cs + k0*sn;
}

// ---------------- 3) hopvT (fp32, k-major, coalesced) ; gate softmax ----------------
__global__ void hopv_gate_kernel(const float* __restrict__ hopW,
                                 const float* __restrict__ gateb)
{
    int gid = blockIdx.x*256 + threadIdx.x;
    if (gid >= NTOK*DD) return;
    int e = gid >> 13;             // 0..63
    int tok = gid & (NTOK-1);
    int b = tok >> 10, s = tok & (SS-1);
    const float* vrow = g_V + (size_t)tok*DD;
    float a0 = 0.f, a1 = 0.f;
    #pragma unroll
    for (int d = 0; d < DD; d++) {
        float v = vrow[d];
        a0 += v * __ldg(&hopW[e*DD + d]);
        a1 += v * __ldg(&hopW[DD*DD + e*DD + d]);
    }
    g_hopvT[((size_t)(0*NB + b)*DD + e)*SS + s] = a0;
    g_hopvT[((size_t)(1*NB + b)*DD + e)*SS + s] = a1;
    if (e == 0) {
        float l0 = g_gate[tok*2]   + gateb[0];
        float l1 = g_gate[tok*2+1] + gateb[1];
        float m = fmaxf(l0, l1);
        float e0 = __expf(l0-m), e1 = __expf(l1-m);
        float inv = 1.f/(e0+e1);
        g_gate[tok*2]   = e0*inv;
        g_gate[tok*2+1] = e1*inv;
    }
}

// ---------------- 4) scores ----------------
__global__ __launch_bounds__(256) void scores_kernel(
    const float* __restrict__ bias_table, const int* __restrict__ rel_idx,
    const float* __restrict__ temperature)
{
    __shared__ float qs[64][65];
    __shared__ float ks[64][65];
    int b = blockIdx.z;
    int s0 = blockIdx.y * 64, t0 = blockIdx.x * 64;
    int tid = threadIdx.x;
    const float* Qb = g_Q + ((size_t)b*SS + s0)*DD;
    const float* Kb = g_K + ((size_t)b*SS + t0)*DD;
    #pragma unroll
    for (int e = tid; e < 64*64; e += 256) {
        qs[e>>6][e&63] = Qb[e];
        ks[e>>6][e&63] = Kb[e];
    }
    __syncthreads();
    int ty = tid >> 4, tx = tid & 15;
    float c[4][4];
    #pragma unroll
    for (int i=0;i<4;i++) { c[i][0]=0;c[i][1]=0;c[i][2]=0;c[i][3]=0; }
    #pragma unroll 4
    for (int d = 0; d < 64; d++) {
        float rq[4], rk[4];
        #pragma unroll
        for (int i=0;i<4;i++) { rq[i] = qs[ty*4+i][d]; rk[i] = ks[tx*4+i][d]; }
        #pragma unroll
        for (int i=0;i<4;i++)
            #pragma unroll
            for (int j=0;j<4;j++) c[i][j] += rq[i]*rk[j];
    }
    float inv_t = 1.f / fmaxf(temperature[0], 0.1f);
    const float scale = 0.125f;
    float* Ab = g_A + (size_t)b*SS*SS;
    #pragma unroll
    for (int i = 0; i < 4; i++) {
        int s = s0 + ty*4 + i;
        int4 idx = *(const int4*)(rel_idx + (size_t)s*SS + t0 + tx*4);
        float4 out;
        out.x = (c[i][0]*scale + __ldg(&bias_table[idx.x])) * inv_t;
        out.y = (c[i][1]*scale + __ldg(&bias_table[idx.y])) * inv_t;
        out.z = (c[i][2]*scale + __ldg(&bias_table[idx.z])) * inv_t;
        out.w = (c[i][3]*scale + __ldg(&bias_table[idx.w])) * inv_t;
        *(float4*)(Ab + (size_t)s*SS + t0 + tx*4) = out;
    }
}

// ---------------- 5) row softmax in place on g_A (+ bf16 copy) ----------------
__global__ __launch_bounds__(256) void softmax_kernel()
{
    size_t row = blockIdx.x;
    float* Ar = g_A + row*SS;
    __nv_bfloat16* Ah = g_Ah + row*SS;
    int tid = threadIdx.x;
    int wid = tid >> 5, lane = tid & 31;
    __shared__ float sm[8];
    float4 v = ((float4*)Ar)[tid];
    float m = fmaxf(fmaxf(v.x, v.y), fmaxf(v.z, v.w));
    m = warp_max(m);
    if (lane == 0) sm[wid] = m;
    __syncthreads();
    if (wid == 0) {
        float t = (lane < 8) ? sm[lane] : -3.4e38f;
        t = warp_max(t);
        if (lane == 0) sm[0] = t;
    }
    __syncthreads();
    m = sm[0];
    __syncthreads();
    float e0 = __expf(v.x-m), e1 = __expf(v.y-m), e2 = __expf(v.z-m), e3 = __expf(v.w-m);
    float s = e0+e1+e2+e3;
    s = warp_sum(s);
    if (lane == 0) sm[wid] = s;
    __syncthreads();
    if (wid == 0) {
        float t = (lane < 8) ? sm[lane] : 0.f;
        t = warp_sum(t);
        if (lane == 0) sm[0] = t;
    }
    __syncthreads();
    float inv = 1.f / sm[0];
    float4 o = make_float4(e0*inv, e1*inv, e2*inv, e3*inv);
    ((float4*)Ar)[tid] = o;
    __nv_bfloat162 h0 = __floats2bfloat162_rn(o.x, o.y);
    __nv_bfloat162 h1 = __floats2bfloat162_rn(o.z, o.w);
    ((__nv_bfloat162*)Ah)[tid*2]   = h0;
    ((__nv_bfloat162*)Ah)[tid*2+1] = h1;
}

// ---------------- 5b) transpose: g_Th = (g_Ah)^T per batch (bf16 in/out) ----------------
__global__ __launch_bounds__(256) void transpose_kernel()
{
    __shared__ __nv_bfloat16 t[32][34];
    int b = blockIdx.z;
    int x0 = blockIdx.x*32, y0 = blockIdx.y*32;
    const __nv_bfloat16* Ab = g_Ah + (size_t)b*SS*SS;
    __nv_bfloat16* Tb = g_Th + (size_t)b*SS*SS;
    int tx = threadIdx.x & 31, ty = threadIdx.x >> 5;   // 32 x 8
    #pragma unroll
    for (int i = 0; i < 32; i += 8)
        t[ty+i][tx] = Ab[(size_t)(y0+ty+i)*SS + x0+tx];
    __syncthreads();
    #pragma unroll
    for (int i = 0; i < 32; i += 8)
        Tb[(size_t)(x0+ty+i)*SS + y0+tx] = t[tx][ty+i];
}

// ================= bf16 mma.sync batched NT GEMM (+rowsum epilogue) =================
__device__ __forceinline__ uint32_t s2u(const void* p) {
    uint32_t a;
    asm("{ .reg .u64 t; cvta.to.shared.u64 t, %1; cvt.u32.u64 %0, t; }" : "=r"(a) : "l"(p));
    return a;
}
#define SWZ(o) ((o) ^ (((o)>>3)&0x70))

__device__ __forceinline__ void cp16(uint32_t dst, const void* src) {
    asm volatile("cp.async.cg.shared.global [%0], [%1], 16;" :: "r"(dst), "l"(src));
}
__device__ __forceinline__ void cp_commit() { asm volatile("cp.async.commit_group;" ::: "memory"); }
#define CP_WAIT(n) asm volatile("cp.async.wait_group %0;" :: "n"(n) : "memory")

__device__ __forceinline__ void ldsm4(uint32_t* r, uint32_t addr) {
    asm volatile("ldmatrix.sync.aligned.m8n8.x4.shared.b16 {%0,%1,%2,%3}, [%4];"
        : "=r"(r[0]), "=r"(r[1]), "=r"(r[2]), "=r"(r[3]) : "r"(addr));
}
__device__ __forceinline__ void mma_bf16(float* c, const uint32_t* a,
                                         uint32_t b0, uint32_t b1) {
    asm volatile(
        "mma.sync.aligned.m16n8k16.row.col.f32.bf16.bf16.f32 "
        "{%0,%1,%2,%3},{%4,%5,%6,%7},{%8,%9},{%0,%1,%2,%3};"
        : "+f"(c[0]), "+f"(c[1]), "+f"(c[2]), "+f"(c[3])
        : "r"(a[0]), "r"(a[1]), "r"(a[2]), "r"(a[3]), "r"(b0), "r"(b1));
}

#define STG 3
#define CK 64                        // k per chunk (bf16): 128B per row
#define NCH (SS/CK)                  // 16
#define STAGE_BYTES 32768
#define GEMM_DSMEM (STG*STAGE_BYTES) // 98304

__global__ __launch_bounds__(256, 2)
void gemm_bf16_kernel(int asel, int bsel, int cfsel, int chsel, int tri)
{
    extern __shared__ __align__(16) char dsmem[];
    uint32_t sb = s2u(dsmem);
    int tid = threadIdx.x;
    int warp = tid >> 5, lane = tid & 31;

    size_t off = (size_t)blockIdx.z*SS*SS;
    const __nv_bfloat16* Ag = hmatsel(asel) + off;
    const __nv_bfloat16* Bg = hmatsel(bsel) + off;
    float* Cg = matsel(cfsel) + off;
    __nv_bfloat16* Chg = (chsel >= 0) ? hmatsel(chsel) + off : nullptr;

    int bi, bj;
    if (tri) {
        int t = blockIdx.x, i = 0;
        while (t >= 8 - i) { t -= 8 - i; i++; }
        bi = i; bj = i + t;
    } else {
        bi = blockIdx.x >> 3; bj = blockIdx.x & 7;
    }
    int m0 = bi*128, n0 = bj*128;
    bool same = (tri != 0) && (bi == bj) && (asel == bsel);
    uint32_t bBase = same ? 0u : 16384u;

    int wm = (warp >> 2)*64, wn = (warp & 3)*32;
    int rlane = (lane & 7) + ((lane >> 3) & 1)*8;
    int clane = (lane >> 4) & 1;

    float acc[4][4][4];
    #pragma unroll
    for (int i = 0; i < 4; i++)
        #pragma unroll
        for (int j = 0; j < 4; j++) {
            acc[i][j][0]=0; acc[i][j][1]=0; acc[i][j][2]=0; acc[i][j][3]=0;
        }

    auto load_chunk = [&](int c) {
        uint32_t stg = sb + (uint32_t)(c % STG) * STAGE_BYTES;
        int k0 = c * CK;
        #pragma unroll
        for (int it = 0; it < 8; it++) {
            int u = tid + it*256;
            int r = u >> 3;
            int ch = u & 7;
            if (r < 128) {
                const __nv_bfloat16* gsrc = Ag + (size_t)(m0 + r)*SS + k0 + ch*8;
                cp16(stg + SWZ((uint32_t)(r*128 + ch*16)), gsrc);
            } else if (!same) {
                const __nv_bfloat16* gsrc = Bg + (size_t)(n0 + (r-128))*SS + k0 + ch*8;
                cp16(stg + 16384u + SWZ((uint32_t)((r-128)*128 + ch*16)), gsrc);
            }
        }
    };

    for (int c = 0; c < STG-1; c++) { load_chunk(c); cp_commit(); }

    for (int c = 0; c < NCH; c++) {
        int lc = c + STG - 1;
        if (lc < NCH) load_chunk(lc);
        cp_commit();
        CP_WAIT(STG-1);
        __syncthreads();
        uint32_t stg = sb + (uint32_t)(c % STG) * STAGE_BYTES;
        #pragma unroll
        for (int ks = 0; ks < CK/16; ks++) {
            uint32_t af[4][4], bfr[2][4];
            int kch = ks*2 + clane;
            #pragma unroll
            for (int mi = 0; mi < 4; mi++) {
                int r = wm + mi*16 + rlane;
                ldsm4(af[mi], stg + SWZ((uint32_t)(r*128 + kch*16)));
            }
            #pragma unroll
            for (int nt = 0; nt < 2; nt++) {
                int r = wn + nt*16 + rlane;
                ldsm4(bfr[nt], stg + bBase + SWZ((uint32_t)(r*128 + kch*16)));
            }
            #pragma unroll
            for (int mi = 0; mi < 4; mi++)
                #pragma unroll
                for (int nj = 0; nj < 4; nj++) {
                    int nt = nj >> 1, sel = nj & 1;
                    mma_bf16(acc[mi][nj], af[mi], bfr[nt][sel], bfr[nt][sel+2]);
                }
        }
        __syncthreads();
    }

    int rr = lane >> 2, cc2 = (lane & 3)*2;
    #pragma unroll
    for (int mi = 0; mi < 4; mi++) {
        #pragma unroll
        for (int nj = 0; nj < 4; nj++) {
            int row = m0 + wm + mi*16 + rr;
            int col = n0 + wn + nj*8 + cc2;
            float2 v01 = make_float2(acc[mi][nj][0], acc[mi][nj][1]);
            float2 v23 = make_float2(acc[mi][nj][2], acc[mi][nj][3]);
            *(float2*)&Cg[(size_t)row*SS + col]     = v01;
            *(float2*)&Cg[(size_t)(row+8)*SS + col] = v23;
            if (Chg) {
                *(__nv_bfloat162*)&Chg[(size_t)row*SS + col] =
                    __floats2bfloat162_rn(v01.x, v01.y);
                *(__nv_bfloat162*)&Chg[(size_t)(row+8)*SS + col] =
                    __floats2bfloat162_rn(v23.x, v23.y);
            }
        }
    }

    // ---- rowsum epilogue: slot index == cfsel ----
    float* rs = g_rs + (size_t)cfsel*NTOK + (size_t)blockIdx.z*SS;
    #pragma unroll
    for (int mi = 0; mi < 4; mi++) {
        float r0 = 0.f, r1 = 0.f;
        #pragma unroll
        for (int nj = 0; nj < 4; nj++) {
            r0 += acc[mi][nj][0] + acc[mi][nj][1];
            r1 += acc[mi][nj][2] + acc[mi][nj][3];
        }
        r0 += __shfl_xor_sync(0xffffffffu, r0, 1);
        r0 += __shfl_xor_sync(0xffffffffu, r0, 2);
        r1 += __shfl_xor_sync(0xffffffffu, r1, 1);
        r1 += __shfl_xor_sync(0xffffffffu, r1, 2);
        if ((lane & 3) == 0) {
            int row = m0 + wm + mi*16 + rr;
            atomicAdd(&rs[row], r0);
            atomicAdd(&rs[row+8], r1);
        }
    }
    if (tri && bi != bj) {
        // mirrored contribution: column sums of this tile are rowsums of rows n0..
        #pragma unroll
        for (int nj = 0; nj < 4; nj++) {
            float c0 = 0.f, c1 = 0.f;
            #pragma unroll
            for (int mi = 0; mi < 4; mi++) {
                c0 += acc[mi][nj][0] + acc[mi][nj][2];
                c1 += acc[mi][nj][1] + acc[mi][nj][3];
            }
            c0 += __shfl_xor_sync(0xffffffffu, c0, 4);
            c0 += __shfl_xor_sync(0xffffffffu, c0, 8);
            c0 += __shfl_xor_sync(0xffffffffu, c0, 16);
            c1 += __shfl_xor_sync(0xffffffffu, c1, 4);
            c1 += __shfl_xor_sync(0xffffffffu, c1, 8);
            c1 += __shfl_xor_sync(0xffffffffu, c1, 16);
            if (lane < 4) {
                int col = n0 + wn + nj*8 + cc2;
                atomicAdd(&rs[col], c0);
                atomicAdd(&rs[col+1], c1);
            }
        }
    }
}

// ---------------- 6b) mirror lower triangle of two symmetric matrices ----------------
__global__ __launch_bounds__(256) void mirror2_kernel(
    int m0sel, int h0sel, int m1sel, int h1sel)
{
    __shared__ float t[32][33];
    size_t off = (size_t)blockIdx.z*SS*SS;
    int which = blockIdx.y >> 4;
    int msel = which ? m1sel : m0sel;
    int hsel = which ? h1sel : h0sel;
    float* M = matsel(msel) + off;
    __nv_bfloat16* Mh = (hsel >= 0) ? hmatsel(hsel) + off : nullptr;

    int p = blockIdx.x, i = 0;
    while (p >= 7 - i) { p -= 7 - i; i++; }
    int j = i + 1 + p;
    int sub = blockIdx.y & 15;
    int y0 = i*128 + (sub >> 2)*32;
    int x0 = j*128 + (sub & 3)*32;
    int tx = threadIdx.x & 31, ty = threadIdx.x >> 5;
    #pragma unroll
    for (int k = 0; k < 32; k += 8)
        t[ty+k][tx] = M[(size_t)(y0+ty+k)*SS + x0+tx];
    __syncthreads();
    #pragma unroll
    for (int k = 0; k < 32; k += 8) {
        float v = t[tx][ty+k];
        size_t dst = (size_t)(x0+ty+k)*SS + y0+tx;
        M[dst] = v;
        if (Mh) Mh[dst] = __float2bfloat16(v);
    }
}

// ---------------- 8a) fused matrices: single pass, rowsums from g_rs ----------------
__device__ __forceinline__ float fuse1(float a, float b, float c,
                                       float ia, float ib, float ic,
                                       bool unitw, float w0, float w1, float w2, float fb)
{
    float ps = fminf(fmaxf(a*ia, EPSV), 1.f-EPSV);
    float pc = fminf(fmaxf(b*ib, EPSV), 1.f-EPSV);
    float pp = fminf(fmaxf(c*ic, EPSV), 1.f-EPSV);
    if (unitw) {
        float num = ps*pc*pp;
        float den = (1.f-ps+EPSV)*(1.f-pc+EPSV)*(1.f-pp+EPSV);
        return __fdividef(num, num + den);
    }
    float L0 = __logf(__fdividef(ps, 1.f-ps+EPSV));
    float L1 = __logf(__fdividef(pc, 1.f-pc+EPSV));
    float L2 = __logf(__fdividef(pp, 1.f-pp+EPSV));
    float logit = fb + w0*L0 + w1*L1 + w2*L2;
    return __fdividef(1.f, 1.f+__expf(-logit));
}

__global__ __launch_bounds__(256) void fusedmat_kernel(
    const float* __restrict__ fusion_w, const float* __restrict__ fusion_b)
{
    __shared__ float irs_s[16], irs_c[16], irs_p[16];
    int hop = blockIdx.z, b = blockIdx.y, sr0 = blockIdx.x*16;
    int tid = threadIdx.x;
    const float *Ms, *Mc, *Mp;
    if (hop == 0) { Ms = g_A;  Mc = g_P;  Mp = g_Qm; }
    else          { Ms = g_A2; Mc = g_P2; Mp = g_Q2; }
    float w0 = fusion_w[hop*3+0], w1 = fusion_w[hop*3+1], w2 = fusion_w[hop*3+2];
    float fb = fusion_b[hop];
    bool unitw = (w0 == 1.f) && (w1 == 1.f) && (w2 == 1.f) && (fb == 0.f);
    size_t rowbase = (size_t)b*SS + sr0;

    if (tid < 16) {
        if (hop == 0) irs_s[tid] = 1.f/(1.f + EPSV);   // softmax rows sum to 1
        else irs_s[tid] = 1.f/(g_rs[(size_t)3*NTOK + rowbase + tid] + EPSV);
        irs_c[tid] = 1.f/(g_rs[(size_t)(hop ? 4 : 1)*NTOK + rowbase + tid] + EPSV);
        irs_p[tid] = 1.f/(g_rs[(size_t)(hop ? 5 : 2)*NTOK + rowbase + tid] + EPSV);
    }
    __syncthreads();

    int r = tid >> 4, c16 = tid & 15;
    float ia = irs_s[r], ib = irs_c[r], ic = irs_p[r];
    size_t rowoff = (rowbase + r)*SS;
    float* Fr = g_F + (size_t)hop*NB*SS*SS + rowoff;
    float sum = 0.f;
    #pragma unroll
    for (int j = 0; j < 16; j++) {
        int col = c16*4 + j*64;
        float4 ms = *(const float4*)(Ms + rowoff + col);
        float4 mc = *(const float4*)(Mc + rowoff + col);
        float4 mp = *(const float4*)(Mp + rowoff + col);
        float4 f;
        f.x = fuse1(ms.x, mc.x, mp.x, ia, ib, ic, unitw, w0, w1, w2, fb);
        f.y = fuse1(ms.y, mc.y, mp.y, ia, ib, ic, unitw, w0, w1, w2, fb);
        f.z = fuse1(ms.z, mc.z, mp.z, ia, ib, ic, unitw, w0, w1, w2, fb);
        f.w = fuse1(ms.w, mc.w, mp.w, ia, ib, ic, unitw, w0, w1, w2, fb);
        sum += (f.x+f.y) + (f.z+f.w);
        *(float4*)(Fr + col) = f;
    }
    #pragma unroll
    for (int o = 8; o > 0; o >>= 1) sum += __shfl_xor_sync(0xffffffffu, sum, o);
    if (c16 == 0) g_frs[(size_t)hop*NTOK + rowbase + r] = sum;
}

// ---------------- 8b) H[hop] += F @ hopvT^T  (TF32 mma, split-K x4) ----------------
__device__ __forceinline__ float to_tf32(float x) {
    uint32_t u;
    asm("cvt.rna.tf32.f32 %0, %1;" : "=r"(u) : "f"(x));
    return __uint_as_float(u);
}
__device__ __forceinline__ void mma_tf32(float* c,
    uint32_t a0, uint32_t a1, uint32_t a2, uint32_t a3, uint32_t b0, uint32_t b1)
{
    asm volatile(
        "mma.sync.aligned.m16n8k8.row.col.f32.tf32.tf32.f32 "
        "{%0,%1,%2,%3},{%4,%5,%6,%7},{%8,%9},{%0,%1,%2,%3};"
        : "+f"(c[0]), "+f"(c[1]), "+f"(c[2]), "+f"(c[3])
        : "r"(a0), "r"(a1), "r"(a2), "r"(a3), "r"(b0), "r"(b1));
}

#define HKS 4                     // split-K factor
#define HKC (SS/HKS)              // 256 k per block

__global__ __launch_bounds__(256) void hop_gemm_kernel()
{
    __shared__ float As[16][132];   // [k][m]
    __shared__ float Bs[16][68];    // [k][n]
    int tid = threadIdx.x;
    int warp = tid >> 5, lane = tid & 31;
    int hop = blockIdx.z >> 2, kc = blockIdx.z & 3;
    int b = blockIdx.y, m0 = blockIdx.x*128;

    const float* Ag = g_F + (size_t)hop*NB*SS*SS + (size_t)b*SS*SS;
    const float* Bg = g_hopvT + (size_t)(hop*NB + b)*DD*SS;
    float* Hg = g_H + (size_t)hop*NTOK*DD + (size_t)b*SS*DD;

    int wr = warp >> 1, wc = warp & 1;     // 4 x 2 warps, tile 32(m) x 32(n)
    int group = lane >> 2, tig = lane & 3;

    float acc[2][4][4];
    #pragma unroll
    for (int i = 0; i < 2; i++)
        #pragma unroll
        for (int j = 0; j < 4; j++) {
            acc[i][j][0]=0; acc[i][j][1]=0; acc[i][j][2]=0; acc[i][j][3]=0;
        }

    int kk = tid & 15, ms = tid >> 4;      // staging indices
    for (int k0 = kc*HKC; k0 < kc*HKC + HKC; k0 += 16) {
        #pragma unroll
        for (int p = 0; p < 8; p++)
            As[kk][ms + p*16] = to_tf32(Ag[(size_t)(m0 + ms + p*16)*SS + k0 + kk]);
        #pragma unroll
        for (int p = 0; p < 4; p++)
            Bs[kk][ms + p*16] = to_tf32(Bg[(size_t)(ms + p*16)*SS + k0 + kk]);
        __syncthreads();
        #pragma unroll
        for (int ks = 0; ks < 2; ks++) {
            int kb = ks * 8;
            uint32_t af[2][4], bf[4][2];
            #pragma unroll
            for (int mi = 0; mi < 2; mi++) {
                int mb = wr*32 + mi*16 + group;
                af[mi][0] = __float_as_uint(As[kb+tig  ][mb]);
                af[mi][1] = __float_as_uint(As[kb+tig  ][mb+8]);
                af[mi][2] = __float_as_uint(As[kb+tig+4][mb]);
                af[mi][3] = __float_as_uint(As[kb+tig+4][mb+8]);
            }
            #pragma unroll
            for (int nj = 0; nj < 4; nj++) {
                int nb = wc*32 + nj*8 + group;
                bf[nj][0] = __float_as_uint(Bs[kb+tig  ][nb]);
                bf[nj][1] = __float_as_uint(Bs[kb+tig+4][nb]);
            }
            #pragma unroll
            for (int mi = 0; mi < 2; mi++)
                #pragma unroll
                for (int nj = 0; nj < 4; nj++)
                    mma_tf32(acc[mi][nj], af[mi][0], af[mi][1], af[mi][2], af[mi][3],
                             bf[nj][0], bf[nj][1]);
        }
        __syncthreads();
    }

    #pragma unroll
    for (int mi = 0; mi < 2; mi++)
        #pragma unroll
        for (int nj = 0; nj < 4; nj++) {
            int row = m0 + wr*32 + mi*16 + group;
            int col = wc*32 + nj*8 + 2*tig;
            atomicAdd(&Hg[(size_t)row*DD + col],     acc[mi][nj][0]);
            atomicAdd(&Hg[(size_t)row*DD + col + 1], acc[mi][nj][1]);
            atomicAdd(&Hg[(size_t)(row+8)*DD + col],     acc[mi][nj][2]);
            atomicAdd(&Hg[(size_t)(row+8)*DD + col + 1], acc[mi][nj][3]);
        }
}

// ---------------- 9) out = (gate-combined H) @ out_W^T ----------------
__global__ __launch_bounds__(256) void outproj_kernel(
    const float* __restrict__ outW, float* __restrict__ out)
{
    __shared__ float cs[16][65];
    __shared__ float ws[128][65];
    int tb = blockIdx.x * 16;
    int tid = threadIdx.x;
    #pragma unroll
    for (int e = tid; e < 16*64; e += 256) {
        int tl = e >> 6, ee = e & 63;
        int tok = tb + tl;
        float s0 = __fdividef(g_gate[tok*2+0], g_frs[tok] + EPSV);
        float s1 = __fdividef(g_gate[tok*2+1], g_frs[NTOK + tok] + EPSV);
        cs[tl][ee] = s0*g_H[(size_t)tok*DD + ee]
                   + s1*g_H[(size_t)NTOK*DD + (size_t)tok*DD + ee];
    }
    int tk2 = tid >> 5;
    int h4  = tid & 31;
    for (int hc = 0; hc < 4; hc++) {
        __syncthreads();
        #pragma unroll
        for (int e = tid; e < 128*64; e += 256)
            ws[e>>6][e&63] = outW[(size_t)hc*128*DD + e];
        __syncthreads();
        float a0[4] = {0,0,0,0}, a1[4] = {0,0,0,0};
        #pragma unroll 4
        for (int d = 0; d < 64; d++) {
            float c0 = cs[2*tk2][d], c1 = cs[2*tk2+1][d];
            #pragma unroll
            for (int j = 0; j < 4; j++) {
                float w = ws[h4*4 + j][d];
                a0[j] += c0*w; a1[j] += c1*w;
            }
        }
        *(float4*)&out[(size_t)(tb + 2*tk2)*HID + hc*128 + h4*4] =
            make_float4(a0[0], a0[1], a0[2], a0[3]);
        *(float4*)&out[(size_t)(tb + 2*tk2 + 1)*HID + hc*128 + h4*4] =
            make_float4(a1[0], a1[1], a1[2], a1[3]);
    }
}

// ---------------- launch ----------------
extern "C" void kernel_launch(void* const* d_in, const int* in_sizes, int n_in,
                              void* d_out, int out_size)
{
    const float* x      = (const float*)d_in[0];
    const float* Wq     = (const float*)d_in[1];
    const float* Wk     = (const float*)d_in[2];
    const float* Wv     = (const float*)d_in[3];
    const float* btab   = (const float*)d_in[4];
    const float* fw     = (const float*)d_in[5];
    const float* fbias  = (const float*)d_in[6];
    const float* hopW   = (const float*)d_in[7];
    const float* gateW  = (const float*)d_in[8];
    const float* gateb  = (const float*)d_in[9];
    const float* outW   = (const float*)d_in[10];
    const float* temp   = (const float*)d_in[11];
    const int*   relidx = (const int*)d_in[12];
    float* out = (float*)d_out;

    cudaFuncSetAttribute(gemm_bf16_kernel,
                         cudaFuncAttributeMaxDynamicSharedMemorySize, GEMM_DSMEM);

    zero_kernel<<<ZERO_BLOCKS, 256>>>();
    proj_kernel<<<NTOK/TOK_PB, 256>>>(x, Wq, Wk, Wv, gateW);
    rope_kernel<<<(NTOK*32)/256, 256>>>();
    hopv_gate_kernel<<<(NTOK*DD)/256, 256>>>(hopW, gateb);
    scores_kernel<<<dim3(16,16,NB), 256>>>(btab, relidx, temp);
    softmax_kernel<<<NTOK, 256>>>();
    transpose_kernel<<<dim3(32,32,NB), 256>>>();

    // hmat: 0=Ah 1=Th 2=Ph 3=Qmh ; mat: 1=P 2=Qm 3=A2 4=P2 5=Q2
    gemm_bf16_kernel<<<dim3(36,1,NB), 256, GEMM_DSMEM>>>(0,0,1, 2, 1); // P  = Ah Ah^T (tri)
    gemm_bf16_kernel<<<dim3(36,1,NB), 256, GEMM_DSMEM>>>(1,1,2, 3, 1); // Qm = Th Th^T (tri)
    gemm_bf16_kernel<<<dim3(64,1,NB), 256, GEMM_DSMEM>>>(0,1,3,-1, 0); // A2 = Ah Th^T (full)
    mirror2_kernel<<<dim3(28,32,NB), 256>>>(1, 2, 2, 3);               // P(+Ph), Qm(+Qmh)
    gemm_bf16_kernel<<<dim3(36,1,NB), 256, GEMM_DSMEM>>>(2,2,4,-1, 1); // P2 = Ph Ph^T (tri)
    gemm_bf16_kernel<<<dim3(36,1,NB), 256, GEMM_DSMEM>>>(3,3,5,-1, 1); // Q2 = Qmh Qmh^T (tri)
    mirror2_kernel<<<dim3(28,32,NB), 256>>>(4, -1, 5, -1);             // P2, Q2

    fusedmat_kernel<<<dim3(SS/16, NB, 2), 256>>>(fw, fbias);
    hop_gemm_kernel<<<dim3(8, NB, HKS*2), 256>>>();
    outproj_kernel<<<NTOK/16, 256>>>(outW, out);
}

// round 13
// speedup vs baseline: 1.9890x; 1.0694x over previous
#include <cuda_runtime.h>
#include <cuda_bf16.h>
#include <cstdint>

#define NB 8
#define SS 1024
#define DD 64
#define HID 512
#define NTOK (NB*SS)          // 8192
#define EPSV 1e-6f

// ---------------- device scratch (no allocation allowed) ----------------
__device__ float g_Q[NTOK*DD];
__device__ float g_K[NTOK*DD];
__device__ float g_V[NTOK*DD];
__device__ float g_gate[NTOK*2];
__device__ float g_rs[6*NTOK];           // rowsums: slots 1..5 = P,Qm,A2,P2,Q2
__device__ float g_frs[2*NTOK];          // rowsums of fused matrices
__device__ float g_H[2*NTOK*DD];         // hop outputs (pre-norm, atomically accumulated)
__device__ float g_A [(size_t)NB*SS*SS]; // softmax attention
__device__ float g_P [(size_t)NB*SS*SS]; // A A^T
__device__ float g_Qm[(size_t)NB*SS*SS]; // A^T A
__device__ float g_A2[(size_t)NB*SS*SS]; // A A
__device__ float g_P2[(size_t)NB*SS*SS]; // P P
__device__ float g_Q2[(size_t)NB*SS*SS]; // Qm Qm
__device__ float g_F [2*(size_t)NB*SS*SS]; // fused matrices fp32
__device__ float g_hopvT[2*(size_t)NB*DD*SS]; // hopv transposed, k-major, fp32
// bf16 GEMM operands
__device__ __nv_bfloat16 g_Ah [(size_t)NB*SS*SS];
__device__ __nv_bfloat16 g_Th [(size_t)NB*SS*SS];
__device__ __nv_bfloat16 g_Ph [(size_t)NB*SS*SS];
__device__ __nv_bfloat16 g_Qmh[(size_t)NB*SS*SS];

__device__ __forceinline__ float* matsel(int s) {
    switch (s) {
        case 0: return g_A;
        case 1: return g_P;
        case 2: return g_Qm;
        case 3: return g_A2;
        case 4: return g_P2;
        default: return g_Q2;
    }
}
__device__ __forceinline__ __nv_bfloat16* hmatsel(int s) {
    switch (s) {
        case 0: return g_Ah;
        case 1: return g_Th;
        case 2: return g_Ph;
        default: return g_Qmh;
    }
}

__device__ __forceinline__ float warp_max(float v) {
    #pragma unroll
    for (int o = 16; o > 0; o >>= 1) v = fmaxf(v, __shfl_xor_sync(0xffffffffu, v, o));
    return v;
}
__device__ __forceinline__ float warp_sum(float v) {
    #pragma unroll
    for (int o = 16; o > 0; o >>= 1) v += __shfl_xor_sync(0xffffffffu, v, o);
    return v;
}

// ---------------- 0) zero g_rs + g_H ----------------
__global__ void zero_kernel()
{
    int gid = blockIdx.x*256 + threadIdx.x;   // float4 index
    if (gid < 6*NTOK/4)
        ((float4*)g_rs)[gid] = make_float4(0.f,0.f,0.f,0.f);
    else
        ((float4*)g_H)[gid - 6*NTOK/4] = make_float4(0.f,0.f,0.f,0.f);
}
#define ZERO_BLOCKS ((6*NTOK/4 + 2*NTOK*DD/4 + 255)/256)

// ---------------- 1) QKV + gate-logit projection ----------------
#define TOK_PB 16
__global__ __launch_bounds__(256) void proj_kernel(
    const float* __restrict__ x, const float* __restrict__ Wq,
    const float* __restrict__ Wk, const float* __restrict__ Wv,
    const float* __restrict__ gW)
{
    __shared__ float xs[TOK_PB*HID];
    int tb = blockIdx.x * TOK_PB;
    int tid = threadIdx.x;
    const float4* xg = (const float4*)(x + (size_t)tb*HID);
    float4* xs4 = (float4*)xs;
    #pragma unroll
    for (int i = tid; i < TOK_PB*HID/4; i += 256) xs4[i] = xg[i];
    __syncthreads();

    for (int o = tid; o < TOK_PB*194; o += 256) {
        int tok = o / 194, ch = o % 194;
        const float* w;
        if (ch < 64)       w = Wq + ch*HID;
        else if (ch < 128) w = Wk + (ch-64)*HID;
        else if (ch < 192) w = Wv + (ch-128)*HID;
        else               w = gW + (ch-192)*HID;
        const float4* w4  = (const float4*)w;
        const float4* xv4 = (const float4*)(xs + tok*HID);
        float acc = 0.f;
        #pragma unroll 8
        for (int k = 0; k < HID/4; k++) {
            float4 a = xv4[k];
            float4 b = __ldg(&w4[k]);
            acc += a.x*b.x + a.y*b.y + a.z*b.z + a.w*b.w;
        }
        size_t gt = tb + tok;
        if (ch < 64)       g_Q[gt*DD + ch]        = acc;
        else if (ch < 128) g_K[gt*DD + (ch-64)]   = acc;
        else if (ch < 192) g_V[gt*DD + (ch-128)]  = acc;
        else               g_gate[gt*2 + (ch-192)] = acc;
    }
}

// ---------------- 2) RoPE in place on Q,K ----------------
__global__ void rope_kernel()
{
    int gid = blockIdx.x*256 + threadIdx.x;
    if (gid >= NTOK*32) return;
    int tok = gid >> 5, j = gid & 31;
    int s = tok & (SS-1);
    float invf = (float)exp(-log(10000.0) * (double)j / 32.0);
    float ang = (float)s * invf;
    float sn, cs;
    sincosf(ang, &sn, &cs);
    size_t base = (size_t)tok * DD;
    float q0 = g_Q[base+j], q1 = g_Q[base+j+32];
    g_Q[base+j]    = q0*cs - q1*sn;
    g_Q[base+j+32] = q1*cs + q0*sn;
    float k0 = g_K[base+j], k1 = g_K[base+j+32];
    g_K[base+j]    = k0*cs - k1*sn;
    g_K[base+j+32] = k1*cs + k0*sn;
}

// ---------------- 3) hopvT (coalesced, smem-tiled) ; gate softmax ----------------
__global__ __launch_bounds__(256) void hopv_gate_kernel(
    const float* __restrict__ hopW, const float* __restrict__ gateb)
{
    __shared__ float vs[64][65];
    int t0tok = blockIdx.x * 64;              // 128 blocks
    int b = t0tok >> 10, s0 = t0tok & (SS-1);
    int tid = threadIdx.x;

    // coalesced load of the 64x64 V tile
    #pragma unroll
    for (int i = tid; i < 64*16; i += 256) {   // float4 granules
        int tokL = i >> 4;
        int d4 = (i & 15) * 4;
        float4 v = *(const float4*)(g_V + (size_t)(t0tok + tokL)*DD + d4);
        vs[tokL][d4] = v.x; vs[tokL][d4+1] = v.y;
        vs[tokL][d4+2] = v.z; vs[tokL][d4+3] = v.w;
    }
    __syncthreads();

    int tokL = tid & 63;                       // lanes -> consecutive tokens
    int e0 = tid >> 6;                         // 0..3
    int s = s0 + tokL;
    #pragma unroll 4
    for (int e = e0; e < DD; e += 4) {
        const float* w0 = hopW + e*DD;
        const float* w1 = hopW + DD*DD + e*DD;
        float a0 = 0.f, a1 = 0.f;
        #pragma unroll
        for (int d = 0; d < DD; d++) {
            float v = vs[tokL][d];             // conflict-free (stride 65)
            a0 += v * __ldg(&w0[d]);           // uniform across warp
            a1 += v * __ldg(&w1[d]);
        }
        g_hopvT[((size_t)b*DD + e)*SS + s] = a0;              // coalesced
        g_hopvT[((size_t)(NB + b)*DD + e)*SS + s] = a1;
    }

    if (tid < 64) {
        int tok = t0tok + tid;
        float l0 = g_gate[tok*2]   + __ldg(&gateb[0]);
        float l1 = g_gate[tok*2+1] + __ldg(&gateb[1]);
        float m = fmaxf(l0, l1);
        float e0v = __expf(l0-m), e1v = __expf(l1-m);
        float inv = 1.f/(e0v+e1v);
        g_gate[tok*2]   = e0v*inv;
        g_gate[tok*2+1] = e1v*inv;
    }
}

// ---------------- 4) scores ----------------
__global__ __launch_bounds__(256) void scores_kernel(
    const float* __restrict__ bias_table, const int* __restrict__ rel_idx,
    const float* __restrict__ temperature)
{
    __shared__ float qs[64][65];
    __shared__ float ks[64][65];
    int b = blockIdx.z;
    int s0 = blockIdx.y * 64, t0 = blockIdx.x * 64;
    int tid = threadIdx.x;
    const float* Qb = g_Q + ((size_t)b*SS + s0)*DD;
    const float* Kb = g_K + ((size_t)b*SS + t0)*DD;
    #pragma unroll
    for (int e = tid; e < 64*64; e += 256) {
        qs[e>>6][e&63] = Qb[e];
        ks[e>>6][e&63] = Kb[e];
    }
    __syncthreads();
    int ty = tid >> 4, tx = tid & 15;
    float c[4][4];
    #pragma unroll
    for (int i=0;i<4;i++) { c[i][0]=0;c[i][1]=0;c[i][2]=0;c[i][3]=0; }
    #pragma unroll 4
    for (int d = 0; d < 64; d++) {
        float rq[4], rk[4];
        #pragma unroll
        for (int i=0;i<4;i++) { rq[i] = qs[ty*4+i][d]; rk[i] = ks[tx*4+i][d]; }
        #pragma unroll
        for (int i=0;i<4;i++)
            #pragma unroll
            for (int j=0;j<4;j++) c[i][j] += rq[i]*rk[j];
    }
    float inv_t = 1.f / fmaxf(temperature[0], 0.1f);
    const float scale = 0.125f;
    float* Ab = g_A + (size_t)b*SS*SS;
    #pragma unroll
    for (int i = 0; i < 4; i++) {
        int s = s0 + ty*4 + i;
        int4 idx = *(const int4*)(rel_idx + (size_t)s*SS + t0 + tx*4);
        float4 out;
        out.x = (c[i][0]*scale + __ldg(&bias_table[idx.x])) * inv_t;
        out.y = (c[i][1]*scale + __ldg(&bias_table[idx.y])) * inv_t;
        out.z = (c[i][2]*scale + __ldg(&bias_table[idx.z])) * inv_t;
        out.w = (c[i][3]*scale + __ldg(&bias_table[idx.w])) * inv_t;
        *(float4*)(Ab + (size_t)s*SS + t0 + tx*4) = out;
    }
}

// ---------------- 5) row softmax in place on g_A (+ bf16 copy) ----------------
__global__ __launch_bounds__(256) void softmax_kernel()
{
    size_t row = blockIdx.x;
    float* Ar = g_A + row*SS;
    __nv_bfloat16* Ah = g_Ah + row*SS;
    int tid = threadIdx.x;
    int wid = tid >> 5, lane = tid & 31;
    __shared__ float sm[8];
    float4 v = ((float4*)Ar)[tid];
    float m = fmaxf(fmaxf(v.x, v.y), fmaxf(v.z, v.w));
    m = warp_max(m);
    if (lane == 0) sm[wid] = m;
    __syncthreads();
    if (wid == 0) {
        float t = (lane < 8) ? sm[lane] : -3.4e38f;
        t = warp_max(t);
        if (lane == 0) sm[0] = t;
    }
    __syncthreads();
    m = sm[0];
    __syncthreads();
    float e0 = __expf(v.x-m), e1 = __expf(v.y-m), e2 = __expf(v.z-m), e3 = __expf(v.w-m);
    float s = e0+e1+e2+e3;
    s = warp_sum(s);
    if (lane == 0) sm[wid] = s;
    __syncthreads();
    if (wid == 0) {
        float t = (lane < 8) ? sm[lane] : 0.f;
        t = warp_sum(t);
        if (lane == 0) sm[0] = t;
    }
    __syncthreads();
    float inv = 1.f / sm[0];
    float4 o = make_float4(e0*inv, e1*inv, e2*inv, e3*inv);
    ((float4*)Ar)[tid] = o;
    __nv_bfloat162 h0 = __floats2bfloat162_rn(o.x, o.y);
    __nv_bfloat162 h1 = __floats2bfloat162_rn(o.z, o.w);
    ((__nv_bfloat162*)Ah)[tid*2]   = h0;
    ((__nv_bfloat162*)Ah)[tid*2+1] = h1;
}

// ---------------- 5b) transpose: g_Th = (g_Ah)^T per batch (bf16 in/out) ----------------
__global__ __launch_bounds__(256) void transpose_kernel()
{
    __shared__ __nv_bfloat16 t[32][34];
    int b = blockIdx.z;
    int x0 = blockIdx.x*32, y0 = blockIdx.y*32;
    const __nv_bfloat16* Ab = g_Ah + (size_t)b*SS*SS;
    __nv_bfloat16* Tb = g_Th + (size_t)b*SS*SS;
    int tx = threadIdx.x & 31, ty = threadIdx.x >> 5;   // 32 x 8
    #pragma unroll
    for (int i = 0; i < 32; i += 8)
        t[ty+i][tx] = Ab[(size_t)(y0+ty+i)*SS + x0+tx];
    __syncthreads();
    #pragma unroll
    for (int i = 0; i < 32; i += 8)
        Tb[(size_t)(x0+ty+i)*SS + y0+tx] = t[tx][ty+i];
}

// ================= bf16 mma.sync batched NT GEMM (+rowsum epilogue) =================
__device__ __forceinline__ uint32_t s2u(const void* p) {
    uint32_t a;
    asm("{ .reg .u64 t; cvta.to.shared.u64 t, %1; cvt.u32.u64 %0, t; }" : "=r"(a) : "l"(p));
    return a;
}
#define SWZ(o) ((o) ^ (((o)>>3)&0x70))

__device__ __forceinline__ void cp16(uint32_t dst, const void* src) {
    asm volatile("cp.async.cg.shared.global [%0], [%1], 16;" :: "r"(dst), "l"(src));
}
__device__ __forceinline__ void cp_commit() { asm volatile("cp.async.commit_group;" ::: "memory"); }
#define CP_WAIT(n) asm volatile("cp.async.wait_group %0;" :: "n"(n) : "memory")

__device__ __forceinline__ void ldsm4(uint32_t* r, uint32_t addr) {
    asm volatile("ldmatrix.sync.aligned.m8n8.x4.shared.b16 {%0,%1,%2,%3}, [%4];"
        : "=r"(r[0]), "=r"(r[1]), "=r"(r[2]), "=r"(r[3]) : "r"(addr));
}
__device__ __forceinline__ void mma_bf16(float* c, const uint32_t* a,
                                         uint32_t b0, uint32_t b1) {
    asm volatile(
        "mma.sync.aligned.m16n8k16.row.col.f32.bf16.bf16.f32 "
        "{%0,%1,%2,%3},{%4,%5,%6,%7},{%8,%9},{%0,%1,%2,%3};"
        : "+f"(c[0]), "+f"(c[1]), "+f"(c[2]), "+f"(c[3])
        : "r"(a[0]), "r"(a[1]), "r"(a[2]), "r"(a[3]), "r"(b0), "r"(b1));
}

#define STG 3
#define CK 64                        // k per chunk (bf16): 128B per row
#define NCH (SS/CK)                  // 16
#define STAGE_BYTES 32768
#define GEMM_DSMEM (STG*STAGE_BYTES) // 98304

__global__ __launch_bounds__(256, 2)
void gemm_bf16_kernel(int asel, int bsel, int cfsel, int chsel, int tri)
{
    extern __shared__ __align__(16) char dsmem[];
    uint32_t sb = s2u(dsmem);
    int tid = threadIdx.x;
    int warp = tid >> 5, lane = tid & 31;

    size_t off = (size_t)blockIdx.z*SS*SS;
    const __nv_bfloat16* Ag = hmatsel(asel) + off;
    const __nv_bfloat16* Bg = hmatsel(bsel) + off;
    float* Cg = matsel(cfsel) + off;
    __nv_bfloat16* Chg = (chsel >= 0) ? hmatsel(chsel) + off : nullptr;

    int bi, bj;
    if (tri) {
        int t = blockIdx.x, i = 0;
        while (t >= 8 - i) { t -= 8 - i; i++; }
        bi = i; bj = i + t;
    } else {
        bi = blockIdx.x >> 3; bj = blockIdx.x & 7;
    }
    int m0 = bi*128, n0 = bj*128;
    bool same = (tri != 0) && (bi == bj) && (asel == bsel);
    uint32_t bBase = same ? 0u : 16384u;

    int wm = (warp >> 2)*64, wn = (warp & 3)*32;
    int rlane = (lane & 7) + ((lane >> 3) & 1)*8;
    int clane = (lane >> 4) & 1;

    float acc[4][4][4];
    #pragma unroll
    for (int i = 0; i < 4; i++)
        #pragma unroll
        for (int j = 0; j < 4; j++) {
            acc[i][j][0]=0; acc[i][j][1]=0; acc[i][j][2]=0; acc[i][j][3]=0;
        }

    auto load_chunk = [&](int c) {
        uint32_t stg = sb + (uint32_t)(c % STG) * STAGE_BYTES;
        int k0 = c * CK;
        #pragma unroll
        for (int it = 0; it < 8; it++) {
            int u = tid + it*256;
            int r = u >> 3;
            int ch = u & 7;
            if (r < 128) {
                const __nv_bfloat16* gsrc = Ag + (size_t)(m0 + r)*SS + k0 + ch*8;
                cp16(stg + SWZ((uint32_t)(r*128 + ch*16)), gsrc);
            } else if (!same) {
                const __nv_bfloat16* gsrc = Bg + (size_t)(n0 + (r-128))*SS + k0 + ch*8;
                cp16(stg + 16384u + SWZ((uint32_t)((r-128)*128 + ch*16)), gsrc);
            }
        }
    };

    for (int c = 0; c < STG-1; c++) { load_chunk(c); cp_commit(); }

    for (int c = 0; c < NCH; c++) {
        int lc = c + STG - 1;
        if (lc < NCH) load_chunk(lc);
        cp_commit();
        CP_WAIT(STG-1);
        __syncthreads();
        uint32_t stg = sb + (uint32_t)(c % STG) * STAGE_BYTES;
        #pragma unroll
        for (int ks = 0; ks < CK/16; ks++) {
            uint32_t af[4][4], bfr[2][4];
            int kch = ks*2 + clane;
            #pragma unroll
            for (int mi = 0; mi < 4; mi++) {
                int r = wm + mi*16 + rlane;
                ldsm4(af[mi], stg + SWZ((uint32_t)(r*128 + kch*16)));
            }
            #pragma unroll
            for (int nt = 0; nt < 2; nt++) {
                int r = wn + nt*16 + rlane;
                ldsm4(bfr[nt], stg + bBase + SWZ((uint32_t)(r*128 + kch*16)));
            }
            #pragma unroll
            for (int mi = 0; mi < 4; mi++)
                #pragma unroll
                for (int nj = 0; nj < 4; nj++) {
                    int nt = nj >> 1, sel = nj & 1;
                    mma_bf16(acc[mi][nj], af[mi], bfr[nt][sel], bfr[nt][sel+2]);
                }
        }
        __syncthreads();
    }

    int rr = lane >> 2, cc2 = (lane & 3)*2;
    #pragma unroll
    for (int mi = 0; mi < 4; mi++) {
        #pragma unroll
        for (int nj = 0; nj < 4; nj++) {
            int row = m0 + wm + mi*16 + rr;
            int col = n0 + wn + nj*8 + cc2;
            float2 v01 = make_float2(acc[mi][nj][0], acc[mi][nj][1]);
            float2 v23 = make_float2(acc[mi][nj][2], acc[mi][nj][3]);
            *(float2*)&Cg[(size_t)row*SS + col]     = v01;
            *(float2*)&Cg[(size_t)(row+8)*SS + col] = v23;
            if (Chg) {
                *(__nv_bfloat162*)&Chg[(size_t)row*SS + col] =
                    __floats2bfloat162_rn(v01.x, v01.y);
                *(__nv_bfloat162*)&Chg[(size_t)(row+8)*SS + col] =
                    __floats2bfloat162_rn(v23.x, v23.y);
            }
        }
    }

    // ---- rowsum epilogue: slot index == cfsel ----
    float* rs = g_rs + (size_t)cfsel*NTOK + (size_t)blockIdx.z*SS;
    #pragma unroll
    for (int mi = 0; mi < 4; mi++) {
        float r0 = 0.f, r1 = 0.f;
        #pragma unroll
        for (int nj = 0; nj < 4; nj++) {
            r0 += acc[mi][nj][0] + acc[mi][nj][1];
            r1 += acc[mi][nj][2] + acc[mi][nj][3];
        }
        r0 += __shfl_xor_sync(0xffffffffu, r0, 1);
        r0 += __shfl_xor_sync(0xffffffffu, r0, 2);
        r1 += __shfl_xor_sync(0xffffffffu, r1, 1);
        r1 += __shfl_xor_sync(0xffffffffu, r1, 2);
        if ((lane & 3) == 0) {
            int row = m0 + wm + mi*16 + rr;
            atomicAdd(&rs[row], r0);
            atomicAdd(&rs[row+8], r1);
        }
    }
    if (tri && bi != bj) {
        #pragma unroll
        for (int nj = 0; nj < 4; nj++) {
            float c0 = 0.f, c1 = 0.f;
            #pragma unroll
            for (int mi = 0; mi < 4; mi++) {
                c0 += acc[mi][nj][0] + acc[mi][nj][2];
                c1 += acc[mi][nj][1] + acc[mi][nj][3];
            }
            c0 += __shfl_xor_sync(0xffffffffu, c0, 4);
            c0 += __shfl_xor_sync(0xffffffffu, c0, 8);
            c0 += __shfl_xor_sync(0xffffffffu, c0, 16);
            c1 += __shfl_xor_sync(0xffffffffu, c1, 4);
            c1 += __shfl_xor_sync(0xffffffffu, c1, 8);
            c1 += __shfl_xor_sync(0xffffffffu, c1, 16);
            if (lane < 4) {
                int col = n0 + wn + nj*8 + cc2;
                atomicAdd(&rs[col], c0);
                atomicAdd(&rs[col+1], c1);
            }
        }
    }
}

// ---------------- 6b) mirror lower triangle of two symmetric matrices ----------------
__global__ __launch_bounds__(256) void mirror2_kernel(
    int m0sel, int h0sel, int m1sel, int h1sel)
{
    __shared__ float t[32][33];
    size_t off = (size_t)blockIdx.z*SS*SS;
    int which = blockIdx.y >> 4;
    int msel = which ? m1sel : m0sel;
    int hsel = which ? h1sel : h0sel;
    float* M = matsel(msel) + off;
    __nv_bfloat16* Mh = (hsel >= 0) ? hmatsel(hsel) + off : nullptr;

    int p = blockIdx.x, i = 0;
    while (p >= 7 - i) { p -= 7 - i; i++; }
    int j = i + 1 + p;
    int sub = blockIdx.y & 15;
    int y0 = i*128 + (sub >> 2)*32;
    int x0 = j*128 + (sub & 3)*32;
    int tx = threadIdx.x & 31, ty = threadIdx.x >> 5;
    #pragma unroll
    for (int k = 0; k < 32; k += 8)
        t[ty+k][tx] = M[(size_t)(y0+ty+k)*SS + x0+tx];
    __syncthreads();
    #pragma unroll
    for (int k = 0; k < 32; k += 8) {
        float v = t[tx][ty+k];
        size_t dst = (size_t)(x0+ty+k)*SS + y0+tx;
        M[dst] = v;
        if (Mh) Mh[dst] = __float2bfloat16(v);
    }
}

// ---------------- 8a) fused matrices: single pass, rowsums from g_rs ----------------
__device__ __forceinline__ float fuse1(float a, float b, float c,
                                       float ia, float ib, float ic,
                                       bool unitw, float w0, float w1, float w2, float fb)
{
    float ps = fminf(fmaxf(a*ia, EPSV), 1.f-EPSV);
    float pc = fminf(fmaxf(b*ib, EPSV), 1.f-EPSV);
    float pp = fminf(fmaxf(c*ic, EPSV), 1.f-EPSV);
    if (unitw) {
        float num = ps*pc*pp;
        float den = (1.f-ps+EPSV)*(1.f-pc+EPSV)*(1.f-pp+EPSV);
        return __fdividef(num, num + den);
    }
    float L0 = __logf(__fdividef(ps, 1.f-ps+EPSV));
    float L1 = __logf(__fdividef(pc, 1.f-pc+EPSV));
    float L2 = __logf(__fdividef(pp, 1.f-pp+EPSV));
    float logit = fb + w0*L0 + w1*L1 + w2*L2;
    return __fdividef(1.f, 1.f+__expf(-logit));
}

__global__ __launch_bounds__(256) void fusedmat_kernel(
    const float* __restrict__ fusion_w, const float* __restrict__ fusion_b)
{
    __shared__ float irs_s[16], irs_c[16], irs_p[16];
    int hop = blockIdx.z, b = blockIdx.y, sr0 = blockIdx.x*16;
    int tid = threadIdx.x;
    const float *Ms, *Mc, *Mp;
    if (hop == 0) { Ms = g_A;  Mc = g_P;  Mp = g_Qm; }
    else          { Ms = g_A2; Mc = g_P2; Mp = g_Q2; }
    float w0 = fusion_w[hop*3+0], w1 = fusion_w[hop*3+1], w2 = fusion_w[hop*3+2];
    float fb = fusion_b[hop];
    bool unitw = (w0 == 1.f) && (w1 == 1.f) && (w2 == 1.f) && (fb == 0.f);
    size_t rowbase = (size_t)b*SS + sr0;

    if (tid < 16) {
        if (hop == 0) irs_s[tid] = 1.f/(1.f + EPSV);   // softmax rows sum to 1
        else irs_s[tid] = 1.f/(g_rs[(size_t)3*NTOK + rowbase + tid] + EPSV);
        irs_c[tid] = 1.f/(g_rs[(size_t)(hop ? 4 : 1)*NTOK + rowbase + tid] + EPSV);
        irs_p[tid] = 1.f/(g_rs[(size_t)(hop ? 5 : 2)*NTOK + rowbase + tid] + EPSV);
    }
    __syncthreads();

    int r = tid >> 4, c16 = tid & 15;
    float ia = irs_s[r], ib = irs_c[r], ic = irs_p[r];
    size_t rowoff = (rowbase + r)*SS;
    float* Fr = g_F + (size_t)hop*NB*SS*SS + rowoff;
    float sum = 0.f;
    #pragma unroll
    for (int j = 0; j < 16; j++) {
        int col = c16*4 + j*64;
        float4 ms = *(const float4*)(Ms + rowoff + col);
        float4 mc = *(const float4*)(Mc + rowoff + col);
        float4 mp = *(const float4*)(Mp + rowoff + col);
        float4 f;
        f.x = fuse1(ms.x, mc.x, mp.x, ia, ib, ic, unitw, w0, w1, w2, fb);
        f.y = fuse1(ms.y, mc.y, mp.y, ia, ib, ic, unitw, w0, w1, w2, fb);
        f.z = fuse1(ms.z, mc.z, mp.z, ia, ib, ic, unitw, w0, w1, w2, fb);
        f.w = fuse1(ms.w, mc.w, mp.w, ia, ib, ic, unitw, w0, w1, w2, fb);
        sum += (f.x+f.y) + (f.z+f.w);
        *(float4*)(Fr + col) = f;
    }
    #pragma unroll
    for (int o = 8; o > 0; o >>= 1) sum += __shfl_xor_sync(0xffffffffu, sum, o);
    if (c16 == 0) g_frs[(size_t)hop*NTOK + rowbase + r] = sum;
}

// ---------------- 8b) H[hop] += F @ hopvT^T  (TF32 mma, split-K x4) ----------------
__device__ __forceinline__ float to_tf32(float x) {
    uint32_t u;
    asm("cvt.rna.tf32.f32 %0, %1;" : "=r"(u) : "f"(x));
    return __uint_as_float(u);
}
__device__ __forceinline__ void mma_tf32(float* c,
    uint32_t a0, uint32_t a1, uint32_t a2, uint32_t a3, uint32_t b0, uint32_t b1)
{
    asm volatile(
        "mma.sync.aligned.m16n8k8.row.col.f32.tf32.tf32.f32 "
        "{%0,%1,%2,%3},{%4,%5,%6,%7},{%8,%9},{%0,%1,%2,%3};"
        : "+f"(c[0]), "+f"(c[1]), "+f"(c[2]), "+f"(c[3])
        : "r"(a0), "r"(a1), "r"(a2), "r"(a3), "r"(b0), "r"(b1));
}

#define HKS 4                     // split-K factor
#define HKC (SS/HKS)              // 256 k per block

__global__ __launch_bounds__(256) void hop_gemm_kernel()
{
    __shared__ float As[16][132];   // [k][m]
    __shared__ float Bs[16][68];    // [k][n]
    int tid = threadIdx.x;
    int warp = tid >> 5, lane = tid & 31;
    int hop = blockIdx.z >> 2, kc = blockIdx.z & 3;
    int b = blockIdx.y, m0 = blockIdx.x*128;

    const float* Ag = g_F + (size_t)hop*NB*SS*SS + (size_t)b*SS*SS;
    const float* Bg = g_hopvT + (size_t)(hop*NB + b)*DD*SS;
    float* Hg = g_H + (size_t)hop*NTOK*DD + (size_t)b*SS*DD;

    int wr = warp >> 1, wc = warp & 1;     // 4 x 2 warps, tile 32(m) x 32(n)
    int group = lane >> 2, tig = lane & 3;

    float acc[2][4][4];
    #pragma unroll
    for (int i = 0; i < 2; i++)
        #pragma unroll
        for (int j = 0; j < 4; j++) {
            acc[i][j][0]=0; acc[i][j][1]=0; acc[i][j][2]=0; acc[i][j][3]=0;
        }

    int kk = tid & 15, ms = tid >> 4;      // staging indices
    for (int k0 = kc*HKC; k0 < kc*HKC + HKC; k0 += 16) {
        #pragma unroll
        for (int p = 0; p < 8; p++)
            As[kk][ms + p*16] = to_tf32(Ag[(size_t)(m0 + ms + p*16)*SS + k0 + kk]);
        #pragma unroll
        for (int p = 0; p < 4; p++)
            Bs[kk][ms + p*16] = to_tf32(Bg[(size_t)(ms + p*16)*SS + k0 + kk]);
        __syncthreads();
        #pragma unroll
        for (int ks = 0; ks < 2; ks++) {
            int kb = ks * 8;
            uint32_t af[2][4], bf[4][2];
            #pragma unroll
            for (int mi = 0; mi < 2; mi++) {
                int mb = wr*32 + mi*16 + group;
                af[mi][0] = __float_as_uint(As[kb+tig  ][mb]);
                af[mi][1] = __float_as_uint(As[kb+tig  ][mb+8]);
                af[mi][2] = __float_as_uint(As[kb+tig+4][mb]);
                af[mi][3] = __float_as_uint(As[kb+tig+4][mb+8]);
            }
            #pragma unroll
            for (int nj = 0; nj < 4; nj++) {
                int nb = wc*32 + nj*8 + group;
                bf[nj][0] = __float_as_uint(Bs[kb+tig  ][nb]);
                bf[nj][1] = __float_as_uint(Bs[kb+tig+4][nb]);
            }
            #pragma unroll
            for (int mi = 0; mi < 2; mi++)
                #pragma unroll
                for (int nj = 0; nj < 4; nj++)
                    mma_tf32(acc[mi][nj], af[mi][0], af[mi][1], af[mi][2], af[mi][3],
                             bf[nj][0], bf[nj][1]);
        }
        __syncthreads();
    }

    #pragma unroll
    for (int mi = 0; mi < 2; mi++)
        #pragma unroll
        for (int nj = 0; nj < 4; nj++) {
            int row = m0 + wr*32 + mi*16 + group;
            int col = wc*32 + nj*8 + 2*tig;
            atomicAdd(&Hg[(size_t)row*DD + col],     acc[mi][nj][0]);
            atomicAdd(&Hg[(size_t)row*DD + col + 1], acc[mi][nj][1]);
            atomicAdd(&Hg[(size_t)(row+8)*DD + col],     acc[mi][nj][2]);
            atomicAdd(&Hg[(size_t)(row+8)*DD + col + 1], acc[mi][nj][3]);
        }
}

// ---------------- 9) out = (gate-combined H) @ out_W^T ----------------
__global__ __launch_bounds__(256) void outproj_kernel(
    const float* __restrict__ outW, float* __restrict__ out)
{
    __shared__ float cs[16][65];
    __shared__ float ws[128][65];
    int tb = blockIdx.x * 16;
    int tid = threadIdx.x;
    #pragma unroll
    for (int e = tid; e < 16*64; e += 256) {
        int tl = e >> 6, ee = e & 63;
        int tok = tb + tl;
        float s0 = __fdividef(g_gate[tok*2+0], g_frs[tok] + EPSV);
        float s1 = __fdividef(g_gate[tok*2+1], g_frs[NTOK + tok] + EPSV);
        cs[tl][ee] = s0*g_H[(size_t)tok*DD + ee]
                   + s1*g_H[(size_t)NTOK*DD + (size_t)tok*DD + ee];
    }
    int tk2 = tid >> 5;
    int h4  = tid & 31;
    for (int hc = 0; hc < 4; hc++) {
        __syncthreads();
        #pragma unroll
        for (int e = tid; e < 128*64; e += 256)
            ws[e>>6][e&63] = outW[(size_t)hc*128*DD + e];
        __syncthreads();
        float a0[4] = {0,0,0,0}, a1[4] = {0,0,0,0};
        #pragma unroll 4
        for (int d = 0; d < 64; d++) {
            float c0 = cs[2*tk2][d], c1 = cs[2*tk2+1][d];
            #pragma unroll
            for (int j = 0; j < 4; j++) {
                float w = ws[h4*4 + j][d];
                a0[j] += c0*w; a1[j] += c1*w;
            }
        }
        *(float4*)&out[(size_t)(tb + 2*tk2)*HID + hc*128 + h4*4] =
            make_float4(a0[0], a0[1], a0[2], a0[3]);
        *(float4*)&out[(size_t)(tb + 2*tk2 + 1)*HID + hc*128 + h4*4] =
            make_float4(a1[0], a1[1], a1[2], a1[3]);
    }
}

// ---------------- launch ----------------
extern "C" void kernel_launch(void* const* d_in, const int* in_sizes, int n_in,
                              void* d_out, int out_size)
{
    const float* x      = (const float*)d_in[0];
    const float* Wq     = (const float*)d_in[1];
    const float* Wk     = (const float*)d_in[2];
    const float* Wv     = (const float*)d_in[3];
    const float* btab   = (const float*)d_in[4];
    const float* fw     = (const float*)d_in[5];
    const float* fbias  = (const float*)d_in[6];
    const float* hopW   = (const float*)d_in[7];
    const float* gateW  = (const float*)d_in[8];
    const float* gateb  = (const float*)d_in[9];
    const float* outW   = (const float*)d_in[10];
    const float* temp   = (const float*)d_in[11];
    const int*   relidx = (const int*)d_in[12];
    float* out = (float*)d_out;

    cudaFuncSetAttribute(gemm_bf16_kernel,
                         cudaFuncAttributeMaxDynamicSharedMemorySize, GEMM_DSMEM);

    zero_kernel<<<ZERO_BLOCKS, 256>>>();
    proj_kernel<<<NTOK/TOK_PB, 256>>>(x, Wq, Wk, Wv, gateW);
    rope_kernel<<<(NTOK*32)/256, 256>>>();
    hopv_gate_kernel<<<NTOK/64, 256>>>(hopW, gateb);
    scores_kernel<<<dim3(16,16,NB), 256>>>(btab, relidx, temp);
    softmax_kernel<<<NTOK, 256>>>();
    transpose_kernel<<<dim3(32,32,NB), 256>>>();

    // hmat: 0=Ah 1=Th 2=Ph 3=Qmh ; mat: 1=P 2=Qm 3=A2 4=P2 5=Q2
    gemm_bf16_kernel<<<dim3(36,1,NB), 256, GEMM_DSMEM>>>(0,0,1, 2, 1); // P  = Ah Ah^T (tri)
    gemm_bf16_kernel<<<dim3(36,1,NB), 256, GEMM_DSMEM>>>(1,1,2, 3, 1); // Qm = Th Th^T (tri)
    gemm_bf16_kernel<<<dim3(64,1,NB), 256, GEMM_DSMEM>>>(0,1,3,-1, 0); // A2 = Ah Th^T (full)
    mirror2_kernel<<<dim3(28,32,NB), 256>>>(1, 2, 2, 3);               // P(+Ph), Qm(+Qmh)
    gemm_bf16_kernel<<<dim3(36,1,NB), 256, GEMM_DSMEM>>>(2,2,4,-1, 1); // P2 = Ph Ph^T (tri)
    gemm_bf16_kernel<<<dim3(36,1,NB), 256, GEMM_DSMEM>>>(3,3,5,-1, 1); // Q2 = Qmh Qmh^T (tri)
    mirror2_kernel<<<dim3(28,32,NB), 256>>>(4, -1, 5, -1);             // P2, Q2

    fusedmat_kernel<<<dim3(SS/16, NB, 2), 256>>>(fw, fbias);
    hop_gemm_kernel<<<dim3(8, NB, HKS*2), 256>>>();
    outproj_kernel<<<NTOK/16, 256>>>(outW, out);
}